// round 1
// baseline (speedup 1.0000x reference)
#include <cuda_runtime.h>
#include <math.h>

// ---------------------------------------------------------------------------
// Problem constants: B=8, T=1024, C=1024, H=16, D=64, TI=256, FF=4096
// M = B*T = 8192 text rows, MI = B*TI = 2048 image rows
// ---------------------------------------------------------------------------

#define CC    1024
#define MM    8192
#define MIMG  2048
#define FFD   4096

// Scratch (device globals — allocation-free, per harness rules)
__device__ float g_h[MM * CC];        // layernorm output
__device__ float g_qkv[MM * 3 * CC];  // fused qkv projection
__device__ float g_attn[MM * CC];     // merged attention output
__device__ float g_q[MM * CC];        // cross-attn queries
__device__ float g_k[MIMG * CC];      // cross-attn keys
__device__ float g_v[MIMG * CC];      // cross-attn values
__device__ float g_ff[MM * FFD];      // MLP hidden

// ---------------------------------------------------------------------------
// Block-wide sum reduction (256 threads)
// ---------------------------------------------------------------------------
__device__ __forceinline__ float block_sum(float v) {
    __shared__ float red[8];
    int lane = threadIdx.x & 31;
    int w    = threadIdx.x >> 5;
    #pragma unroll
    for (int o = 16; o; o >>= 1) v += __shfl_xor_sync(0xffffffffu, v, o);
    __syncthreads();                 // protect red[] reuse across calls
    if (lane == 0) red[w] = v;
    __syncthreads();
    if (w == 0) {
        v = (lane < 8) ? red[lane] : 0.f;
        #pragma unroll
        for (int o = 4; o; o >>= 1) v += __shfl_xor_sync(0xffffffffu, v, o);
        if (lane == 0) red[0] = v;
    }
    __syncthreads();
    return red[0];
}

// ---------------------------------------------------------------------------
// LayerNorm: one block per row, C=1024, 256 threads x float4
// ---------------------------------------------------------------------------
__global__ __launch_bounds__(256) void ln_kernel(
    const float* __restrict__ in, const float* __restrict__ g,
    const float* __restrict__ b, float* __restrict__ out)
{
    const int row = blockIdx.x;
    const float4 v = ((const float4*)(in + (size_t)row * CC))[threadIdx.x];
    float s = v.x + v.y + v.z + v.w;
    s = block_sum(s);
    const float mean = s * (1.0f / CC);
    float dx = v.x - mean, dy = v.y - mean, dz = v.z - mean, dw = v.w - mean;
    float sq = dx*dx + dy*dy + dz*dz + dw*dw;
    sq = block_sum(sq);
    const float rstd = rsqrtf(sq * (1.0f / CC) + 1e-5f);
    const float4 gg = ((const float4*)g)[threadIdx.x];
    const float4 bb = ((const float4*)b)[threadIdx.x];
    float4 o;
    o.x = dx * rstd * gg.x + bb.x;
    o.y = dy * rstd * gg.y + bb.y;
    o.z = dz * rstd * gg.z + bb.z;
    o.w = dw * rstd * gg.w + bb.w;
    ((float4*)(out + (size_t)row * CC))[threadIdx.x] = o;
}

// ---------------------------------------------------------------------------
// Tiled SGEMM: out[M,N] = A[M,K] @ W[K,N] + bias (+ residual) (opt GELU)
// 128x128 tile, BK=16, 256 threads, 8x8 micro-tile
// ---------------------------------------------------------------------------
__device__ __forceinline__ float gelu_tanh(float x) {
    float u = 0.7978845608028654f * (x + 0.044715f * x * x * x);
    return 0.5f * x * (1.0f + tanhf(u));
}

template<bool GELU>
__global__ __launch_bounds__(256) void gemm_kernel(
    const float* __restrict__ A, const float* __restrict__ W,
    const float* __restrict__ bias, const float* __restrict__ res,
    float* __restrict__ out, int M, int N, int K)
{
    __shared__ float As[16][128];
    __shared__ float Bs[16][128];
    const int tid = threadIdx.x;
    const int tx = tid & 15, ty = tid >> 4;
    const int m0 = blockIdx.y * 128, n0 = blockIdx.x * 128;

    float acc[8][8];
    #pragma unroll
    for (int i = 0; i < 8; i++)
        #pragma unroll
        for (int j = 0; j < 8; j++) acc[i][j] = 0.f;

    for (int k0 = 0; k0 < K; k0 += 16) {
        #pragma unroll
        for (int i = 0; i < 2; i++) {
            int idx = tid + i * 256;         // float4 index 0..511
            int r = idx >> 2, c = (idx & 3) << 2;
            float4 a4 = *(const float4*)(A + (size_t)(m0 + r) * K + k0 + c);
            As[c + 0][r] = a4.x; As[c + 1][r] = a4.y;
            As[c + 2][r] = a4.z; As[c + 3][r] = a4.w;
            int r2 = idx >> 5, c2 = (idx & 31) << 2;
            *(float4*)&Bs[r2][c2] =
                *(const float4*)(W + (size_t)(k0 + r2) * N + n0 + c2);
        }
        __syncthreads();
        #pragma unroll
        for (int k = 0; k < 16; k++) {
            float a[8], b[8];
            *(float4*)(a)     = *(const float4*)&As[k][ty * 8];
            *(float4*)(a + 4) = *(const float4*)&As[k][ty * 8 + 4];
            *(float4*)(b)     = *(const float4*)&Bs[k][tx * 8];
            *(float4*)(b + 4) = *(const float4*)&Bs[k][tx * 8 + 4];
            #pragma unroll
            for (int i = 0; i < 8; i++)
                #pragma unroll
                for (int j = 0; j < 8; j++)
                    acc[i][j] = fmaf(a[i], b[j], acc[i][j]);
        }
        __syncthreads();
    }

    #pragma unroll
    for (int i = 0; i < 8; i++) {
        const int m = m0 + ty * 8 + i;
        #pragma unroll
        for (int jj = 0; jj < 2; jj++) {
            const int n = n0 + tx * 8 + jj * 4;
            const float4 bv = *(const float4*)(bias + n);
            float4 c4;
            c4.x = acc[i][jj * 4 + 0] + bv.x;
            c4.y = acc[i][jj * 4 + 1] + bv.y;
            c4.z = acc[i][jj * 4 + 2] + bv.z;
            c4.w = acc[i][jj * 4 + 3] + bv.w;
            if (GELU) {
                c4.x = gelu_tanh(c4.x); c4.y = gelu_tanh(c4.y);
                c4.z = gelu_tanh(c4.z); c4.w = gelu_tanh(c4.w);
            }
            if (res) {
                const float4 r4 = *(const float4*)(res + (size_t)m * N + n);
                c4.x += r4.x; c4.y += r4.y; c4.z += r4.z; c4.w += r4.w;
            }
            *(float4*)(out + (size_t)m * N + n) = c4;
        }
    }
}

// ---------------------------------------------------------------------------
// Flash attention (fp32, online softmax). D=64 fixed.
// BLOCK_Q=64, BLOCK_K=32, 256 threads (16x16): thread owns 4 queries x {2 keys | 4 dims}
// grid: (Tq/64, B*H)
// ---------------------------------------------------------------------------
template<bool CAUSAL>
__global__ __launch_bounds__(256) void flash_kernel(
    const float* __restrict__ Q, const float* __restrict__ K,
    const float* __restrict__ V, float* __restrict__ O,
    int Tq, int Tkv, int qStride, int kvStride, float scale)
{
    __shared__ float Qs[64][64];
    __shared__ float Ks[32][68];
    __shared__ float Vs[32][68];
    __shared__ float Pst[32][68];   // P transposed: [key][query]

    const int tid = threadIdx.x;
    const int tx = tid & 15, ty = tid >> 4;
    const int bh = blockIdx.y;
    const int b = bh >> 4, h = bh & 15;     // H = 16
    const int qt = blockIdx.x;

    const float* Qb = Q + (size_t)(b * Tq + qt * 64) * qStride + h * 64;
    const float* Kb = K + (size_t)(b * Tkv) * kvStride + h * 64;
    const float* Vb = V + (size_t)(b * Tkv) * kvStride + h * 64;

    // load Q tile, pre-scaled
    #pragma unroll
    for (int i = 0; i < 4; i++) {
        int idx = tid + i * 256;
        int r = idx >> 4, c = (idx & 15) << 2;
        float4 q4 = *(const float4*)(Qb + (size_t)r * qStride + c);
        q4.x *= scale; q4.y *= scale; q4.z *= scale; q4.w *= scale;
        *(float4*)&Qs[r][c] = q4;
    }

    float m_i[4] = {-1e30f, -1e30f, -1e30f, -1e30f};
    float l_i[4] = {0.f, 0.f, 0.f, 0.f};
    float o[4][4];
    #pragma unroll
    for (int i = 0; i < 4; i++)
        #pragma unroll
        for (int j = 0; j < 4; j++) o[i][j] = 0.f;

    const int nkt = CAUSAL ? (2 * qt + 2) : (Tkv >> 5);

    for (int kt = 0; kt < nkt; kt++) {
        __syncthreads();   // also covers Qs visibility on first iter
        #pragma unroll
        for (int i = 0; i < 2; i++) {
            int idx = tid + i * 256;
            int r = idx >> 4, c = (idx & 15) << 2;
            *(float4*)&Ks[r][c] =
                *(const float4*)(Kb + (size_t)(kt * 32 + r) * kvStride + c);
            *(float4*)&Vs[r][c] =
                *(const float4*)(Vb + (size_t)(kt * 32 + r) * kvStride + c);
        }
        __syncthreads();

        // S = Q @ K^T (scaled)
        float s[4][2];
        #pragma unroll
        for (int iq = 0; iq < 4; iq++) { s[iq][0] = 0.f; s[iq][1] = 0.f; }
        #pragma unroll
        for (int d0 = 0; d0 < 64; d0 += 4) {
            float4 qv[4];
            #pragma unroll
            for (int iq = 0; iq < 4; iq++)
                qv[iq] = *(const float4*)&Qs[ty * 4 + iq][d0];
            #pragma unroll
            for (int ik = 0; ik < 2; ik++) {
                const float4 kv = *(const float4*)&Ks[tx * 2 + ik][d0];
                #pragma unroll
                for (int iq = 0; iq < 4; iq++)
                    s[iq][ik] += qv[iq].x * kv.x + qv[iq].y * kv.y +
                                 qv[iq].z * kv.z + qv[iq].w * kv.w;
            }
        }

        if (CAUSAL && kt >= 2 * qt) {  // only last two tiles touch the diagonal
            #pragma unroll
            for (int iq = 0; iq < 4; iq++)
                #pragma unroll
                for (int ik = 0; ik < 2; ik++)
                    if (kt * 32 + tx * 2 + ik > qt * 64 + ty * 4 + iq)
                        s[iq][ik] = -1e30f;
        }

        // online softmax update (row group = 16 tx-lanes within half-warp)
        #pragma unroll
        for (int iq = 0; iq < 4; iq++) {
            float tm = fmaxf(s[iq][0], s[iq][1]);
            #pragma unroll
            for (int off = 8; off; off >>= 1)
                tm = fmaxf(tm, __shfl_xor_sync(0xffffffffu, tm, off));
            const float mn = fmaxf(m_i[iq], tm);
            const float f = __expf(m_i[iq] - mn);
            m_i[iq] = mn;
            const float p0 = __expf(s[iq][0] - mn);
            const float p1 = __expf(s[iq][1] - mn);
            float rs = p0 + p1;
            #pragma unroll
            for (int off = 8; off; off >>= 1)
                rs += __shfl_xor_sync(0xffffffffu, rs, off);
            l_i[iq] = l_i[iq] * f + rs;
            #pragma unroll
            for (int id = 0; id < 4; id++) o[iq][id] *= f;
            Pst[tx * 2 + 0][ty * 4 + iq] = p0;
            Pst[tx * 2 + 1][ty * 4 + iq] = p1;
        }
        __syncthreads();

        // O += P @ V (thread owns 4 queries x 4 dims)
        #pragma unroll 8
        for (int j = 0; j < 32; j++) {
            const float4 pv = *(const float4*)&Pst[j][ty * 4];
            const float4 vv = *(const float4*)&Vs[j][tx * 4];
            const float p[4] = {pv.x, pv.y, pv.z, pv.w};
            const float vd[4] = {vv.x, vv.y, vv.z, vv.w};
            #pragma unroll
            for (int iq = 0; iq < 4; iq++)
                #pragma unroll
                for (int id = 0; id < 4; id++)
                    o[iq][id] = fmaf(p[iq], vd[id], o[iq][id]);
        }
    }

    // finalize + store (merged-head layout, O row stride = C)
    #pragma unroll
    for (int iq = 0; iq < 4; iq++) {
        const float inv = 1.0f / l_i[iq];
        const int r = qt * 64 + ty * 4 + iq;
        float4 ov;
        ov.x = o[iq][0] * inv; ov.y = o[iq][1] * inv;
        ov.z = o[iq][2] * inv; ov.w = o[iq][3] * inv;
        *(float4*)(O + (size_t)(b * Tq + r) * CC + h * 64 + tx * 4) = ov;
    }
}

// ---------------------------------------------------------------------------
// Launch sequence
// ---------------------------------------------------------------------------
extern "C" void kernel_launch(void* const* d_in, const int* in_sizes, int n_in,
                              void* d_out, int out_size)
{
    (void)in_sizes; (void)n_in; (void)out_size;
    const float* x      = (const float*)d_in[0];
    const float* ximg   = (const float*)d_in[1];
    const float* ln1_g  = (const float*)d_in[2];
    const float* ln1_b  = (const float*)d_in[3];
    const float* ln2_g  = (const float*)d_in[4];
    const float* ln2_b  = (const float*)d_in[5];
    const float* W_attn = (const float*)d_in[6];
    const float* b_attn = (const float*)d_in[7];
    const float* W_aproj= (const float*)d_in[8];
    const float* b_aproj= (const float*)d_in[9];
    const float* Wq     = (const float*)d_in[10];
    const float* bq     = (const float*)d_in[11];
    const float* Wk     = (const float*)d_in[12];
    const float* bk     = (const float*)d_in[13];
    const float* Wv     = (const float*)d_in[14];
    const float* bv     = (const float*)d_in[15];
    const float* Wcproj = (const float*)d_in[16];
    const float* bcproj = (const float*)d_in[17];
    const float* W_fc   = (const float*)d_in[18];
    const float* b_fc   = (const float*)d_in[19];
    const float* W_mproj= (const float*)d_in[20];
    const float* b_mproj= (const float*)d_in[21];
    float* out = (float*)d_out;

    float *hb, *qkvb, *attnb, *qb, *kb, *vb, *ffb;
    cudaGetSymbolAddress((void**)&hb,    g_h);
    cudaGetSymbolAddress((void**)&qkvb,  g_qkv);
    cudaGetSymbolAddress((void**)&attnb, g_attn);
    cudaGetSymbolAddress((void**)&qb,    g_q);
    cudaGetSymbolAddress((void**)&kb,    g_k);
    cudaGetSymbolAddress((void**)&vb,    g_v);
    cudaGetSymbolAddress((void**)&ffb,   g_ff);

    const float scale = 0.125f;   // 1/sqrt(64)

    // --- causal self-attention ---
    ln_kernel<<<MM, 256>>>(x, ln1_g, ln1_b, hb);
    gemm_kernel<false><<<dim3(3 * CC / 128, MM / 128), 256>>>(
        hb, W_attn, b_attn, nullptr, qkvb, MM, 3 * CC, CC);
    flash_kernel<true><<<dim3(16, 128), 256>>>(
        qkvb, qkvb + CC, qkvb + 2 * CC, attnb, 1024, 1024, 3 * CC, 3 * CC, scale);
    gemm_kernel<false><<<dim3(CC / 128, MM / 128), 256>>>(
        attnb, W_aproj, b_aproj, x, out, MM, CC, CC);   // out = x + sa

    // --- cross-attention ---
    ln_kernel<<<MM, 256>>>(out, ln1_g, ln1_b, hb);
    gemm_kernel<false><<<dim3(CC / 128, MM / 128), 256>>>(
        hb, Wq, bq, nullptr, qb, MM, CC, CC);
    gemm_kernel<false><<<dim3(CC / 128, MIMG / 128), 256>>>(
        ximg, Wk, bk, nullptr, kb, MIMG, CC, CC);
    gemm_kernel<false><<<dim3(CC / 128, MIMG / 128), 256>>>(
        ximg, Wv, bv, nullptr, vb, MIMG, CC, CC);
    flash_kernel<false><<<dim3(16, 128), 256>>>(
        qb, kb, vb, attnb, 1024, 256, CC, CC, scale);
    gemm_kernel<false><<<dim3(CC / 128, MM / 128), 256>>>(
        attnb, Wcproj, bcproj, out, out, MM, CC, CC);   // out += ca

    // --- MLP ---
    ln_kernel<<<MM, 256>>>(out, ln2_g, ln2_b, hb);
    gemm_kernel<true><<<dim3(FFD / 128, MM / 128), 256>>>(
        hb, W_fc, b_fc, nullptr, ffb, MM, FFD, CC);
    gemm_kernel<false><<<dim3(CC / 128, MM / 128), 256>>>(
        ffb, W_mproj, b_mproj, out, out, MM, CC, FFD);  // out += mlp
}

// round 5
// speedup vs baseline: 2.2681x; 2.2681x over previous
#include <cuda_runtime.h>
#include <cuda_bf16.h>
#include <cstdint>
#include <math.h>

// ---------------------------------------------------------------------------
// B=8, T=1024, C=1024, H=16, D=64, TI=256, FF=4096
// ---------------------------------------------------------------------------
#define CC    1024
#define MM    8192
#define MIMG  2048
#define FFD   4096

// ---------------------------------------------------------------------------
// helpers
// ---------------------------------------------------------------------------
__device__ __forceinline__ uint32_t smem_u32(const void* p) {
    uint32_t a;
    asm("{ .reg .u64 t; cvta.to.shared.u64 t, %1; cvt.u32.u64 %0, t; }" : "=r"(a) : "l"(p));
    return a;
}
__device__ __forceinline__ void ldsm4(uint32_t a, uint32_t& r0, uint32_t& r1,
                                      uint32_t& r2, uint32_t& r3) {
    asm volatile("ldmatrix.sync.aligned.m8n8.x4.shared.b16 {%0,%1,%2,%3}, [%4];"
                 : "=r"(r0), "=r"(r1), "=r"(r2), "=r"(r3) : "r"(a));
}
__device__ __forceinline__ void ldsm4t(uint32_t a, uint32_t& r0, uint32_t& r1,
                                       uint32_t& r2, uint32_t& r3) {
    asm volatile("ldmatrix.sync.aligned.m8n8.x4.trans.shared.b16 {%0,%1,%2,%3}, [%4];"
                 : "=r"(r0), "=r"(r1), "=r"(r2), "=r"(r3) : "r"(a));
}
__device__ __forceinline__ void mma_bf16(float* c, const uint32_t* a, uint32_t b0, uint32_t b1) {
    asm volatile("mma.sync.aligned.m16n8k16.row.col.f32.bf16.bf16.f32 "
                 "{%0,%1,%2,%3}, {%4,%5,%6,%7}, {%8,%9}, {%0,%1,%2,%3};"
                 : "+f"(c[0]), "+f"(c[1]), "+f"(c[2]), "+f"(c[3])
                 : "r"(a[0]), "r"(a[1]), "r"(a[2]), "r"(a[3]), "r"(b0), "r"(b1));
}
__device__ __forceinline__ void cp16(uint32_t dst, const void* src) {
    asm volatile("cp.async.cg.shared.global [%0], [%1], 16;" :: "r"(dst), "l"(src));
}
__device__ __forceinline__ uint32_t pack2(__nv_bfloat16 a, __nv_bfloat16 b) {
    __nv_bfloat162 t = __halves2bfloat162(a, b);
    return *reinterpret_cast<uint32_t*>(&t);
}
__device__ __forceinline__ void split2(float x, __nv_bfloat16& h, __nv_bfloat16& l) {
    h = __float2bfloat16(x);
    l = __float2bfloat16(x - __bfloat162float(h));
}
__device__ __forceinline__ float gelu_tanh(float x) {
    float u = 0.7978845608028654f * (x + 0.044715f * x * x * x);
    return 0.5f * x * (1.0f + tanhf(u));
}

// ---------------------------------------------------------------------------
// Scratch (device globals)
// ---------------------------------------------------------------------------
__device__ __nv_bfloat16 g_wt_hi[16777216];
__device__ __nv_bfloat16 g_wt_lo[16777216];
__device__ __nv_bfloat16 g_qkv_hi[MM * 3 * CC];
__device__ __nv_bfloat16 g_qkv_lo[MM * 3 * CC];
__device__ __nv_bfloat16 g_q_hi[MM * CC];
__device__ __nv_bfloat16 g_q_lo[MM * CC];
__device__ __nv_bfloat16 g_k_hi[MIMG * CC];
__device__ __nv_bfloat16 g_k_lo[MIMG * CC];
__device__ __nv_bfloat16 g_v_hi[MIMG * CC];
__device__ __nv_bfloat16 g_v_lo[MIMG * CC];
__device__ __nv_bfloat16 g_a_hi[MM * CC];
__device__ __nv_bfloat16 g_a_lo[MM * CC];
__device__ __nv_bfloat16 g_ff_hi[MM * FFD];
__device__ __nv_bfloat16 g_ff_lo[MM * FFD];
__device__ __nv_bfloat16 g_xi_hi[MIMG * CC];
__device__ __nv_bfloat16 g_xi_lo[MIMG * CC];

#define OFF_ATTN  0u
#define OFF_APROJ 3145728u
#define OFF_Q     4194304u
#define OFF_K     5242880u
#define OFF_V     6291456u
#define OFF_CPROJ 7340032u
#define OFF_FC    8388608u
#define OFF_MPROJ 12582912u

// ---------------------------------------------------------------------------
// transpose + split: W[K,N] fp32 -> Wt_hi/lo[N,K] bf16
// ---------------------------------------------------------------------------
__global__ __launch_bounds__(256) void transpose_split_kernel(
    const float* __restrict__ W, __nv_bfloat16* __restrict__ hi,
    __nv_bfloat16* __restrict__ lo, int K, int N)
{
    __shared__ float t[32][33];
    const int n0 = blockIdx.x * 32, k0 = blockIdx.y * 32;
    const int tx = threadIdx.x & 31, ty = threadIdx.x >> 5;
    #pragma unroll
    for (int i = 0; i < 4; i++) {
        int kk = ty + i * 8;
        t[kk][tx] = W[(size_t)(k0 + kk) * N + n0 + tx];
    }
    __syncthreads();
    #pragma unroll
    for (int i = 0; i < 4; i++) {
        int nn = ty + i * 8;
        float v = t[tx][nn];
        __nv_bfloat16 h, l; split2(v, h, l);
        size_t o = (size_t)(n0 + nn) * K + k0 + tx;
        hi[o] = h; lo[o] = l;
    }
}

__global__ void split_kernel(const float* __restrict__ x,
                             __nv_bfloat16* __restrict__ hi,
                             __nv_bfloat16* __restrict__ lo, int n)
{
    int i = blockIdx.x * blockDim.x + threadIdx.x;
    if (i < n) { __nv_bfloat16 h, l; split2(x[i], h, l); hi[i] = h; lo[i] = l; }
}

// ---------------------------------------------------------------------------
// block reduction + LayerNorm (split output)
// ---------------------------------------------------------------------------
__device__ __forceinline__ float block_sum(float v) {
    __shared__ float red[8];
    int lane = threadIdx.x & 31;
    int w    = threadIdx.x >> 5;
    #pragma unroll
    for (int o = 16; o; o >>= 1) v += __shfl_xor_sync(0xffffffffu, v, o);
    __syncthreads();
    if (lane == 0) red[w] = v;
    __syncthreads();
    if (w == 0) {
        v = (lane < 8) ? red[lane] : 0.f;
        #pragma unroll
        for (int o = 4; o; o >>= 1) v += __shfl_xor_sync(0xffffffffu, v, o);
        if (lane == 0) red[0] = v;
    }
    __syncthreads();
    return red[0];
}

__global__ __launch_bounds__(256) void ln_split_kernel(
    const float* __restrict__ in, const float* __restrict__ g,
    const float* __restrict__ b, __nv_bfloat16* __restrict__ out_hi,
    __nv_bfloat16* __restrict__ out_lo)
{
    const int row = blockIdx.x;
    const float4 v = ((const float4*)(in + (size_t)row * CC))[threadIdx.x];
    float s = v.x + v.y + v.z + v.w;
    s = block_sum(s);
    const float mean = s * (1.0f / CC);
    float dx = v.x - mean, dy = v.y - mean, dz = v.z - mean, dw = v.w - mean;
    float sq = dx*dx + dy*dy + dz*dz + dw*dw;
    sq = block_sum(sq);
    const float rstd = rsqrtf(sq * (1.0f / CC) + 1e-5f);
    const float4 gg = ((const float4*)g)[threadIdx.x];
    const float4 bb = ((const float4*)b)[threadIdx.x];
    float o0 = dx * rstd * gg.x + bb.x;
    float o1 = dy * rstd * gg.y + bb.y;
    float o2 = dz * rstd * gg.z + bb.z;
    float o3 = dw * rstd * gg.w + bb.w;
    __nv_bfloat16 h0,h1,h2,h3,l0,l1,l2,l3;
    split2(o0,h0,l0); split2(o1,h1,l1); split2(o2,h2,l2); split2(o3,h3,l3);
    size_t off = (size_t)row * CC + threadIdx.x * 4;
    *(uint2*)(out_hi + off) = make_uint2(pack2(h0,h1), pack2(h2,h3));
    *(uint2*)(out_lo + off) = make_uint2(pack2(l0,l1), pack2(l2,l3));
}

// ---------------------------------------------------------------------------
// HMMA split-bf16 GEMM: out[M,N] = A[M,K] @ Wt[N,K]^T + bias (+res)(gelu)
// D ≈ Ah·Bh + Ah·Bl + Al·Bh.  Tile 128x128x32, 8 warps (warp tile 32x64),
// cp.async double-buffered smem (padded rows, 40 elems).
// ---------------------------------------------------------------------------
#define GRS 40
#define GTILE_B (128 * GRS * 2)          // 10240 bytes per matrix tile
#define GBUF_B  (4 * GTILE_B)            // 40960 per stage
#define GEMM_SMEM (2 * GBUF_B)           // 81920

template<bool GELU, bool SPLIT_OUT>
__global__ __launch_bounds__(256, 1) void mma_gemm(
    const __nv_bfloat16* __restrict__ Ahi, const __nv_bfloat16* __restrict__ Alo,
    const __nv_bfloat16* __restrict__ Bhi, const __nv_bfloat16* __restrict__ Blo,
    const float* __restrict__ bias, const float* __restrict__ res,
    float* __restrict__ outf,
    __nv_bfloat16* __restrict__ out_hi, __nv_bfloat16* __restrict__ out_lo,
    int M, int N, int K)
{
    extern __shared__ __align__(16) char smem[];
    const uint32_t base = smem_u32(smem);
    const int tid = threadIdx.x;
    const int wid = tid >> 5, lane = tid & 31;
    const int wm = wid & 3, wn = wid >> 2;
    const int m0 = blockIdx.y * 128, n0 = blockIdx.x * 128;

    const __nv_bfloat16* gA[2] = { Ahi + (size_t)m0 * K, Alo + (size_t)m0 * K };
    const __nv_bfloat16* gB[2] = { Bhi + (size_t)n0 * K, Blo + (size_t)n0 * K };

    auto stage = [&](int k0, int buf) {
        const uint32_t sb = base + buf * GBUF_B;
        #pragma unroll
        for (int t = 0; t < 4; t++) {
            const __nv_bfloat16* src = (t < 2) ? gA[t] : gB[t - 2];
            #pragma unroll
            for (int i = 0; i < 2; i++) {
                int idx = tid + i * 256;
                int r = idx >> 2, s = idx & 3;
                cp16(sb + t * GTILE_B + (r * GRS + s * 8) * 2,
                     src + (size_t)r * K + k0 + s * 8);
            }
        }
        asm volatile("cp.async.commit_group;");
    };

    const int laRowA = ((lane >> 3) & 1) * 8 + (lane & 7);
    const int laColA = (lane >> 4) * 8;
    const int laRowB = ((lane >> 4) << 3) + (lane & 7);
    const int laColB = ((lane >> 3) & 1) * 8;

    float c[2][8][4];
    #pragma unroll
    for (int i = 0; i < 2; i++)
        #pragma unroll
        for (int j = 0; j < 8; j++)
            #pragma unroll
            for (int q = 0; q < 4; q++) c[i][j][q] = 0.f;

    const int nch = K >> 5;
    stage(0, 0);

    for (int ch = 0; ch < nch; ch++) {
        if (ch + 1 < nch) {
            stage((ch + 1) << 5, (ch + 1) & 1);
            asm volatile("cp.async.wait_group 1;");
        } else {
            asm volatile("cp.async.wait_group 0;");
        }
        __syncthreads();

        const uint32_t sb = base + (ch & 1) * GBUF_B;
        const uint32_t sAh = sb, sAl = sb + GTILE_B;
        const uint32_t sBh = sb + 2 * GTILE_B, sBl = sb + 3 * GTILE_B;

        #pragma unroll
        for (int ks = 0; ks < 32; ks += 16) {
            uint32_t ah[2][4], al[2][4];
            #pragma unroll
            for (int mf = 0; mf < 2; mf++) {
                uint32_t off = ((wm * 32 + mf * 16 + laRowA) * GRS + ks + laColA) * 2;
                ldsm4(sAh + off, ah[mf][0], ah[mf][1], ah[mf][2], ah[mf][3]);
                ldsm4(sAl + off, al[mf][0], al[mf][1], al[mf][2], al[mf][3]);
            }
            uint32_t bh[8][2], bl[8][2];
            #pragma unroll
            for (int np = 0; np < 4; np++) {
                uint32_t off = ((wn * 64 + np * 16 + laRowB) * GRS + ks + laColB) * 2;
                ldsm4(sBh + off, bh[2*np][0], bh[2*np][1], bh[2*np+1][0], bh[2*np+1][1]);
                ldsm4(sBl + off, bl[2*np][0], bl[2*np][1], bl[2*np+1][0], bl[2*np+1][1]);
            }
            #pragma unroll
            for (int mf = 0; mf < 2; mf++)
                #pragma unroll
                for (int nf = 0; nf < 8; nf++) {
                    mma_bf16(c[mf][nf], ah[mf], bh[nf][0], bh[nf][1]);
                    mma_bf16(c[mf][nf], ah[mf], bl[nf][0], bl[nf][1]);
                    mma_bf16(c[mf][nf], al[mf], bh[nf][0], bh[nf][1]);
                }
        }
        __syncthreads();
    }

    #pragma unroll
    for (int mf = 0; mf < 2; mf++) {
        const int rbase = m0 + wm * 32 + mf * 16 + (lane >> 2);
        #pragma unroll
        for (int nf = 0; nf < 8; nf++) {
            const int gn = n0 + wn * 64 + nf * 8 + (lane & 3) * 2;
            const float2 b2 = *(const float2*)(bias + gn);
            #pragma unroll
            for (int half = 0; half < 2; half++) {
                const int gm = rbase + half * 8;
                float v0 = c[mf][nf][half * 2 + 0] + b2.x;
                float v1 = c[mf][nf][half * 2 + 1] + b2.y;
                if (GELU) { v0 = gelu_tanh(v0); v1 = gelu_tanh(v1); }
                if (!SPLIT_OUT) {
                    if (res) {
                        const float2 r2 = *(const float2*)(res + (size_t)gm * N + gn);
                        v0 += r2.x; v1 += r2.y;
                    }
                    *(float2*)(outf + (size_t)gm * N + gn) = make_float2(v0, v1);
                } else {
                    __nv_bfloat16 h0, l0, h1, l1;
                    split2(v0, h0, l0); split2(v1, h1, l1);
                    *(uint32_t*)(out_hi + (size_t)gm * N + gn) = pack2(h0, h1);
                    *(uint32_t*)(out_lo + (size_t)gm * N + gn) = pack2(l0, l1);
                }
            }
        }
    }
}

// ---------------------------------------------------------------------------
// Flash attention via HMMA (split-bf16 S and PV), FA2 style.
// BQ=64 (4 warps x 16 rows), BK=64, D=64. inputs/outputs are split bf16.
// ---------------------------------------------------------------------------
#define FRS 72
#define FTILE_B (64 * FRS * 2)       // 9216 bytes
#define FLASH_SMEM (6 * FTILE_B)     // 55296

template<bool CAUSAL>
__global__ __launch_bounds__(128) void flash_mma(
    const __nv_bfloat16* __restrict__ Qh, const __nv_bfloat16* __restrict__ Ql,
    const __nv_bfloat16* __restrict__ Kh, const __nv_bfloat16* __restrict__ Kl,
    const __nv_bfloat16* __restrict__ Vh, const __nv_bfloat16* __restrict__ Vl,
    __nv_bfloat16* __restrict__ Ohi, __nv_bfloat16* __restrict__ Olo,
    int Tq, int Tkv, int qS, int kS, float scale)
{
    extern __shared__ __align__(16) char smem[];
    const uint32_t base = smem_u32(smem);
    const uint32_t sQh = base,             sQl = base + FTILE_B;
    const uint32_t sKh = base + 2*FTILE_B, sKl = base + 3*FTILE_B;
    const uint32_t sVh = base + 4*FTILE_B, sVl = base + 5*FTILE_B;

    const int tid = threadIdx.x;
    const int wid = tid >> 5, lane = tid & 31;
    const int bh = blockIdx.y;
    const int b = bh >> 4, h = bh & 15;
    const int qt = blockIdx.x;

    const __nv_bfloat16* Qhb = Qh + (size_t)(b * Tq + qt * 64) * qS + h * 64;
    const __nv_bfloat16* Qlb = Ql + (size_t)(b * Tq + qt * 64) * qS + h * 64;
    const __nv_bfloat16* Khb = Kh + (size_t)(b * Tkv) * kS + h * 64;
    const __nv_bfloat16* Klb = Kl + (size_t)(b * Tkv) * kS + h * 64;
    const __nv_bfloat16* Vhb = Vh + (size_t)(b * Tkv) * kS + h * 64;
    const __nv_bfloat16* Vlb = Vl + (size_t)(b * Tkv) * kS + h * 64;

    #pragma unroll
    for (int i = 0; i < 4; i++) {
        int idx = tid + i * 128;
        int r = idx >> 3, s = idx & 7;
        uint4 vh = *(const uint4*)(Qhb + (size_t)r * qS + s * 8);
        uint4 vl = *(const uint4*)(Qlb + (size_t)r * qS + s * 8);
        uint32_t off = (r * FRS + s * 8) * 2;
        asm volatile("st.shared.v4.b32 [%0], {%1,%2,%3,%4};"
                     :: "r"(sQh + off), "r"(vh.x), "r"(vh.y), "r"(vh.z), "r"(vh.w));
        asm volatile("st.shared.v4.b32 [%0], {%1,%2,%3,%4};"
                     :: "r"(sQl + off), "r"(vl.x), "r"(vl.y), "r"(vl.z), "r"(vl.w));
    }

    const int laRowA = ((lane >> 3) & 1) * 8 + (lane & 7);
    const int laColA = (lane >> 4) * 8;
    const int laRowB = ((lane >> 4) << 3) + (lane & 7);
    const int laColB = ((lane >> 3) & 1) * 8;

    float o[8][4];
    #pragma unroll
    for (int i = 0; i < 8; i++)
        #pragma unroll
        for (int j = 0; j < 4; j++) o[i][j] = 0.f;
    float mr0 = -1e30f, mr1 = -1e30f, lr0 = 0.f, lr1 = 0.f;

    const int nkt = CAUSAL ? (qt + 1) : (Tkv >> 6);

    for (int kt = 0; kt < nkt; kt++) {
        __syncthreads();
        #pragma unroll
        for (int i = 0; i < 4; i++) {
            int idx = tid + i * 128;
            int r = idx >> 3, s = idx & 7;
            size_t go = (size_t)(kt * 64 + r) * kS + s * 8;
            uint32_t off = (r * FRS + s * 8) * 2;
            uint4 a  = *(const uint4*)(Khb + go);
            uint4 bq = *(const uint4*)(Klb + go);
            uint4 cq = *(const uint4*)(Vhb + go);
            uint4 d  = *(const uint4*)(Vlb + go);
            asm volatile("st.shared.v4.b32 [%0], {%1,%2,%3,%4};"
                         :: "r"(sKh + off), "r"(a.x), "r"(a.y), "r"(a.z), "r"(a.w));
            asm volatile("st.shared.v4.b32 [%0], {%1,%2,%3,%4};"
                         :: "r"(sKl + off), "r"(bq.x), "r"(bq.y), "r"(bq.z), "r"(bq.w));
            asm volatile("st.shared.v4.b32 [%0], {%1,%2,%3,%4};"
                         :: "r"(sVh + off), "r"(cq.x), "r"(cq.y), "r"(cq.z), "r"(cq.w));
            asm volatile("st.shared.v4.b32 [%0], {%1,%2,%3,%4};"
                         :: "r"(sVl + off), "r"(d.x), "r"(d.y), "r"(d.z), "r"(d.w));
        }
        __syncthreads();

        float s[8][4];
        #pragma unroll
        for (int i = 0; i < 8; i++)
            #pragma unroll
            for (int j = 0; j < 4; j++) s[i][j] = 0.f;

        #pragma unroll
        for (int ks = 0; ks < 4; ks++) {
            uint32_t qh[4], ql[4];
            uint32_t qoff = ((wid * 16 + laRowA) * FRS + ks * 16 + laColA) * 2;
            ldsm4(sQh + qoff, qh[0], qh[1], qh[2], qh[3]);
            ldsm4(sQl + qoff, ql[0], ql[1], ql[2], ql[3]);
            #pragma unroll
            for (int np = 0; np < 4; np++) {
                uint32_t koff = ((np * 16 + laRowB) * FRS + ks * 16 + laColB) * 2;
                uint32_t kh0, kh1, kh2, kh3, kl0, kl1, kl2, kl3;
                ldsm4(sKh + koff, kh0, kh1, kh2, kh3);
                ldsm4(sKl + koff, kl0, kl1, kl2, kl3);
                mma_bf16(s[2*np],   qh, kh0, kh1);
                mma_bf16(s[2*np],   qh, kl0, kl1);
                mma_bf16(s[2*np],   ql, kh0, kh1);
                mma_bf16(s[2*np+1], qh, kh2, kh3);
                mma_bf16(s[2*np+1], qh, kl2, kl3);
                mma_bf16(s[2*np+1], ql, kh2, kh3);
            }
        }
        #pragma unroll
        for (int i = 0; i < 8; i++)
            #pragma unroll
            for (int j = 0; j < 4; j++) s[i][j] *= scale;

        if (CAUSAL && kt == qt) {
            const int row0 = qt * 64 + wid * 16 + (lane >> 2);
            #pragma unroll
            for (int nf = 0; nf < 8; nf++) {
                const int col = kt * 64 + nf * 8 + (lane & 3) * 2;
                if (col     > row0)     s[nf][0] = -1e30f;
                if (col + 1 > row0)     s[nf][1] = -1e30f;
                if (col     > row0 + 8) s[nf][2] = -1e30f;
                if (col + 1 > row0 + 8) s[nf][3] = -1e30f;
            }
        }

        float t0 = -1e30f, t1 = -1e30f;
        #pragma unroll
        for (int nf = 0; nf < 8; nf++) {
            t0 = fmaxf(t0, fmaxf(s[nf][0], s[nf][1]));
            t1 = fmaxf(t1, fmaxf(s[nf][2], s[nf][3]));
        }
        t0 = fmaxf(t0, __shfl_xor_sync(0xffffffffu, t0, 1));
        t0 = fmaxf(t0, __shfl_xor_sync(0xffffffffu, t0, 2));
        t1 = fmaxf(t1, __shfl_xor_sync(0xffffffffu, t1, 1));
        t1 = fmaxf(t1, __shfl_xor_sync(0xffffffffu, t1, 2));
        const float nm0 = fmaxf(mr0, t0), nm1 = fmaxf(mr1, t1);
        const float f0 = __expf(mr0 - nm0), f1 = __expf(mr1 - nm1);
        mr0 = nm0; mr1 = nm1;

        float rs0 = 0.f, rs1 = 0.f;
        #pragma unroll
        for (int nf = 0; nf < 8; nf++) {
            s[nf][0] = __expf(s[nf][0] - nm0);
            s[nf][1] = __expf(s[nf][1] - nm0);
            s[nf][2] = __expf(s[nf][2] - nm1);
            s[nf][3] = __expf(s[nf][3] - nm1);
            rs0 += s[nf][0] + s[nf][1];
            rs1 += s[nf][2] + s[nf][3];
        }
        rs0 += __shfl_xor_sync(0xffffffffu, rs0, 1);
        rs0 += __shfl_xor_sync(0xffffffffu, rs0, 2);
        rs1 += __shfl_xor_sync(0xffffffffu, rs1, 1);
        rs1 += __shfl_xor_sync(0xffffffffu, rs1, 2);
        lr0 = lr0 * f0 + rs0;
        lr1 = lr1 * f1 + rs1;
        #pragma unroll
        for (int nf = 0; nf < 8; nf++) {
            o[nf][0] *= f0; o[nf][1] *= f0;
            o[nf][2] *= f1; o[nf][3] *= f1;
        }

        uint32_t ph[4][4], pl[4][4];
        #pragma unroll
        for (int j = 0; j < 4; j++) {
            __nv_bfloat16 h0,h1,l0,l1;
            split2(s[2*j][0], h0, l0);   split2(s[2*j][1], h1, l1);
            ph[j][0] = pack2(h0, h1);    pl[j][0] = pack2(l0, l1);
            split2(s[2*j][2], h0, l0);   split2(s[2*j][3], h1, l1);
            ph[j][1] = pack2(h0, h1);    pl[j][1] = pack2(l0, l1);
            split2(s[2*j+1][0], h0, l0); split2(s[2*j+1][1], h1, l1);
            ph[j][2] = pack2(h0, h1);    pl[j][2] = pack2(l0, l1);
            split2(s[2*j+1][2], h0, l0); split2(s[2*j+1][3], h1, l1);
            ph[j][3] = pack2(h0, h1);    pl[j][3] = pack2(l0, l1);
        }

        #pragma unroll
        for (int j = 0; j < 4; j++) {
            #pragma unroll
            for (int np = 0; np < 4; np++) {
                uint32_t voff = ((j * 16 + laRowA) * FRS + np * 16 + laColA) * 2;
                uint32_t vh0, vh1, vh2, vh3, vl0, vl1, vl2, vl3;
                ldsm4t(sVh + voff, vh0, vh1, vh2, vh3);
                ldsm4t(sVl + voff, vl0, vl1, vl2, vl3);
                mma_bf16(o[2*np],   ph[j], vh0, vh1);
                mma_bf16(o[2*np],   ph[j], vl0, vl1);
                mma_bf16(o[2*np],   pl[j], vh0, vh1);
                mma_bf16(o[2*np+1], ph[j], vh2, vh3);
                mma_bf16(o[2*np+1], ph[j], vl2, vl3);
                mma_bf16(o[2*np+1], pl[j], vh2, vh3);
            }
        }
    }

    const float inv0 = 1.0f / lr0, inv1 = 1.0f / lr1;
    const int row0 = qt * 64 + wid * 16 + (lane >> 2);
    #pragma unroll
    for (int nf = 0; nf < 8; nf++) {
        const int col = h * 64 + nf * 8 + (lane & 3) * 2;
        {
            float v0 = o[nf][0] * inv0, v1 = o[nf][1] * inv0;
            __nv_bfloat16 h0, l0, h1, l1;
            split2(v0, h0, l0); split2(v1, h1, l1);
            size_t off = (size_t)(b * Tq + row0) * CC + col;
            *(uint32_t*)(Ohi + off) = pack2(h0, h1);
            *(uint32_t*)(Olo + off) = pack2(l0, l1);
        }
        {
            float v0 = o[nf][2] * inv1, v1 = o[nf][3] * inv1;
            __nv_bfloat16 h0, l0, h1, l1;
            split2(v0, h0, l0); split2(v1, h1, l1);
            size_t off = (size_t)(b * Tq + row0 + 8) * CC + col;
            *(uint32_t*)(Ohi + off) = pack2(h0, h1);
            *(uint32_t*)(Olo + off) = pack2(l0, l1);
        }
    }
}

// ---------------------------------------------------------------------------
// Launch sequence
// ---------------------------------------------------------------------------
extern "C" void kernel_launch(void* const* d_in, const int* in_sizes, int n_in,
                              void* d_out, int out_size)
{
    (void)in_sizes; (void)n_in; (void)out_size;
    const float* x      = (const float*)d_in[0];
    const float* ximg   = (const float*)d_in[1];
    const float* ln1_g  = (const float*)d_in[2];
    const float* ln1_b  = (const float*)d_in[3];
    const float* ln2_g  = (const float*)d_in[4];
    const float* ln2_b  = (const float*)d_in[5];
    const float* W_attn = (const float*)d_in[6];
    const float* b_attn = (const float*)d_in[7];
    const float* W_aproj= (const float*)d_in[8];
    const float* b_aproj= (const float*)d_in[9];
    const float* Wq     = (const float*)d_in[10];
    const float* bq     = (const float*)d_in[11];
    const float* Wk     = (const float*)d_in[12];
    const float* bk     = (const float*)d_in[13];
    const float* Wv     = (const float*)d_in[14];
    const float* bv     = (const float*)d_in[15];
    const float* Wcproj = (const float*)d_in[16];
    const float* bcproj = (const float*)d_in[17];
    const float* W_fc   = (const float*)d_in[18];
    const float* b_fc   = (const float*)d_in[19];
    const float* W_mproj= (const float*)d_in[20];
    const float* b_mproj= (const float*)d_in[21];
    float* out = (float*)d_out;

    __nv_bfloat16 *wt_hi, *wt_lo, *qkv_hi, *qkv_lo, *q_hi, *q_lo, *k_hi, *k_lo,
                  *v_hi, *v_lo, *a_hi, *a_lo, *ff_hi, *ff_lo, *xi_hi, *xi_lo;
    cudaGetSymbolAddress((void**)&wt_hi,  g_wt_hi);
    cudaGetSymbolAddress((void**)&wt_lo,  g_wt_lo);
    cudaGetSymbolAddress((void**)&qkv_hi, g_qkv_hi);
    cudaGetSymbolAddress((void**)&qkv_lo, g_qkv_lo);
    cudaGetSymbolAddress((void**)&q_hi,   g_q_hi);
    cudaGetSymbolAddress((void**)&q_lo,   g_q_lo);
    cudaGetSymbolAddress((void**)&k_hi,   g_k_hi);
    cudaGetSymbolAddress((void**)&k_lo,   g_k_lo);
    cudaGetSymbolAddress((void**)&v_hi,   g_v_hi);
    cudaGetSymbolAddress((void**)&v_lo,   g_v_lo);
    cudaGetSymbolAddress((void**)&a_hi,   g_a_hi);
    cudaGetSymbolAddress((void**)&a_lo,   g_a_lo);
    cudaGetSymbolAddress((void**)&ff_hi,  g_ff_hi);
    cudaGetSymbolAddress((void**)&ff_lo,  g_ff_lo);
    cudaGetSymbolAddress((void**)&xi_hi,  g_xi_hi);
    cudaGetSymbolAddress((void**)&xi_lo,  g_xi_lo);

    cudaFuncSetAttribute(mma_gemm<false,false>, cudaFuncAttributeMaxDynamicSharedMemorySize, GEMM_SMEM);
    cudaFuncSetAttribute(mma_gemm<false,true>,  cudaFuncAttributeMaxDynamicSharedMemorySize, GEMM_SMEM);
    cudaFuncSetAttribute(mma_gemm<true,true>,   cudaFuncAttributeMaxDynamicSharedMemorySize, GEMM_SMEM);
    cudaFuncSetAttribute(flash_mma<true>,  cudaFuncAttributeMaxDynamicSharedMemorySize, FLASH_SMEM);
    cudaFuncSetAttribute(flash_mma<false>, cudaFuncAttributeMaxDynamicSharedMemorySize, FLASH_SMEM);

    const float scale = 0.125f;

    // weight prep
    transpose_split_kernel<<<dim3(3*CC/32, CC/32), 256>>>(W_attn,  wt_hi+OFF_ATTN,  wt_lo+OFF_ATTN,  CC, 3*CC);
    transpose_split_kernel<<<dim3(CC/32,   CC/32), 256>>>(W_aproj, wt_hi+OFF_APROJ, wt_lo+OFF_APROJ, CC, CC);
    transpose_split_kernel<<<dim3(CC/32,   CC/32), 256>>>(Wq,      wt_hi+OFF_Q,     wt_lo+OFF_Q,     CC, CC);
    transpose_split_kernel<<<dim3(CC/32,   CC/32), 256>>>(Wk,      wt_hi+OFF_K,     wt_lo+OFF_K,     CC, CC);
    transpose_split_kernel<<<dim3(CC/32,   CC/32), 256>>>(Wv,      wt_hi+OFF_V,     wt_lo+OFF_V,     CC, CC);
    transpose_split_kernel<<<dim3(CC/32,   CC/32), 256>>>(Wcproj,  wt_hi+OFF_CPROJ, wt_lo+OFF_CPROJ, CC, CC);
    transpose_split_kernel<<<dim3(FFD/32,  CC/32), 256>>>(W_fc,    wt_hi+OFF_FC,    wt_lo+OFF_FC,    CC, FFD);
    transpose_split_kernel<<<dim3(CC/32,   FFD/32), 256>>>(W_mproj, wt_hi+OFF_MPROJ, wt_lo+OFF_MPROJ, FFD, CC);
    split_kernel<<<(MIMG*CC + 255)/256, 256>>>(ximg, xi_hi, xi_lo, MIMG*CC);

    // ---- causal self-attention ----
    ln_split_kernel<<<MM, 256>>>(x, ln1_g, ln1_b, a_hi, a_lo);
    mma_gemm<false,true><<<dim3(3*CC/128, MM/128), 256, GEMM_SMEM>>>(
        a_hi, a_lo, wt_hi+OFF_ATTN, wt_lo+OFF_ATTN, b_attn, nullptr,
        nullptr, qkv_hi, qkv_lo, MM, 3*CC, CC);
    flash_mma<true><<<dim3(16, 128), 128, FLASH_SMEM>>>(
        qkv_hi, qkv_lo, qkv_hi + CC, qkv_lo + CC, qkv_hi + 2*CC, qkv_lo + 2*CC,
        a_hi, a_lo, 1024, 1024, 3*CC, 3*CC, scale);
    mma_gemm<false,false><<<dim3(CC/128, MM/128), 256, GEMM_SMEM>>>(
        a_hi, a_lo, wt_hi+OFF_APROJ, wt_lo+OFF_APROJ, b_aproj, x,
        out, nullptr, nullptr, MM, CC, CC);

    // ---- cross-attention ----
    ln_split_kernel<<<MM, 256>>>(out, ln1_g, ln1_b, a_hi, a_lo);
    mma_gemm<false,true><<<dim3(CC/128, MM/128), 256, GEMM_SMEM>>>(
        a_hi, a_lo, wt_hi+OFF_Q, wt_lo+OFF_Q, bq, nullptr,
        nullptr, q_hi, q_lo, MM, CC, CC);
    mma_gemm<false,true><<<dim3(CC/128, MIMG/128), 256, GEMM_SMEM>>>(
        xi_hi, xi_lo, wt_hi+OFF_K, wt_lo+OFF_K, bk, nullptr,
        nullptr, k_hi, k_lo, MIMG, CC, CC);
    mma_gemm<false,true><<<dim3(CC/128, MIMG/128), 256, GEMM_SMEM>>>(
        xi_hi, xi_lo, wt_hi+OFF_V, wt_lo+OFF_V, bv, nullptr,
        nullptr, v_hi, v_lo, MIMG, CC, CC);
    flash_mma<false><<<dim3(16, 128), 128, FLASH_SMEM>>>(
        q_hi, q_lo, k_hi, k_lo, v_hi, v_lo,
        a_hi, a_lo, 1024, 256, CC, CC, scale);
    mma_gemm<false,false><<<dim3(CC/128, MM/128), 256, GEMM_SMEM>>>(
        a_hi, a_lo, wt_hi+OFF_CPROJ, wt_lo+OFF_CPROJ, bcproj, out,
        out, nullptr, nullptr, MM, CC, CC);

    // ---- MLP ----
    ln_split_kernel<<<MM, 256>>>(out, ln2_g, ln2_b, a_hi, a_lo);
    mma_gemm<true,true><<<dim3(FFD/128, MM/128), 256, GEMM_SMEM>>>(
        a_hi, a_lo, wt_hi+OFF_FC, wt_lo+OFF_FC, b_fc, nullptr,
        nullptr, ff_hi, ff_lo, MM, FFD, CC);
    mma_gemm<false,false><<<dim3(CC/128, MM/128), 256, GEMM_SMEM>>>(
        ff_hi, ff_lo, wt_hi+OFF_MPROJ, wt_lo+OFF_MPROJ, b_mproj, out,
        out, nullptr, nullptr, MM, CC, FFD);
}

// round 6
// speedup vs baseline: 2.5582x; 1.1279x over previous
#include <cuda_runtime.h>
#include <cuda_bf16.h>
#include <cstdint>
#include <math.h>

#define CC    1024
#define MM    8192
#define MIMG  2048
#define FFD   4096

// ---------------------------------------------------------------------------
// helpers
// ---------------------------------------------------------------------------
__device__ __forceinline__ uint32_t smem_u32(const void* p) {
    uint32_t a;
    asm("{ .reg .u64 t; cvta.to.shared.u64 t, %1; cvt.u32.u64 %0, t; }" : "=r"(a) : "l"(p));
    return a;
}
__device__ __forceinline__ void ldsm4(uint32_t a, uint32_t& r0, uint32_t& r1,
                                      uint32_t& r2, uint32_t& r3) {
    asm volatile("ldmatrix.sync.aligned.m8n8.x4.shared.b16 {%0,%1,%2,%3}, [%4];"
                 : "=r"(r0), "=r"(r1), "=r"(r2), "=r"(r3) : "r"(a));
}
__device__ __forceinline__ void ldsm4t(uint32_t a, uint32_t& r0, uint32_t& r1,
                                       uint32_t& r2, uint32_t& r3) {
    asm volatile("ldmatrix.sync.aligned.m8n8.x4.trans.shared.b16 {%0,%1,%2,%3}, [%4];"
                 : "=r"(r0), "=r"(r1), "=r"(r2), "=r"(r3) : "r"(a));
}
__device__ __forceinline__ void mma_bf16(float* c, const uint32_t* a, uint32_t b0, uint32_t b1) {
    asm volatile("mma.sync.aligned.m16n8k16.row.col.f32.bf16.bf16.f32 "
                 "{%0,%1,%2,%3}, {%4,%5,%6,%7}, {%8,%9}, {%0,%1,%2,%3};"
                 : "+f"(c[0]), "+f"(c[1]), "+f"(c[2]), "+f"(c[3])
                 : "r"(a[0]), "r"(a[1]), "r"(a[2]), "r"(a[3]), "r"(b0), "r"(b1));
}
__device__ __forceinline__ void cp16(uint32_t dst, const void* src) {
    asm volatile("cp.async.cg.shared.global [%0], [%1], 16;" :: "r"(dst), "l"(src));
}
__device__ __forceinline__ uint32_t pack2(__nv_bfloat16 a, __nv_bfloat16 b) {
    __nv_bfloat162 t = __halves2bfloat162(a, b);
    return *reinterpret_cast<uint32_t*>(&t);
}
__device__ __forceinline__ void split2(float x, __nv_bfloat16& h, __nv_bfloat16& l) {
    h = __float2bfloat16(x);
    l = __float2bfloat16(x - __bfloat162float(h));
}
__device__ __forceinline__ float gelu_tanh(float x) {
    float u = 0.7978845608028654f * (x + 0.044715f * x * x * x);
    return 0.5f * x * (1.0f + tanhf(u));
}

// ---------------------------------------------------------------------------
// Scratch
// ---------------------------------------------------------------------------
__device__ __nv_bfloat16 g_wt_hi[16777216];
__device__ __nv_bfloat16 g_wt_lo[16777216];
__device__ __nv_bfloat16 g_qkv_hi[MM * 3 * CC];
__device__ __nv_bfloat16 g_qkv_lo[MM * 3 * CC];
__device__ __nv_bfloat16 g_q_hi[MM * CC];
__device__ __nv_bfloat16 g_q_lo[MM * CC];
__device__ __nv_bfloat16 g_kv_hi[MIMG * 2 * CC];
__device__ __nv_bfloat16 g_kv_lo[MIMG * 2 * CC];
__device__ __nv_bfloat16 g_a_hi[MM * CC];
__device__ __nv_bfloat16 g_a_lo[MM * CC];
__device__ __nv_bfloat16 g_ff_hi[MM * FFD];
__device__ __nv_bfloat16 g_ff_lo[MM * FFD];
__device__ __nv_bfloat16 g_xi_hi[MIMG * CC];
__device__ __nv_bfloat16 g_xi_lo[MIMG * CC];
__device__ float g_bkv[2 * CC];

#define OFF_ATTN  0u
#define OFF_APROJ 3145728u
#define OFF_Q     4194304u
#define OFF_K     5242880u
#define OFF_V     6291456u
#define OFF_CPROJ 7340032u
#define OFF_FC    8388608u
#define OFF_MPROJ 12582912u

// ---------------------------------------------------------------------------
// transpose + split: W[K,N] fp32 -> Wt_hi/lo[N,K] bf16
// ---------------------------------------------------------------------------
__global__ __launch_bounds__(256) void transpose_split_kernel(
    const float* __restrict__ W, __nv_bfloat16* __restrict__ hi,
    __nv_bfloat16* __restrict__ lo, int K, int N)
{
    __shared__ float t[32][33];
    const int n0 = blockIdx.x * 32, k0 = blockIdx.y * 32;
    const int tx = threadIdx.x & 31, ty = threadIdx.x >> 5;
    #pragma unroll
    for (int i = 0; i < 4; i++) {
        int kk = ty + i * 8;
        t[kk][tx] = W[(size_t)(k0 + kk) * N + n0 + tx];
    }
    __syncthreads();
    #pragma unroll
    for (int i = 0; i < 4; i++) {
        int nn = ty + i * 8;
        float v = t[tx][nn];
        __nv_bfloat16 h, l; split2(v, h, l);
        size_t o = (size_t)(n0 + nn) * K + k0 + tx;
        hi[o] = h; lo[o] = l;
    }
}

__global__ void split_kernel(const float* __restrict__ x,
                             __nv_bfloat16* __restrict__ hi,
                             __nv_bfloat16* __restrict__ lo, int n)
{
    int i = blockIdx.x * blockDim.x + threadIdx.x;
    if (i < n) { __nv_bfloat16 h, l; split2(x[i], h, l); hi[i] = h; lo[i] = l; }
}

__global__ void concat_bias_kernel(const float* __restrict__ a,
                                   const float* __restrict__ b,
                                   float* __restrict__ o)
{
    int i = blockIdx.x * blockDim.x + threadIdx.x;
    if (i < CC) o[i] = a[i];
    else if (i < 2 * CC) o[i] = b[i - CC];
}

// ---------------------------------------------------------------------------
// block reduction + LayerNorm (split output)
// ---------------------------------------------------------------------------
__device__ __forceinline__ float block_sum(float v) {
    __shared__ float red[8];
    int lane = threadIdx.x & 31;
    int w    = threadIdx.x >> 5;
    #pragma unroll
    for (int o = 16; o; o >>= 1) v += __shfl_xor_sync(0xffffffffu, v, o);
    __syncthreads();
    if (lane == 0) red[w] = v;
    __syncthreads();
    if (w == 0) {
        v = (lane < 8) ? red[lane] : 0.f;
        #pragma unroll
        for (int o = 4; o; o >>= 1) v += __shfl_xor_sync(0xffffffffu, v, o);
        if (lane == 0) red[0] = v;
    }
    __syncthreads();
    return red[0];
}

__global__ __launch_bounds__(256) void ln_split_kernel(
    const float* __restrict__ in, const float* __restrict__ g,
    const float* __restrict__ b, __nv_bfloat16* __restrict__ out_hi,
    __nv_bfloat16* __restrict__ out_lo)
{
    const int row = blockIdx.x;
    const float4 v = ((const float4*)(in + (size_t)row * CC))[threadIdx.x];
    float s = v.x + v.y + v.z + v.w;
    s = block_sum(s);
    const float mean = s * (1.0f / CC);
    float dx = v.x - mean, dy = v.y - mean, dz = v.z - mean, dw = v.w - mean;
    float sq = dx*dx + dy*dy + dz*dz + dw*dw;
    sq = block_sum(sq);
    const float rstd = rsqrtf(sq * (1.0f / CC) + 1e-5f);
    const float4 gg = ((const float4*)g)[threadIdx.x];
    const float4 bb = ((const float4*)b)[threadIdx.x];
    float o0 = dx * rstd * gg.x + bb.x;
    float o1 = dy * rstd * gg.y + bb.y;
    float o2 = dz * rstd * gg.z + bb.z;
    float o3 = dw * rstd * gg.w + bb.w;
    __nv_bfloat16 h0,h1,h2,h3,l0,l1,l2,l3;
    split2(o0,h0,l0); split2(o1,h1,l1); split2(o2,h2,l2); split2(o3,h3,l3);
    size_t off = (size_t)row * CC + threadIdx.x * 4;
    *(uint2*)(out_hi + off) = make_uint2(pack2(h0,h1), pack2(h2,h3));
    *(uint2*)(out_lo + off) = make_uint2(pack2(l0,l1), pack2(l2,l3));
}

// ---------------------------------------------------------------------------
// HMMA split-bf16 GEMM: out[M,N] = A[M,K] @ Wt[N,K]^T + bias (+res)(gelu)
// Block tile 128(M) x 256(N) x 32(K); 8 warps as 2(M)x4(N) -> warp tile 64x64.
// cp.async double-buffered.
// ---------------------------------------------------------------------------
#define GRS 40
#define ATB (128 * GRS * 2)              // 10240 bytes (A hi or lo)
#define BTB (256 * GRS * 2)              // 20480 bytes (B hi or lo)
#define GSTAGE (2 * ATB + 2 * BTB)       // 61440 per stage
#define GEMM_SMEM (2 * GSTAGE)           // 122880

template<bool GELU, bool SPLIT_OUT>
__global__ __launch_bounds__(256, 1) void mma_gemm(
    const __nv_bfloat16* __restrict__ Ahi, const __nv_bfloat16* __restrict__ Alo,
    const __nv_bfloat16* __restrict__ Bhi, const __nv_bfloat16* __restrict__ Blo,
    const float* __restrict__ bias, const float* __restrict__ res,
    float* __restrict__ outf,
    __nv_bfloat16* __restrict__ out_hi, __nv_bfloat16* __restrict__ out_lo,
    int M, int N, int K)
{
    extern __shared__ __align__(16) char smem[];
    const uint32_t base = smem_u32(smem);
    const int tid = threadIdx.x;
    const int wid = tid >> 5, lane = tid & 31;
    const int wm = wid >> 2, wn = wid & 3;        // 2 x 4 warps
    const int m0 = blockIdx.y * 128, n0 = blockIdx.x * 256;

    const __nv_bfloat16* gA[2] = { Ahi + (size_t)m0 * K, Alo + (size_t)m0 * K };
    const __nv_bfloat16* gB[2] = { Bhi + (size_t)n0 * K, Blo + (size_t)n0 * K };

    auto stage = [&](int k0, int buf) {
        const uint32_t sb = base + buf * GSTAGE;
        // A hi/lo: 128 rows x 32 cols = 512 cp16 each
        #pragma unroll
        for (int t = 0; t < 2; t++) {
            #pragma unroll
            for (int i = 0; i < 2; i++) {
                int idx = tid + i * 256;
                int r = idx >> 2, s = idx & 3;
                cp16(sb + t * ATB + (r * GRS + s * 8) * 2,
                     gA[t] + (size_t)r * K + k0 + s * 8);
            }
        }
        // B hi/lo: 256 rows x 32 cols = 1024 cp16 each
        #pragma unroll
        for (int t = 0; t < 2; t++) {
            #pragma unroll
            for (int i = 0; i < 4; i++) {
                int idx = tid + i * 256;
                int r = idx >> 2, s = idx & 3;
                cp16(sb + 2 * ATB + t * BTB + (r * GRS + s * 8) * 2,
                     gB[t] + (size_t)r * K + k0 + s * 8);
            }
        }
        asm volatile("cp.async.commit_group;");
    };

    const int laRowA = ((lane >> 3) & 1) * 8 + (lane & 7);
    const int laColA = (lane >> 4) * 8;
    const int laRowB = ((lane >> 4) << 3) + (lane & 7);
    const int laColB = ((lane >> 3) & 1) * 8;

    float c[4][8][4];
    #pragma unroll
    for (int i = 0; i < 4; i++)
        #pragma unroll
        for (int j = 0; j < 8; j++)
            #pragma unroll
            for (int q = 0; q < 4; q++) c[i][j][q] = 0.f;

    const int nch = K >> 5;
    stage(0, 0);

    for (int ch = 0; ch < nch; ch++) {
        if (ch + 1 < nch) {
            stage((ch + 1) << 5, (ch + 1) & 1);
            asm volatile("cp.async.wait_group 1;");
        } else {
            asm volatile("cp.async.wait_group 0;");
        }
        __syncthreads();

        const uint32_t sb = base + (ch & 1) * GSTAGE;
        const uint32_t sAh = sb, sAl = sb + ATB;
        const uint32_t sBh = sb + 2 * ATB, sBl = sb + 2 * ATB + BTB;

        #pragma unroll
        for (int ks = 0; ks < 32; ks += 16) {
            uint32_t ah[4][4], al[4][4];
            #pragma unroll
            for (int mf = 0; mf < 4; mf++) {
                uint32_t off = ((wm * 64 + mf * 16 + laRowA) * GRS + ks + laColA) * 2;
                ldsm4(sAh + off, ah[mf][0], ah[mf][1], ah[mf][2], ah[mf][3]);
                ldsm4(sAl + off, al[mf][0], al[mf][1], al[mf][2], al[mf][3]);
            }
            uint32_t bh[8][2], bl[8][2];
            #pragma unroll
            for (int np = 0; np < 4; np++) {
                uint32_t off = ((wn * 64 + np * 16 + laRowB) * GRS + ks + laColB) * 2;
                ldsm4(sBh + off, bh[2*np][0], bh[2*np][1], bh[2*np+1][0], bh[2*np+1][1]);
                ldsm4(sBl + off, bl[2*np][0], bl[2*np][1], bl[2*np+1][0], bl[2*np+1][1]);
            }
            #pragma unroll
            for (int mf = 0; mf < 4; mf++)
                #pragma unroll
                for (int nf = 0; nf < 8; nf++) {
                    mma_bf16(c[mf][nf], ah[mf], bh[nf][0], bh[nf][1]);
                    mma_bf16(c[mf][nf], ah[mf], bl[nf][0], bl[nf][1]);
                    mma_bf16(c[mf][nf], al[mf], bh[nf][0], bh[nf][1]);
                }
        }
        __syncthreads();
    }

    #pragma unroll
    for (int mf = 0; mf < 4; mf++) {
        const int rbase = m0 + wm * 64 + mf * 16 + (lane >> 2);
        #pragma unroll
        for (int nf = 0; nf < 8; nf++) {
            const int gn = n0 + wn * 64 + nf * 8 + (lane & 3) * 2;
            const float2 b2 = *(const float2*)(bias + gn);
            #pragma unroll
            for (int half = 0; half < 2; half++) {
                const int gm = rbase + half * 8;
                float v0 = c[mf][nf][half * 2 + 0] + b2.x;
                float v1 = c[mf][nf][half * 2 + 1] + b2.y;
                if (GELU) { v0 = gelu_tanh(v0); v1 = gelu_tanh(v1); }
                if (!SPLIT_OUT) {
                    if (res) {
                        const float2 r2 = *(const float2*)(res + (size_t)gm * N + gn);
                        v0 += r2.x; v1 += r2.y;
                    }
                    *(float2*)(outf + (size_t)gm * N + gn) = make_float2(v0, v1);
                } else {
                    __nv_bfloat16 h0, l0, h1, l1;
                    split2(v0, h0, l0); split2(v1, h1, l1);
                    *(uint32_t*)(out_hi + (size_t)gm * N + gn) = pack2(h0, h1);
                    *(uint32_t*)(out_lo + (size_t)gm * N + gn) = pack2(l0, l1);
                }
            }
        }
    }
}

// ---------------------------------------------------------------------------
// Flash attention via HMMA. BQ=128 (8 warps x 16 rows), BK=64, D=64.
// cp.async double-buffered K/V, split-bf16 3-pass everywhere.
// ---------------------------------------------------------------------------
#define FRS 72
#define QTB (128 * FRS * 2)          // 18432 (Q hi or lo)
#define KVT (64 * FRS * 2)           // 9216 per tensor
#define KVSTAGE (4 * KVT)            // 36864
#define FLASH_SMEM (2 * QTB + 2 * KVSTAGE)   // 110592

template<bool CAUSAL>
__global__ __launch_bounds__(256, 1) void flash_mma(
    const __nv_bfloat16* __restrict__ Qh, const __nv_bfloat16* __restrict__ Ql,
    const __nv_bfloat16* __restrict__ Kh, const __nv_bfloat16* __restrict__ Kl,
    const __nv_bfloat16* __restrict__ Vh, const __nv_bfloat16* __restrict__ Vl,
    __nv_bfloat16* __restrict__ Ohi, __nv_bfloat16* __restrict__ Olo,
    int Tq, int Tkv, int qS, int kS, float scale)
{
    extern __shared__ __align__(16) char smem[];
    const uint32_t base = smem_u32(smem);
    const uint32_t sQh = base, sQl = base + QTB;

    const int tid = threadIdx.x;
    const int wid = tid >> 5, lane = tid & 31;
    const int bh = blockIdx.y;
    const int b = bh >> 4, h = bh & 15;
    const int qt = blockIdx.x;

    const __nv_bfloat16* Qhb = Qh + (size_t)(b * Tq + qt * 128) * qS + h * 64;
    const __nv_bfloat16* Qlb = Ql + (size_t)(b * Tq + qt * 128) * qS + h * 64;
    const __nv_bfloat16* Khb = Kh + (size_t)(b * Tkv) * kS + h * 64;
    const __nv_bfloat16* Klb = Kl + (size_t)(b * Tkv) * kS + h * 64;
    const __nv_bfloat16* Vhb = Vh + (size_t)(b * Tkv) * kS + h * 64;
    const __nv_bfloat16* Vlb = Vl + (size_t)(b * Tkv) * kS + h * 64;

    auto stage_kv = [&](int kt, int buf) {
        const uint32_t sb = base + 2 * QTB + buf * KVSTAGE;
        #pragma unroll
        for (int i = 0; i < 2; i++) {
            int idx = tid + i * 256;
            int r = idx >> 3, s = idx & 7;
            size_t go = (size_t)(kt * 64 + r) * kS + s * 8;
            uint32_t off = (r * FRS + s * 8) * 2;
            cp16(sb + 0 * KVT + off, Khb + go);
            cp16(sb + 1 * KVT + off, Klb + go);
            cp16(sb + 2 * KVT + off, Vhb + go);
            cp16(sb + 3 * KVT + off, Vlb + go);
        }
        asm volatile("cp.async.commit_group;");
    };

    // stage Q (group 0, together with kv stage 0)
    #pragma unroll
    for (int i = 0; i < 4; i++) {
        int idx = tid + i * 256;
        int r = idx >> 3, s = idx & 7;
        size_t go = (size_t)r * qS + s * 8;
        uint32_t off = (r * FRS + s * 8) * 2;
        cp16(sQh + off, Qhb + go);
        cp16(sQl + off, Qlb + go);
    }
    stage_kv(0, 0);   // commits group containing Q + kv0

    const int laRowA = ((lane >> 3) & 1) * 8 + (lane & 7);
    const int laColA = (lane >> 4) * 8;
    const int laRowB = ((lane >> 4) << 3) + (lane & 7);
    const int laColB = ((lane >> 3) & 1) * 8;

    float o[8][4];
    #pragma unroll
    for (int i = 0; i < 8; i++)
        #pragma unroll
        for (int j = 0; j < 4; j++) o[i][j] = 0.f;
    float mr0 = -1e30f, mr1 = -1e30f, lr0 = 0.f, lr1 = 0.f;

    const int nkt = CAUSAL ? (2 * qt + 2) : (Tkv >> 6);

    for (int kt = 0; kt < nkt; kt++) {
        if (kt + 1 < nkt) {
            stage_kv(kt + 1, (kt + 1) & 1);
            asm volatile("cp.async.wait_group 1;");
        } else {
            asm volatile("cp.async.wait_group 0;");
        }
        __syncthreads();

        const uint32_t sb = base + 2 * QTB + (kt & 1) * KVSTAGE;
        const uint32_t sKh = sb, sKl = sb + KVT, sVh = sb + 2 * KVT, sVl = sb + 3 * KVT;

        // S = Q @ K^T (3-pass split)
        float s[8][4];
        #pragma unroll
        for (int i = 0; i < 8; i++)
            #pragma unroll
            for (int j = 0; j < 4; j++) s[i][j] = 0.f;

        #pragma unroll
        for (int ks = 0; ks < 4; ks++) {
            uint32_t qh[4], ql[4];
            uint32_t qoff = ((wid * 16 + laRowA) * FRS + ks * 16 + laColA) * 2;
            ldsm4(sQh + qoff, qh[0], qh[1], qh[2], qh[3]);
            ldsm4(sQl + qoff, ql[0], ql[1], ql[2], ql[3]);
            #pragma unroll
            for (int np = 0; np < 4; np++) {
                uint32_t koff = ((np * 16 + laRowB) * FRS + ks * 16 + laColB) * 2;
                uint32_t kh0, kh1, kh2, kh3, kl0, kl1, kl2, kl3;
                ldsm4(sKh + koff, kh0, kh1, kh2, kh3);
                ldsm4(sKl + koff, kl0, kl1, kl2, kl3);
                mma_bf16(s[2*np],   qh, kh0, kh1);
                mma_bf16(s[2*np],   qh, kl0, kl1);
                mma_bf16(s[2*np],   ql, kh0, kh1);
                mma_bf16(s[2*np+1], qh, kh2, kh3);
                mma_bf16(s[2*np+1], qh, kl2, kl3);
                mma_bf16(s[2*np+1], ql, kh2, kh3);
            }
        }
        #pragma unroll
        for (int i = 0; i < 8; i++)
            #pragma unroll
            for (int j = 0; j < 4; j++) s[i][j] *= scale;

        if (CAUSAL && kt >= 2 * qt) {
            const int row0 = qt * 128 + wid * 16 + (lane >> 2);
            #pragma unroll
            for (int nf = 0; nf < 8; nf++) {
                const int col = kt * 64 + nf * 8 + (lane & 3) * 2;
                if (col     > row0)     s[nf][0] = -1e30f;
                if (col + 1 > row0)     s[nf][1] = -1e30f;
                if (col     > row0 + 8) s[nf][2] = -1e30f;
                if (col + 1 > row0 + 8) s[nf][3] = -1e30f;
            }
        }

        float t0 = -1e30f, t1 = -1e30f;
        #pragma unroll
        for (int nf = 0; nf < 8; nf++) {
            t0 = fmaxf(t0, fmaxf(s[nf][0], s[nf][1]));
            t1 = fmaxf(t1, fmaxf(s[nf][2], s[nf][3]));
        }
        t0 = fmaxf(t0, __shfl_xor_sync(0xffffffffu, t0, 1));
        t0 = fmaxf(t0, __shfl_xor_sync(0xffffffffu, t0, 2));
        t1 = fmaxf(t1, __shfl_xor_sync(0xffffffffu, t1, 1));
        t1 = fmaxf(t1, __shfl_xor_sync(0xffffffffu, t1, 2));
        const float nm0 = fmaxf(mr0, t0), nm1 = fmaxf(mr1, t1);
        const float f0 = __expf(mr0 - nm0), f1 = __expf(mr1 - nm1);
        mr0 = nm0; mr1 = nm1;

        float rs0 = 0.f, rs1 = 0.f;
        #pragma unroll
        for (int nf = 0; nf < 8; nf++) {
            s[nf][0] = __expf(s[nf][0] - nm0);
            s[nf][1] = __expf(s[nf][1] - nm0);
            s[nf][2] = __expf(s[nf][2] - nm1);
            s[nf][3] = __expf(s[nf][3] - nm1);
            rs0 += s[nf][0] + s[nf][1];
            rs1 += s[nf][2] + s[nf][3];
        }
        rs0 += __shfl_xor_sync(0xffffffffu, rs0, 1);
        rs0 += __shfl_xor_sync(0xffffffffu, rs0, 2);
        rs1 += __shfl_xor_sync(0xffffffffu, rs1, 1);
        rs1 += __shfl_xor_sync(0xffffffffu, rs1, 2);
        lr0 = lr0 * f0 + rs0;
        lr1 = lr1 * f1 + rs1;
        #pragma unroll
        for (int nf = 0; nf < 8; nf++) {
            o[nf][0] *= f0; o[nf][1] *= f0;
            o[nf][2] *= f1; o[nf][3] *= f1;
        }

        uint32_t ph[4][4], pl[4][4];
        #pragma unroll
        for (int j = 0; j < 4; j++) {
            __nv_bfloat16 h0,h1,l0,l1;
            split2(s[2*j][0], h0, l0);   split2(s[2*j][1], h1, l1);
            ph[j][0] = pack2(h0, h1);    pl[j][0] = pack2(l0, l1);
            split2(s[2*j][2], h0, l0);   split2(s[2*j][3], h1, l1);
            ph[j][1] = pack2(h0, h1);    pl[j][1] = pack2(l0, l1);
            split2(s[2*j+1][0], h0, l0); split2(s[2*j+1][1], h1, l1);
            ph[j][2] = pack2(h0, h1);    pl[j][2] = pack2(l0, l1);
            split2(s[2*j+1][2], h0, l0); split2(s[2*j+1][3], h1, l1);
            ph[j][3] = pack2(h0, h1);    pl[j][3] = pack2(l0, l1);
        }

        #pragma unroll
        for (int j = 0; j < 4; j++) {
            #pragma unroll
            for (int np = 0; np < 4; np++) {
                uint32_t voff = ((j * 16 + laRowA) * FRS + np * 16 + laColA) * 2;
                uint32_t vh0, vh1, vh2, vh3, vl0, vl1, vl2, vl3;
                ldsm4t(sVh + voff, vh0, vh1, vh2, vh3);
                ldsm4t(sVl + voff, vl0, vl1, vl2, vl3);
                mma_bf16(o[2*np],   ph[j], vh0, vh1);
                mma_bf16(o[2*np],   ph[j], vl0, vl1);
                mma_bf16(o[2*np],   pl[j], vh0, vh1);
                mma_bf16(o[2*np+1], ph[j], vh2, vh3);
                mma_bf16(o[2*np+1], ph[j], vl2, vl3);
                mma_bf16(o[2*np+1], pl[j], vh2, vh3);
            }
        }
        __syncthreads();   // all warps done with this KV buffer before restage
    }

    const float inv0 = 1.0f / lr0, inv1 = 1.0f / lr1;
    const int row0 = qt * 128 + wid * 16 + (lane >> 2);
    #pragma unroll
    for (int nf = 0; nf < 8; nf++) {
        const int col = h * 64 + nf * 8 + (lane & 3) * 2;
        {
            float v0 = o[nf][0] * inv0, v1 = o[nf][1] * inv0;
            __nv_bfloat16 h0, l0, h1, l1;
            split2(v0, h0, l0); split2(v1, h1, l1);
            size_t off = (size_t)(b * Tq + row0) * CC + col;
            *(uint32_t*)(Ohi + off) = pack2(h0, h1);
            *(uint32_t*)(Olo + off) = pack2(l0, l1);
        }
        {
            float v0 = o[nf][2] * inv1, v1 = o[nf][3] * inv1;
            __nv_bfloat16 h0, l0, h1, l1;
            split2(v0, h0, l0); split2(v1, h1, l1);
            size_t off = (size_t)(b * Tq + row0 + 8) * CC + col;
            *(uint32_t*)(Ohi + off) = pack2(h0, h1);
            *(uint32_t*)(Olo + off) = pack2(l0, l1);
        }
    }
}

// ---------------------------------------------------------------------------
// Launch sequence
// ---------------------------------------------------------------------------
extern "C" void kernel_launch(void* const* d_in, const int* in_sizes, int n_in,
                              void* d_out, int out_size)
{
    (void)in_sizes; (void)n_in; (void)out_size;
    const float* x      = (const float*)d_in[0];
    const float* ximg   = (const float*)d_in[1];
    const float* ln1_g  = (const float*)d_in[2];
    const float* ln1_b  = (const float*)d_in[3];
    const float* ln2_g  = (const float*)d_in[4];
    const float* ln2_b  = (const float*)d_in[5];
    const float* W_attn = (const float*)d_in[6];
    const float* b_attn = (const float*)d_in[7];
    const float* W_aproj= (const float*)d_in[8];
    const float* b_aproj= (const float*)d_in[9];
    const float* Wq     = (const float*)d_in[10];
    const float* bq     = (const float*)d_in[11];
    const float* Wk     = (const float*)d_in[12];
    const float* bk     = (const float*)d_in[13];
    const float* Wv     = (const float*)d_in[14];
    const float* bv     = (const float*)d_in[15];
    const float* Wcproj = (const float*)d_in[16];
    const float* bcproj = (const float*)d_in[17];
    const float* W_fc   = (const float*)d_in[18];
    const float* b_fc   = (const float*)d_in[19];
    const float* W_mproj= (const float*)d_in[20];
    const float* b_mproj= (const float*)d_in[21];
    float* out = (float*)d_out;

    __nv_bfloat16 *wt_hi, *wt_lo, *qkv_hi, *qkv_lo, *q_hi, *q_lo, *kv_hi, *kv_lo,
                  *a_hi, *a_lo, *ff_hi, *ff_lo, *xi_hi, *xi_lo;
    float* bkv;
    cudaGetSymbolAddress((void**)&wt_hi,  g_wt_hi);
    cudaGetSymbolAddress((void**)&wt_lo,  g_wt_lo);
    cudaGetSymbolAddress((void**)&qkv_hi, g_qkv_hi);
    cudaGetSymbolAddress((void**)&qkv_lo, g_qkv_lo);
    cudaGetSymbolAddress((void**)&q_hi,   g_q_hi);
    cudaGetSymbolAddress((void**)&q_lo,   g_q_lo);
    cudaGetSymbolAddress((void**)&kv_hi,  g_kv_hi);
    cudaGetSymbolAddress((void**)&kv_lo,  g_kv_lo);
    cudaGetSymbolAddress((void**)&a_hi,   g_a_hi);
    cudaGetSymbolAddress((void**)&a_lo,   g_a_lo);
    cudaGetSymbolAddress((void**)&ff_hi,  g_ff_hi);
    cudaGetSymbolAddress((void**)&ff_lo,  g_ff_lo);
    cudaGetSymbolAddress((void**)&xi_hi,  g_xi_hi);
    cudaGetSymbolAddress((void**)&xi_lo,  g_xi_lo);
    cudaGetSymbolAddress((void**)&bkv,    g_bkv);

    cudaFuncSetAttribute(mma_gemm<false,false>, cudaFuncAttributeMaxDynamicSharedMemorySize, GEMM_SMEM);
    cudaFuncSetAttribute(mma_gemm<false,true>,  cudaFuncAttributeMaxDynamicSharedMemorySize, GEMM_SMEM);
    cudaFuncSetAttribute(mma_gemm<true,true>,   cudaFuncAttributeMaxDynamicSharedMemorySize, GEMM_SMEM);
    cudaFuncSetAttribute(flash_mma<true>,  cudaFuncAttributeMaxDynamicSharedMemorySize, FLASH_SMEM);
    cudaFuncSetAttribute(flash_mma<false>, cudaFuncAttributeMaxDynamicSharedMemorySize, FLASH_SMEM);

    const float scale = 0.125f;

    // weight prep
    transpose_split_kernel<<<dim3(3*CC/32, CC/32), 256>>>(W_attn,  wt_hi+OFF_ATTN,  wt_lo+OFF_ATTN,  CC, 3*CC);
    transpose_split_kernel<<<dim3(CC/32,   CC/32), 256>>>(W_aproj, wt_hi+OFF_APROJ, wt_lo+OFF_APROJ, CC, CC);
    transpose_split_kernel<<<dim3(CC/32,   CC/32), 256>>>(Wq,      wt_hi+OFF_Q,     wt_lo+OFF_Q,     CC, CC);
    transpose_split_kernel<<<dim3(CC/32,   CC/32), 256>>>(Wk,      wt_hi+OFF_K,     wt_lo+OFF_K,     CC, CC);
    transpose_split_kernel<<<dim3(CC/32,   CC/32), 256>>>(Wv,      wt_hi+OFF_V,     wt_lo+OFF_V,     CC, CC);
    transpose_split_kernel<<<dim3(CC/32,   CC/32), 256>>>(Wcproj,  wt_hi+OFF_CPROJ, wt_lo+OFF_CPROJ, CC, CC);
    transpose_split_kernel<<<dim3(FFD/32,  CC/32), 256>>>(W_fc,    wt_hi+OFF_FC,    wt_lo+OFF_FC,    CC, FFD);
    transpose_split_kernel<<<dim3(CC/32,   FFD/32), 256>>>(W_mproj, wt_hi+OFF_MPROJ, wt_lo+OFF_MPROJ, FFD, CC);
    split_kernel<<<(MIMG*CC + 255)/256, 256>>>(ximg, xi_hi, xi_lo, MIMG*CC);
    concat_bias_kernel<<<(2*CC + 255)/256, 256>>>(bk, bv, bkv);

    // ---- causal self-attention ----
    ln_split_kernel<<<MM, 256>>>(x, ln1_g, ln1_b, a_hi, a_lo);
    mma_gemm<false,true><<<dim3(3*CC/256, MM/128), 256, GEMM_SMEM>>>(
        a_hi, a_lo, wt_hi+OFF_ATTN, wt_lo+OFF_ATTN, b_attn, nullptr,
        nullptr, qkv_hi, qkv_lo, MM, 3*CC, CC);
    flash_mma<true><<<dim3(8, 128), 256, FLASH_SMEM>>>(
        qkv_hi, qkv_lo, qkv_hi + CC, qkv_lo + CC, qkv_hi + 2*CC, qkv_lo + 2*CC,
        a_hi, a_lo, 1024, 1024, 3*CC, 3*CC, scale);
    mma_gemm<false,false><<<dim3(CC/256, MM/128), 256, GEMM_SMEM>>>(
        a_hi, a_lo, wt_hi+OFF_APROJ, wt_lo+OFF_APROJ, b_aproj, x,
        out, nullptr, nullptr, MM, CC, CC);

    // ---- cross-attention ----
    ln_split_kernel<<<MM, 256>>>(out, ln1_g, ln1_b, a_hi, a_lo);
    mma_gemm<false,true><<<dim3(CC/256, MM/128), 256, GEMM_SMEM>>>(
        a_hi, a_lo, wt_hi+OFF_Q, wt_lo+OFF_Q, bq, nullptr,
        nullptr, q_hi, q_lo, MM, CC, CC);
    mma_gemm<false,true><<<dim3(2*CC/256, MIMG/128), 256, GEMM_SMEM>>>(
        xi_hi, xi_lo, wt_hi+OFF_K, wt_lo+OFF_K, bkv, nullptr,
        nullptr, kv_hi, kv_lo, MIMG, 2*CC, CC);
    flash_mma<false><<<dim3(8, 128), 256, FLASH_SMEM>>>(
        q_hi, q_lo, kv_hi, kv_lo, kv_hi + CC, kv_lo + CC,
        a_hi, a_lo, 1024, 256, CC, 2*CC, scale);
    mma_gemm<false,false><<<dim3(CC/256, MM/128), 256, GEMM_SMEM>>>(
        a_hi, a_lo, wt_hi+OFF_CPROJ, wt_lo+OFF_CPROJ, bcproj, out,
        out, nullptr, nullptr, MM, CC, CC);

    // ---- MLP ----
    ln_split_kernel<<<MM, 256>>>(out, ln2_g, ln2_b, a_hi, a_lo);
    mma_gemm<true,true><<<dim3(FFD/256, MM/128), 256, GEMM_SMEM>>>(
        a_hi, a_lo, wt_hi+OFF_FC, wt_lo+OFF_FC, b_fc, nullptr,
        nullptr, ff_hi, ff_lo, MM, FFD, CC);
    mma_gemm<false,false><<<dim3(CC/256, MM/128), 256, GEMM_SMEM>>>(
        ff_hi, ff_lo, wt_hi+OFF_MPROJ, wt_lo+OFF_MPROJ, b_mproj, out,
        out, nullptr, nullptr, MM, CC, FFD);
}

// round 7
// speedup vs baseline: 3.4415x; 1.3453x over previous
#include <cuda_runtime.h>
#include <cuda_fp16.h>
#include <cstdint>
#include <math.h>

#define CC    1024
#define MM    8192
#define MIMG  2048
#define FFD   4096

// ---------------------------------------------------------------------------
// helpers
// ---------------------------------------------------------------------------
__device__ __forceinline__ uint32_t smem_u32(const void* p) {
    uint32_t a;
    asm("{ .reg .u64 t; cvta.to.shared.u64 t, %1; cvt.u32.u64 %0, t; }" : "=r"(a) : "l"(p));
    return a;
}
__device__ __forceinline__ void ldsm4(uint32_t a, uint32_t& r0, uint32_t& r1,
                                      uint32_t& r2, uint32_t& r3) {
    asm volatile("ldmatrix.sync.aligned.m8n8.x4.shared.b16 {%0,%1,%2,%3}, [%4];"
                 : "=r"(r0), "=r"(r1), "=r"(r2), "=r"(r3) : "r"(a));
}
__device__ __forceinline__ void ldsm4t(uint32_t a, uint32_t& r0, uint32_t& r1,
                                       uint32_t& r2, uint32_t& r3) {
    asm volatile("ldmatrix.sync.aligned.m8n8.x4.trans.shared.b16 {%0,%1,%2,%3}, [%4];"
                 : "=r"(r0), "=r"(r1), "=r"(r2), "=r"(r3) : "r"(a));
}
__device__ __forceinline__ void mma_f16(float* c, const uint32_t* a, uint32_t b0, uint32_t b1) {
    asm volatile("mma.sync.aligned.m16n8k16.row.col.f32.f16.f16.f32 "
                 "{%0,%1,%2,%3}, {%4,%5,%6,%7}, {%8,%9}, {%0,%1,%2,%3};"
                 : "+f"(c[0]), "+f"(c[1]), "+f"(c[2]), "+f"(c[3])
                 : "r"(a[0]), "r"(a[1]), "r"(a[2]), "r"(a[3]), "r"(b0), "r"(b1));
}
__device__ __forceinline__ void cp16(uint32_t dst, const void* src) {
    asm volatile("cp.async.cg.shared.global [%0], [%1], 16;" :: "r"(dst), "l"(src));
}
__device__ __forceinline__ uint32_t pack2(__half a, __half b) {
    __half2 t = __halves2half2(a, b);
    return *reinterpret_cast<uint32_t*>(&t);
}
__device__ __forceinline__ void split2(float x, __half& h, __half& l) {
    h = __float2half(x);
    l = __float2half(x - __half2float(h));
}
__device__ __forceinline__ float gelu_tanh(float x) {
    float u = 0.7978845608028654f * (x + 0.044715f * x * x * x);
    return 0.5f * x * (1.0f + tanhf(u));
}

// ---------------------------------------------------------------------------
// Scratch
// ---------------------------------------------------------------------------
__device__ __half g_wt_hi[16777216];
__device__ __half g_wt_lo[16777216];
__device__ __half g_qkv_hi[MM * 3 * CC];
__device__ __half g_qkv_lo[MM * 3 * CC];
__device__ __half g_q_hi[MM * CC];
__device__ __half g_kv_hi[MIMG * 2 * CC];
__device__ __half g_kv_lo[MIMG * 2 * CC];
__device__ __half g_a_hi[MM * CC];
__device__ __half g_ff_hi[MM * FFD];
__device__ __half g_xi_hi[MIMG * CC];
__device__ float g_bkv[2 * CC];

#define OFF_ATTN  0u
#define OFF_APROJ 3145728u
#define OFF_Q     4194304u
#define OFF_K     5242880u
#define OFF_V     6291456u
#define OFF_CPROJ 7340032u
#define OFF_FC    8388608u
#define OFF_MPROJ 12582912u

// ---------------------------------------------------------------------------
// transpose + split: W[K,N] fp32 -> Wt_hi/lo[N,K] fp16
// ---------------------------------------------------------------------------
__global__ __launch_bounds__(256) void transpose_split_kernel(
    const float* __restrict__ W, __half* __restrict__ hi,
    __half* __restrict__ lo, int K, int N)
{
    __shared__ float t[32][33];
    const int n0 = blockIdx.x * 32, k0 = blockIdx.y * 32;
    const int tx = threadIdx.x & 31, ty = threadIdx.x >> 5;
    #pragma unroll
    for (int i = 0; i < 4; i++) {
        int kk = ty + i * 8;
        t[kk][tx] = W[(size_t)(k0 + kk) * N + n0 + tx];
    }
    __syncthreads();
    #pragma unroll
    for (int i = 0; i < 4; i++) {
        int nn = ty + i * 8;
        float v = t[tx][nn];
        __half h, l; split2(v, h, l);
        size_t o = (size_t)(n0 + nn) * K + k0 + tx;
        hi[o] = h; lo[o] = l;
    }
}

// fp32 -> fp16 (hi only), for x_img_feats
__global__ void tofp16_kernel(const float* __restrict__ x,
                              __half* __restrict__ hi, int n)
{
    int i = blockIdx.x * blockDim.x + threadIdx.x;
    if (i < n) hi[i] = __float2half(x[i]);
}

__global__ void concat_bias_kernel(const float* __restrict__ a,
                                   const float* __restrict__ b,
                                   float* __restrict__ o)
{
    int i = blockIdx.x * blockDim.x + threadIdx.x;
    if (i < CC) o[i] = a[i];
    else if (i < 2 * CC) o[i] = b[i - CC];
}

// ---------------------------------------------------------------------------
// block reduction + LayerNorm (fp16 hi output)
// ---------------------------------------------------------------------------
__device__ __forceinline__ float block_sum(float v) {
    __shared__ float red[8];
    int lane = threadIdx.x & 31;
    int w    = threadIdx.x >> 5;
    #pragma unroll
    for (int o = 16; o; o >>= 1) v += __shfl_xor_sync(0xffffffffu, v, o);
    __syncthreads();
    if (lane == 0) red[w] = v;
    __syncthreads();
    if (w == 0) {
        v = (lane < 8) ? red[lane] : 0.f;
        #pragma unroll
        for (int o = 4; o; o >>= 1) v += __shfl_xor_sync(0xffffffffu, v, o);
        if (lane == 0) red[0] = v;
    }
    __syncthreads();
    return red[0];
}

__global__ __launch_bounds__(256) void ln_h_kernel(
    const float* __restrict__ in, const float* __restrict__ g,
    const float* __restrict__ b, __half* __restrict__ out_hi)
{
    const int row = blockIdx.x;
    const float4 v = ((const float4*)(in + (size_t)row * CC))[threadIdx.x];
    float s = v.x + v.y + v.z + v.w;
    s = block_sum(s);
    const float mean = s * (1.0f / CC);
    float dx = v.x - mean, dy = v.y - mean, dz = v.z - mean, dw = v.w - mean;
    float sq = dx*dx + dy*dy + dz*dz + dw*dw;
    sq = block_sum(sq);
    const float rstd = rsqrtf(sq * (1.0f / CC) + 1e-5f);
    const float4 gg = ((const float4*)g)[threadIdx.x];
    const float4 bb = ((const float4*)b)[threadIdx.x];
    __half h0 = __float2half(dx * rstd * gg.x + bb.x);
    __half h1 = __float2half(dy * rstd * gg.y + bb.y);
    __half h2 = __float2half(dz * rstd * gg.z + bb.z);
    __half h3 = __float2half(dw * rstd * gg.w + bb.w);
    size_t off = (size_t)row * CC + threadIdx.x * 4;
    *(uint2*)(out_hi + off) = make_uint2(pack2(h0,h1), pack2(h2,h3));
}

// ---------------------------------------------------------------------------
// HMMA fp16 2-pass GEMM: out[M,N] ≈ Ah[M,K] @ (Bh+Bl)[N,K]^T + bias
// Block 128x256x32; 8 warps 2(M)x4(N); warp tile 64x64; 3-stage cp.async.
// OMODE: 0 = fp32 out (+res), 1 = fp16 hi out, 2 = fp16 hi+lo out
// ---------------------------------------------------------------------------
#define GRS 40
#define ATB (128 * GRS * 2)              // 10240 bytes (A hi)
#define BTB (256 * GRS * 2)              // 20480 bytes (B hi or lo)
#define GSTAGE (ATB + 2 * BTB)           // 51200 per stage
#define GEMM_SMEM (3 * GSTAGE)           // 153600

template<int OMODE, bool GELU>
__global__ __launch_bounds__(256, 1) void mma_gemm(
    const __half* __restrict__ Ahi,
    const __half* __restrict__ Bhi, const __half* __restrict__ Blo,
    const float* __restrict__ bias, const float* __restrict__ res,
    float* __restrict__ outf,
    __half* __restrict__ out_hi, __half* __restrict__ out_lo,
    int M, int N, int K)
{
    extern __shared__ __align__(16) char smem[];
    const uint32_t base = smem_u32(smem);
    const int tid = threadIdx.x;
    const int wid = tid >> 5, lane = tid & 31;
    const int wm = wid >> 2, wn = wid & 3;
    const int m0 = blockIdx.y * 128, n0 = blockIdx.x * 256;

    const __half* gA = Ahi + (size_t)m0 * K;
    const __half* gB[2] = { Bhi + (size_t)n0 * K, Blo + (size_t)n0 * K };

    auto stage = [&](int k0, int buf) {
        const uint32_t sb = base + buf * GSTAGE;
        #pragma unroll
        for (int i = 0; i < 2; i++) {
            int idx = tid + i * 256;
            int r = idx >> 2, s = idx & 3;
            cp16(sb + (r * GRS + s * 8) * 2, gA + (size_t)r * K + k0 + s * 8);
        }
        #pragma unroll
        for (int t = 0; t < 2; t++) {
            #pragma unroll
            for (int i = 0; i < 4; i++) {
                int idx = tid + i * 256;
                int r = idx >> 2, s = idx & 3;
                cp16(sb + ATB + t * BTB + (r * GRS + s * 8) * 2,
                     gB[t] + (size_t)r * K + k0 + s * 8);
            }
        }
        asm volatile("cp.async.commit_group;");
    };

    const int laRowA = ((lane >> 3) & 1) * 8 + (lane & 7);
    const int laColA = (lane >> 4) * 8;
    const int laRowB = ((lane >> 4) << 3) + (lane & 7);
    const int laColB = ((lane >> 3) & 1) * 8;

    float c[4][8][4];
    #pragma unroll
    for (int i = 0; i < 4; i++)
        #pragma unroll
        for (int j = 0; j < 8; j++)
            #pragma unroll
            for (int q = 0; q < 4; q++) c[i][j][q] = 0.f;

    const int nch = K >> 5;
    stage(0, 0);
    stage(32, 1);

    for (int ch = 0; ch < nch; ch++) {
        if (ch + 1 < nch) asm volatile("cp.async.wait_group 1;");
        else              asm volatile("cp.async.wait_group 0;");
        __syncthreads();
        if (ch + 2 < nch) stage((ch + 2) << 5, (ch + 2) % 3);

        const uint32_t sb = base + (ch % 3) * GSTAGE;
        const uint32_t sA = sb;
        const uint32_t sBh = sb + ATB, sBl = sb + ATB + BTB;

        #pragma unroll
        for (int ks = 0; ks < 32; ks += 16) {
            uint32_t a[4][4];
            #pragma unroll
            for (int mf = 0; mf < 4; mf++) {
                uint32_t off = ((wm * 64 + mf * 16 + laRowA) * GRS + ks + laColA) * 2;
                ldsm4(sA + off, a[mf][0], a[mf][1], a[mf][2], a[mf][3]);
            }
            uint32_t bh[8][2], bl[8][2];
            #pragma unroll
            for (int np = 0; np < 4; np++) {
                uint32_t off = ((wn * 64 + np * 16 + laRowB) * GRS + ks + laColB) * 2;
                ldsm4(sBh + off, bh[2*np][0], bh[2*np][1], bh[2*np+1][0], bh[2*np+1][1]);
                ldsm4(sBl + off, bl[2*np][0], bl[2*np][1], bl[2*np+1][0], bl[2*np+1][1]);
            }
            #pragma unroll
            for (int mf = 0; mf < 4; mf++)
                #pragma unroll
                for (int nf = 0; nf < 8; nf++) {
                    mma_f16(c[mf][nf], a[mf], bh[nf][0], bh[nf][1]);
                    mma_f16(c[mf][nf], a[mf], bl[nf][0], bl[nf][1]);
                }
        }
    }

    __syncthreads();

    #pragma unroll
    for (int mf = 0; mf < 4; mf++) {
        const int rbase = m0 + wm * 64 + mf * 16 + (lane >> 2);
        #pragma unroll
        for (int nf = 0; nf < 8; nf++) {
            const int gn = n0 + wn * 64 + nf * 8 + (lane & 3) * 2;
            const float2 b2 = *(const float2*)(bias + gn);
            #pragma unroll
            for (int half_ = 0; half_ < 2; half_++) {
                const int gm = rbase + half_ * 8;
                float v0 = c[mf][nf][half_ * 2 + 0] + b2.x;
                float v1 = c[mf][nf][half_ * 2 + 1] + b2.y;
                if (GELU) { v0 = gelu_tanh(v0); v1 = gelu_tanh(v1); }
                if (OMODE == 0) {
                    if (res) {
                        const float2 r2 = *(const float2*)(res + (size_t)gm * N + gn);
                        v0 += r2.x; v1 += r2.y;
                    }
                    *(float2*)(outf + (size_t)gm * N + gn) = make_float2(v0, v1);
                } else if (OMODE == 1) {
                    *(uint32_t*)(out_hi + (size_t)gm * N + gn) =
                        pack2(__float2half(v0), __float2half(v1));
                } else {
                    __half h0, l0, h1, l1;
                    split2(v0, h0, l0); split2(v1, h1, l1);
                    *(uint32_t*)(out_hi + (size_t)gm * N + gn) = pack2(h0, h1);
                    *(uint32_t*)(out_lo + (size_t)gm * N + gn) = pack2(l0, l1);
                }
            }
        }
    }
}

// ---------------------------------------------------------------------------
// Flash attention, fp16 2-pass. BQ=128 (8 warps), BK=64, D=64.
// Q: hi only. K,V: hi+lo. Output: hi only.
// ---------------------------------------------------------------------------
#define FRS 72
#define QTB (128 * FRS * 2)          // 18432
#define KVT (64 * FRS * 2)           // 9216
#define KVSTAGE (4 * KVT)            // 36864
#define FLASH_SMEM (QTB + 2 * KVSTAGE)   // 92160

template<bool CAUSAL>
__global__ __launch_bounds__(256, 1) void flash_mma(
    const __half* __restrict__ Qh,
    const __half* __restrict__ Kh, const __half* __restrict__ Kl,
    const __half* __restrict__ Vh, const __half* __restrict__ Vl,
    __half* __restrict__ Ohi,
    int Tq, int Tkv, int qS, int kS, float scale)
{
    extern __shared__ __align__(16) char smem[];
    const uint32_t base = smem_u32(smem);
    const uint32_t sQ = base;

    const int tid = threadIdx.x;
    const int wid = tid >> 5, lane = tid & 31;
    const int bh = blockIdx.y;
    const int b = bh >> 4, h = bh & 15;
    const int qt = blockIdx.x;

    const __half* Qb  = Qh + (size_t)(b * Tq + qt * 128) * qS + h * 64;
    const __half* Khb = Kh + (size_t)(b * Tkv) * kS + h * 64;
    const __half* Klb = Kl + (size_t)(b * Tkv) * kS + h * 64;
    const __half* Vhb = Vh + (size_t)(b * Tkv) * kS + h * 64;
    const __half* Vlb = Vl + (size_t)(b * Tkv) * kS + h * 64;

    auto stage_kv = [&](int kt, int buf) {
        const uint32_t sb = base + QTB + buf * KVSTAGE;
        #pragma unroll
        for (int i = 0; i < 2; i++) {
            int idx = tid + i * 256;
            int r = idx >> 3, s = idx & 7;
            size_t go = (size_t)(kt * 64 + r) * kS + s * 8;
            uint32_t off = (r * FRS + s * 8) * 2;
            cp16(sb + 0 * KVT + off, Khb + go);
            cp16(sb + 1 * KVT + off, Klb + go);
            cp16(sb + 2 * KVT + off, Vhb + go);
            cp16(sb + 3 * KVT + off, Vlb + go);
        }
        asm volatile("cp.async.commit_group;");
    };

    // stage Q (hi only) + kv0 in group 0
    #pragma unroll
    for (int i = 0; i < 4; i++) {
        int idx = tid + i * 256;
        int r = idx >> 3, s = idx & 7;
        cp16(sQ + (r * FRS + s * 8) * 2, Qb + (size_t)r * qS + s * 8);
    }
    stage_kv(0, 0);

    const int laRowA = ((lane >> 3) & 1) * 8 + (lane & 7);
    const int laColA = (lane >> 4) * 8;
    const int laRowB = ((lane >> 4) << 3) + (lane & 7);
    const int laColB = ((lane >> 3) & 1) * 8;

    float o[8][4];
    #pragma unroll
    for (int i = 0; i < 8; i++)
        #pragma unroll
        for (int j = 0; j < 4; j++) o[i][j] = 0.f;
    float mr0 = -1e30f, mr1 = -1e30f, lr0 = 0.f, lr1 = 0.f;

    const int nkt = CAUSAL ? (2 * qt + 2) : (Tkv >> 6);

    for (int kt = 0; kt < nkt; kt++) {
        if (kt + 1 < nkt) {
            stage_kv(kt + 1, (kt + 1) & 1);
            asm volatile("cp.async.wait_group 1;");
        } else {
            asm volatile("cp.async.wait_group 0;");
        }
        __syncthreads();

        const uint32_t sb = base + QTB + (kt & 1) * KVSTAGE;
        const uint32_t sKh = sb, sKl = sb + KVT, sVh = sb + 2 * KVT, sVl = sb + 3 * KVT;

        // S = Qh @ (Kh + Kl)^T
        float s[8][4];
        #pragma unroll
        for (int i = 0; i < 8; i++)
            #pragma unroll
            for (int j = 0; j < 4; j++) s[i][j] = 0.f;

        #pragma unroll
        for (int ks = 0; ks < 4; ks++) {
            uint32_t q[4];
            uint32_t qoff = ((wid * 16 + laRowA) * FRS + ks * 16 + laColA) * 2;
            ldsm4(sQ + qoff, q[0], q[1], q[2], q[3]);
            #pragma unroll
            for (int np = 0; np < 4; np++) {
                uint32_t koff = ((np * 16 + laRowB) * FRS + ks * 16 + laColB) * 2;
                uint32_t kh0, kh1, kh2, kh3, kl0, kl1, kl2, kl3;
                ldsm4(sKh + koff, kh0, kh1, kh2, kh3);
                ldsm4(sKl + koff, kl0, kl1, kl2, kl3);
                mma_f16(s[2*np],   q, kh0, kh1);
                mma_f16(s[2*np],   q, kl0, kl1);
                mma_f16(s[2*np+1], q, kh2, kh3);
                mma_f16(s[2*np+1], q, kl2, kl3);
            }
        }
        #pragma unroll
        for (int i = 0; i < 8; i++)
            #pragma unroll
            for (int j = 0; j < 4; j++) s[i][j] *= scale;

        if (CAUSAL && kt >= 2 * qt) {
            const int row0 = qt * 128 + wid * 16 + (lane >> 2);
            #pragma unroll
            for (int nf = 0; nf < 8; nf++) {
                const int col = kt * 64 + nf * 8 + (lane & 3) * 2;
                if (col     > row0)     s[nf][0] = -1e30f;
                if (col + 1 > row0)     s[nf][1] = -1e30f;
                if (col     > row0 + 8) s[nf][2] = -1e30f;
                if (col + 1 > row0 + 8) s[nf][3] = -1e30f;
            }
        }

        float t0 = -1e30f, t1 = -1e30f;
        #pragma unroll
        for (int nf = 0; nf < 8; nf++) {
            t0 = fmaxf(t0, fmaxf(s[nf][0], s[nf][1]));
            t1 = fmaxf(t1, fmaxf(s[nf][2], s[nf][3]));
        }
        t0 = fmaxf(t0, __shfl_xor_sync(0xffffffffu, t0, 1));
        t0 = fmaxf(t0, __shfl_xor_sync(0xffffffffu, t0, 2));
        t1 = fmaxf(t1, __shfl_xor_sync(0xffffffffu, t1, 1));
        t1 = fmaxf(t1, __shfl_xor_sync(0xffffffffu, t1, 2));
        const float nm0 = fmaxf(mr0, t0), nm1 = fmaxf(mr1, t1);
        const float f0 = __expf(mr0 - nm0), f1 = __expf(mr1 - nm1);
        mr0 = nm0; mr1 = nm1;

        float rs0 = 0.f, rs1 = 0.f;
        #pragma unroll
        for (int nf = 0; nf < 8; nf++) {
            s[nf][0] = __expf(s[nf][0] - nm0);
            s[nf][1] = __expf(s[nf][1] - nm0);
            s[nf][2] = __expf(s[nf][2] - nm1);
            s[nf][3] = __expf(s[nf][3] - nm1);
            rs0 += s[nf][0] + s[nf][1];
            rs1 += s[nf][2] + s[nf][3];
        }
        rs0 += __shfl_xor_sync(0xffffffffu, rs0, 1);
        rs0 += __shfl_xor_sync(0xffffffffu, rs0, 2);
        rs1 += __shfl_xor_sync(0xffffffffu, rs1, 1);
        rs1 += __shfl_xor_sync(0xffffffffu, rs1, 2);
        lr0 = lr0 * f0 + rs0;
        lr1 = lr1 * f1 + rs1;
        #pragma unroll
        for (int nf = 0; nf < 8; nf++) {
            o[nf][0] *= f0; o[nf][1] *= f0;
            o[nf][2] *= f1; o[nf][3] *= f1;
        }

        // P hi fragments
        uint32_t ph[4][4];
        #pragma unroll
        for (int j = 0; j < 4; j++) {
            ph[j][0] = pack2(__float2half(s[2*j][0]),   __float2half(s[2*j][1]));
            ph[j][1] = pack2(__float2half(s[2*j][2]),   __float2half(s[2*j][3]));
            ph[j][2] = pack2(__float2half(s[2*j+1][0]), __float2half(s[2*j+1][1]));
            ph[j][3] = pack2(__float2half(s[2*j+1][2]), __float2half(s[2*j+1][3]));
        }

        // O += Ph @ (Vh + Vl)
        #pragma unroll
        for (int j = 0; j < 4; j++) {
            #pragma unroll
            for (int np = 0; np < 4; np++) {
                uint32_t voff = ((j * 16 + laRowA) * FRS + np * 16 + laColA) * 2;
                uint32_t vh0, vh1, vh2, vh3, vl0, vl1, vl2, vl3;
                ldsm4t(sVh + voff, vh0, vh1, vh2, vh3);
                ldsm4t(sVl + voff, vl0, vl1, vl2, vl3);
                mma_f16(o[2*np],   ph[j], vh0, vh1);
                mma_f16(o[2*np],   ph[j], vl0, vl1);
                mma_f16(o[2*np+1], ph[j], vh2, vh3);
                mma_f16(o[2*np+1], ph[j], vl2, vl3);
            }
        }
        __syncthreads();
    }

    const float inv0 = 1.0f / lr0, inv1 = 1.0f / lr1;
    const int row0 = qt * 128 + wid * 16 + (lane >> 2);
    #pragma unroll
    for (int nf = 0; nf < 8; nf++) {
        const int col = h * 64 + nf * 8 + (lane & 3) * 2;
        {
            size_t off = (size_t)(b * Tq + row0) * CC + col;
            *(uint32_t*)(Ohi + off) =
                pack2(__float2half(o[nf][0] * inv0), __float2half(o[nf][1] * inv0));
        }
        {
            size_t off = (size_t)(b * Tq + row0 + 8) * CC + col;
            *(uint32_t*)(Ohi + off) =
                pack2(__float2half(o[nf][2] * inv1), __float2half(o[nf][3] * inv1));
        }
    }
}

// ---------------------------------------------------------------------------
// Launch sequence
// ---------------------------------------------------------------------------
extern "C" void kernel_launch(void* const* d_in, const int* in_sizes, int n_in,
                              void* d_out, int out_size)
{
    (void)in_sizes; (void)n_in; (void)out_size;
    const float* x      = (const float*)d_in[0];
    const float* ximg   = (const float*)d_in[1];
    const float* ln1_g  = (const float*)d_in[2];
    const float* ln1_b  = (const float*)d_in[3];
    const float* ln2_g  = (const float*)d_in[4];
    const float* ln2_b  = (const float*)d_in[5];
    const float* W_attn = (const float*)d_in[6];
    const float* b_attn = (const float*)d_in[7];
    const float* W_aproj= (const float*)d_in[8];
    const float* b_aproj= (const float*)d_in[9];
    const float* Wq     = (const float*)d_in[10];
    const float* bq     = (const float*)d_in[11];
    const float* Wk     = (const float*)d_in[12];
    const float* bk     = (const float*)d_in[13];
    const float* Wv     = (const float*)d_in[14];
    const float* bv     = (const float*)d_in[15];
    const float* Wcproj = (const float*)d_in[16];
    const float* bcproj = (const float*)d_in[17];
    const float* W_fc   = (const float*)d_in[18];
    const float* b_fc   = (const float*)d_in[19];
    const float* W_mproj= (const float*)d_in[20];
    const float* b_mproj= (const float*)d_in[21];
    float* out = (float*)d_out;

    __half *wt_hi, *wt_lo, *qkv_hi, *qkv_lo, *q_hi, *kv_hi, *kv_lo,
           *a_hi, *ff_hi, *xi_hi;
    float* bkv;
    cudaGetSymbolAddress((void**)&wt_hi,  g_wt_hi);
    cudaGetSymbolAddress((void**)&wt_lo,  g_wt_lo);
    cudaGetSymbolAddress((void**)&qkv_hi, g_qkv_hi);
    cudaGetSymbolAddress((void**)&qkv_lo, g_qkv_lo);
    cudaGetSymbolAddress((void**)&q_hi,   g_q_hi);
    cudaGetSymbolAddress((void**)&kv_hi,  g_kv_hi);
    cudaGetSymbolAddress((void**)&kv_lo,  g_kv_lo);
    cudaGetSymbolAddress((void**)&a_hi,   g_a_hi);
    cudaGetSymbolAddress((void**)&ff_hi,  g_ff_hi);
    cudaGetSymbolAddress((void**)&xi_hi,  g_xi_hi);
    cudaGetSymbolAddress((void**)&bkv,    g_bkv);

    cudaFuncSetAttribute(mma_gemm<0,false>, cudaFuncAttributeMaxDynamicSharedMemorySize, GEMM_SMEM);
    cudaFuncSetAttribute(mma_gemm<1,false>, cudaFuncAttributeMaxDynamicSharedMemorySize, GEMM_SMEM);
    cudaFuncSetAttribute(mma_gemm<1,true>,  cudaFuncAttributeMaxDynamicSharedMemorySize, GEMM_SMEM);
    cudaFuncSetAttribute(mma_gemm<2,false>, cudaFuncAttributeMaxDynamicSharedMemorySize, GEMM_SMEM);
    cudaFuncSetAttribute(flash_mma<true>,  cudaFuncAttributeMaxDynamicSharedMemorySize, FLASH_SMEM);
    cudaFuncSetAttribute(flash_mma<false>, cudaFuncAttributeMaxDynamicSharedMemorySize, FLASH_SMEM);

    const float scale = 0.125f;

    // weight prep
    transpose_split_kernel<<<dim3(3*CC/32, CC/32), 256>>>(W_attn,  wt_hi+OFF_ATTN,  wt_lo+OFF_ATTN,  CC, 3*CC);
    transpose_split_kernel<<<dim3(CC/32,   CC/32), 256>>>(W_aproj, wt_hi+OFF_APROJ, wt_lo+OFF_APROJ, CC, CC);
    transpose_split_kernel<<<dim3(CC/32,   CC/32), 256>>>(Wq,      wt_hi+OFF_Q,     wt_lo+OFF_Q,     CC, CC);
    transpose_split_kernel<<<dim3(CC/32,   CC/32), 256>>>(Wk,      wt_hi+OFF_K,     wt_lo+OFF_K,     CC, CC);
    transpose_split_kernel<<<dim3(CC/32,   CC/32), 256>>>(Wv,      wt_hi+OFF_V,     wt_lo+OFF_V,     CC, CC);
    transpose_split_kernel<<<dim3(CC/32,   CC/32), 256>>>(Wcproj,  wt_hi+OFF_CPROJ, wt_lo+OFF_CPROJ, CC, CC);
    transpose_split_kernel<<<dim3(FFD/32,  CC/32), 256>>>(W_fc,    wt_hi+OFF_FC,    wt_lo+OFF_FC,    CC, FFD);
    transpose_split_kernel<<<dim3(CC/32,   FFD/32), 256>>>(W_mproj, wt_hi+OFF_MPROJ, wt_lo+OFF_MPROJ, FFD, CC);
    tofp16_kernel<<<(MIMG*CC + 255)/256, 256>>>(ximg, xi_hi, MIMG*CC);
    concat_bias_kernel<<<(2*CC + 255)/256, 256>>>(bk, bv, bkv);

    // ---- causal self-attention ----
    ln_h_kernel<<<MM, 256>>>(x, ln1_g, ln1_b, a_hi);
    mma_gemm<2,false><<<dim3(3*CC/256, MM/128), 256, GEMM_SMEM>>>(
        a_hi, wt_hi+OFF_ATTN, wt_lo+OFF_ATTN, b_attn, nullptr,
        nullptr, qkv_hi, qkv_lo, MM, 3*CC, CC);
    flash_mma<true><<<dim3(8, 128), 256, FLASH_SMEM>>>(
        qkv_hi, qkv_hi + CC, qkv_lo + CC, qkv_hi + 2*CC, qkv_lo + 2*CC,
        a_hi, 1024, 1024, 3*CC, 3*CC, scale);
    mma_gemm<0,false><<<dim3(CC/256, MM/128), 256, GEMM_SMEM>>>(
        a_hi, wt_hi+OFF_APROJ, wt_lo+OFF_APROJ, b_aproj, x,
        out, nullptr, nullptr, MM, CC, CC);

    // ---- cross-attention ----
    ln_h_kernel<<<MM, 256>>>(out, ln1_g, ln1_b, a_hi);
    mma_gemm<1,false><<<dim3(CC/256, MM/128), 256, GEMM_SMEM>>>(
        a_hi, wt_hi+OFF_Q, wt_lo+OFF_Q, bq, nullptr,
        nullptr, q_hi, nullptr, MM, CC, CC);
    mma_gemm<2,false><<<dim3(2*CC/256, MIMG/128), 256, GEMM_SMEM>>>(
        xi_hi, wt_hi+OFF_K, wt_lo+OFF_K, bkv, nullptr,
        nullptr, kv_hi, kv_lo, MIMG, 2*CC, CC);
    flash_mma<false><<<dim3(8, 128), 256, FLASH_SMEM>>>(
        q_hi, kv_hi, kv_lo, kv_hi + CC, kv_lo + CC,
        a_hi, 1024, 256, CC, 2*CC, scale);
    mma_gemm<0,false><<<dim3(CC/256, MM/128), 256, GEMM_SMEM>>>(
        a_hi, wt_hi+OFF_CPROJ, wt_lo+OFF_CPROJ, bcproj, out,
        out, nullptr, nullptr, MM, CC, CC);

    // ---- MLP ----
    ln_h_kernel<<<MM, 256>>>(out, ln2_g, ln2_b, a_hi);
    mma_gemm<1,true><<<dim3(FFD/256, MM/128), 256, GEMM_SMEM>>>(
        a_hi, wt_hi+OFF_FC, wt_lo+OFF_FC, b_fc, nullptr,
        nullptr, ff_hi, nullptr, MM, FFD, CC);
    mma_gemm<0,false><<<dim3(CC/256, MM/128), 256, GEMM_SMEM>>>(
        ff_hi, wt_hi+OFF_MPROJ, wt_lo+OFF_MPROJ, b_mproj, out,
        out, nullptr, nullptr, MM, CC, FFD);
}

// round 8
// speedup vs baseline: 5.6771x; 1.6496x over previous
#include <cuda_runtime.h>
#include <cuda_fp16.h>
#include <cstdint>
#include <math.h>

#define CC    1024
#define MM    8192
#define MIMG  2048
#define FFD   4096

// ---------------------------------------------------------------------------
// helpers
// ---------------------------------------------------------------------------
__device__ __forceinline__ uint32_t smem_u32(const void* p) {
    uint32_t a;
    asm("{ .reg .u64 t; cvta.to.shared.u64 t, %1; cvt.u32.u64 %0, t; }" : "=r"(a) : "l"(p));
    return a;
}
__device__ __forceinline__ void ldsm4(uint32_t a, uint32_t& r0, uint32_t& r1,
                                      uint32_t& r2, uint32_t& r3) {
    asm volatile("ldmatrix.sync.aligned.m8n8.x4.shared.b16 {%0,%1,%2,%3}, [%4];"
                 : "=r"(r0), "=r"(r1), "=r"(r2), "=r"(r3) : "r"(a));
}
__device__ __forceinline__ void ldsm4t(uint32_t a, uint32_t& r0, uint32_t& r1,
                                       uint32_t& r2, uint32_t& r3) {
    asm volatile("ldmatrix.sync.aligned.m8n8.x4.trans.shared.b16 {%0,%1,%2,%3}, [%4];"
                 : "=r"(r0), "=r"(r1), "=r"(r2), "=r"(r3) : "r"(a));
}
__device__ __forceinline__ void mma_f16(float* c, const uint32_t* a, uint32_t b0, uint32_t b1) {
    asm volatile("mma.sync.aligned.m16n8k16.row.col.f32.f16.f16.f32 "
                 "{%0,%1,%2,%3}, {%4,%5,%6,%7}, {%8,%9}, {%0,%1,%2,%3};"
                 : "+f"(c[0]), "+f"(c[1]), "+f"(c[2]), "+f"(c[3])
                 : "r"(a[0]), "r"(a[1]), "r"(a[2]), "r"(a[3]), "r"(b0), "r"(b1));
}
__device__ __forceinline__ void cp16(uint32_t dst, const void* src) {
    asm volatile("cp.async.cg.shared.global [%0], [%1], 16;" :: "r"(dst), "l"(src));
}
__device__ __forceinline__ uint32_t pack2(__half a, __half b) {
    __half2 t = __halves2half2(a, b);
    return *reinterpret_cast<uint32_t*>(&t);
}
__device__ __forceinline__ float gelu_tanh(float x) {
    float u = 0.7978845608028654f * (x + 0.044715f * x * x * x);
    return 0.5f * x * (1.0f + tanhf(u));
}

// ---------------------------------------------------------------------------
// Scratch
// ---------------------------------------------------------------------------
__device__ __half g_wt[16777216];          // transposed fp16 weights [N,K]
__device__ __half g_qkv[MM * 3 * CC];
__device__ __half g_q[MM * CC];
__device__ __half g_kv[MIMG * 2 * CC];
__device__ __half g_a[MM * CC];
__device__ __half g_ff[MM * FFD];
__device__ __half g_xi[MIMG * CC];
__device__ float g_bkv[2 * CC];

#define OFF_ATTN  0u
#define OFF_APROJ 3145728u
#define OFF_Q     4194304u
#define OFF_K     5242880u
#define OFF_V     6291456u
#define OFF_CPROJ 7340032u
#define OFF_FC    8388608u
#define OFF_MPROJ 12582912u

// ---------------------------------------------------------------------------
// transpose + cast: W[K,N] fp32 -> Wt[N,K] fp16
// ---------------------------------------------------------------------------
__global__ __launch_bounds__(256) void transpose_cast_kernel(
    const float* __restrict__ W, __half* __restrict__ o, int K, int N)
{
    __shared__ float t[32][33];
    const int n0 = blockIdx.x * 32, k0 = blockIdx.y * 32;
    const int tx = threadIdx.x & 31, ty = threadIdx.x >> 5;
    #pragma unroll
    for (int i = 0; i < 4; i++) {
        int kk = ty + i * 8;
        t[kk][tx] = W[(size_t)(k0 + kk) * N + n0 + tx];
    }
    __syncthreads();
    #pragma unroll
    for (int i = 0; i < 4; i++) {
        int nn = ty + i * 8;
        o[(size_t)(n0 + nn) * K + k0 + tx] = __float2half(t[tx][nn]);
    }
}

__global__ void tofp16_kernel(const float* __restrict__ x,
                              __half* __restrict__ o, int n)
{
    int i = blockIdx.x * blockDim.x + threadIdx.x;
    if (i < n) o[i] = __float2half(x[i]);
}

__global__ void concat_bias_kernel(const float* __restrict__ a,
                                   const float* __restrict__ b,
                                   float* __restrict__ o)
{
    int i = blockIdx.x * blockDim.x + threadIdx.x;
    if (i < CC) o[i] = a[i];
    else if (i < 2 * CC) o[i] = b[i - CC];
}

// ---------------------------------------------------------------------------
// block reduction + LayerNorm (fp16 output)
// ---------------------------------------------------------------------------
__device__ __forceinline__ float block_sum(float v) {
    __shared__ float red[8];
    int lane = threadIdx.x & 31;
    int w    = threadIdx.x >> 5;
    #pragma unroll
    for (int o = 16; o; o >>= 1) v += __shfl_xor_sync(0xffffffffu, v, o);
    __syncthreads();
    if (lane == 0) red[w] = v;
    __syncthreads();
    if (w == 0) {
        v = (lane < 8) ? red[lane] : 0.f;
        #pragma unroll
        for (int o = 4; o; o >>= 1) v += __shfl_xor_sync(0xffffffffu, v, o);
        if (lane == 0) red[0] = v;
    }
    __syncthreads();
    return red[0];
}

__global__ __launch_bounds__(256) void ln_h_kernel(
    const float* __restrict__ in, const float* __restrict__ g,
    const float* __restrict__ b, __half* __restrict__ out)
{
    const int row = blockIdx.x;
    const float4 v = ((const float4*)(in + (size_t)row * CC))[threadIdx.x];
    float s = v.x + v.y + v.z + v.w;
    s = block_sum(s);
    const float mean = s * (1.0f / CC);
    float dx = v.x - mean, dy = v.y - mean, dz = v.z - mean, dw = v.w - mean;
    float sq = dx*dx + dy*dy + dz*dz + dw*dw;
    sq = block_sum(sq);
    const float rstd = rsqrtf(sq * (1.0f / CC) + 1e-5f);
    const float4 gg = ((const float4*)g)[threadIdx.x];
    const float4 bb = ((const float4*)b)[threadIdx.x];
    __half h0 = __float2half(dx * rstd * gg.x + bb.x);
    __half h1 = __float2half(dy * rstd * gg.y + bb.y);
    __half h2 = __float2half(dz * rstd * gg.z + bb.z);
    __half h3 = __float2half(dw * rstd * gg.w + bb.w);
    size_t off = (size_t)row * CC + threadIdx.x * 4;
    *(uint2*)(out + off) = make_uint2(pack2(h0,h1), pack2(h2,h3));
}

// ---------------------------------------------------------------------------
// HMMA fp16 single-pass GEMM: out[M,N] = A[M,K] @ Wt[N,K]^T + bias
// Block 128x256x32; 8 warps 2(M)x4(N); warp tile 64x64; 4-stage cp.async.
// OMODE: 0 = fp32 out (+res), 1 = fp16 out
// ---------------------------------------------------------------------------
#define GRS 40
#define ATB (128 * GRS * 2)              // 10240 bytes
#define BTB (256 * GRS * 2)              // 20480 bytes
#define GSTAGE (ATB + BTB)               // 30720 per stage
#define GEMM_SMEM (4 * GSTAGE)           // 122880

template<int OMODE, bool GELU>
__global__ __launch_bounds__(256, 1) void mma_gemm(
    const __half* __restrict__ Ah, const __half* __restrict__ Bh,
    const float* __restrict__ bias, const float* __restrict__ res,
    float* __restrict__ outf, __half* __restrict__ outh,
    int M, int N, int K)
{
    extern __shared__ __align__(16) char smem[];
    const uint32_t base = smem_u32(smem);
    const int tid = threadIdx.x;
    const int wid = tid >> 5, lane = tid & 31;
    const int wm = wid >> 2, wn = wid & 3;
    const int m0 = blockIdx.y * 128, n0 = blockIdx.x * 256;

    const __half* gA = Ah + (size_t)m0 * K;
    const __half* gB = Bh + (size_t)n0 * K;

    auto stage = [&](int k0, int buf) {
        const uint32_t sb = base + buf * GSTAGE;
        #pragma unroll
        for (int i = 0; i < 2; i++) {
            int idx = tid + i * 256;
            int r = idx >> 2, s = idx & 3;
            cp16(sb + (r * GRS + s * 8) * 2, gA + (size_t)r * K + k0 + s * 8);
        }
        #pragma unroll
        for (int i = 0; i < 4; i++) {
            int idx = tid + i * 256;
            int r = idx >> 2, s = idx & 3;
            cp16(sb + ATB + (r * GRS + s * 8) * 2, gB + (size_t)r * K + k0 + s * 8);
        }
        asm volatile("cp.async.commit_group;");
    };

    const int laRowA = ((lane >> 3) & 1) * 8 + (lane & 7);
    const int laColA = (lane >> 4) * 8;
    const int laRowB = ((lane >> 4) << 3) + (lane & 7);
    const int laColB = ((lane >> 3) & 1) * 8;

    float c[4][8][4];
    #pragma unroll
    for (int i = 0; i < 4; i++)
        #pragma unroll
        for (int j = 0; j < 8; j++)
            #pragma unroll
            for (int q = 0; q < 4; q++) c[i][j][q] = 0.f;

    const int nch = K >> 5;
    stage(0, 0);
    stage(32, 1);
    stage(64, 2);

    for (int ch = 0; ch < nch; ch++) {
        if (ch + 3 < nch) asm volatile("cp.async.wait_group 2;");
        else if (ch + 2 < nch) asm volatile("cp.async.wait_group 2;");
        else if (ch + 1 < nch) asm volatile("cp.async.wait_group 1;");
        else                   asm volatile("cp.async.wait_group 0;");
        __syncthreads();
        if (ch + 3 < nch) stage((ch + 3) << 5, (ch + 3) & 3);

        const uint32_t sb = base + (ch & 3) * GSTAGE;
        const uint32_t sA = sb, sB = sb + ATB;

        #pragma unroll
        for (int ks = 0; ks < 32; ks += 16) {
            uint32_t a[4][4];
            #pragma unroll
            for (int mf = 0; mf < 4; mf++) {
                uint32_t off = ((wm * 64 + mf * 16 + laRowA) * GRS + ks + laColA) * 2;
                ldsm4(sA + off, a[mf][0], a[mf][1], a[mf][2], a[mf][3]);
            }
            uint32_t bh[8][2];
            #pragma unroll
            for (int np = 0; np < 4; np++) {
                uint32_t off = ((wn * 64 + np * 16 + laRowB) * GRS + ks + laColB) * 2;
                ldsm4(sB + off, bh[2*np][0], bh[2*np][1], bh[2*np+1][0], bh[2*np+1][1]);
            }
            #pragma unroll
            for (int mf = 0; mf < 4; mf++)
                #pragma unroll
                for (int nf = 0; nf < 8; nf++)
                    mma_f16(c[mf][nf], a[mf], bh[nf][0], bh[nf][1]);
        }
    }

    __syncthreads();

    #pragma unroll
    for (int mf = 0; mf < 4; mf++) {
        const int rbase = m0 + wm * 64 + mf * 16 + (lane >> 2);
        #pragma unroll
        for (int nf = 0; nf < 8; nf++) {
            const int gn = n0 + wn * 64 + nf * 8 + (lane & 3) * 2;
            const float2 b2 = *(const float2*)(bias + gn);
            #pragma unroll
            for (int half_ = 0; half_ < 2; half_++) {
                const int gm = rbase + half_ * 8;
                float v0 = c[mf][nf][half_ * 2 + 0] + b2.x;
                float v1 = c[mf][nf][half_ * 2 + 1] + b2.y;
                if (GELU) { v0 = gelu_tanh(v0); v1 = gelu_tanh(v1); }
                if (OMODE == 0) {
                    if (res) {
                        const float2 r2 = *(const float2*)(res + (size_t)gm * N + gn);
                        v0 += r2.x; v1 += r2.y;
                    }
                    *(float2*)(outf + (size_t)gm * N + gn) = make_float2(v0, v1);
                } else {
                    *(uint32_t*)(outh + (size_t)gm * N + gn) =
                        pack2(__float2half(v0), __float2half(v1));
                }
            }
        }
    }
}

// ---------------------------------------------------------------------------
// Flash attention, fp16 single-pass. BQ=128 (8 warps), BK=64, D=64.
// ---------------------------------------------------------------------------
#define FRS 72
#define QTB (128 * FRS * 2)          // 18432
#define KVT (64 * FRS * 2)           // 9216
#define KVSTAGE (2 * KVT)            // 18432
#define FLASH_SMEM (QTB + 2 * KVSTAGE)   // 55296

template<bool CAUSAL>
__global__ __launch_bounds__(256, 1) void flash_mma(
    const __half* __restrict__ Qh,
    const __half* __restrict__ Kh, const __half* __restrict__ Vh,
    __half* __restrict__ Ohi,
    int Tq, int Tkv, int qS, int kS, float scale)
{
    extern __shared__ __align__(16) char smem[];
    const uint32_t base = smem_u32(smem);
    const uint32_t sQ = base;

    const int tid = threadIdx.x;
    const int wid = tid >> 5, lane = tid & 31;
    const int bh = blockIdx.y;
    const int b = bh >> 4, h = bh & 15;
    const int qt = blockIdx.x;

    const __half* Qb  = Qh + (size_t)(b * Tq + qt * 128) * qS + h * 64;
    const __half* Khb = Kh + (size_t)(b * Tkv) * kS + h * 64;
    const __half* Vhb = Vh + (size_t)(b * Tkv) * kS + h * 64;

    auto stage_kv = [&](int kt, int buf) {
        const uint32_t sb = base + QTB + buf * KVSTAGE;
        #pragma unroll
        for (int i = 0; i < 2; i++) {
            int idx = tid + i * 256;
            int r = idx >> 3, s = idx & 7;
            size_t go = (size_t)(kt * 64 + r) * kS + s * 8;
            uint32_t off = (r * FRS + s * 8) * 2;
            cp16(sb + 0 * KVT + off, Khb + go);
            cp16(sb + 1 * KVT + off, Vhb + go);
        }
        asm volatile("cp.async.commit_group;");
    };

    #pragma unroll
    for (int i = 0; i < 4; i++) {
        int idx = tid + i * 256;
        int r = idx >> 3, s = idx & 7;
        cp16(sQ + (r * FRS + s * 8) * 2, Qb + (size_t)r * qS + s * 8);
    }
    stage_kv(0, 0);

    const int laRowA = ((lane >> 3) & 1) * 8 + (lane & 7);
    const int laColA = (lane >> 4) * 8;
    const int laRowB = ((lane >> 4) << 3) + (lane & 7);
    const int laColB = ((lane >> 3) & 1) * 8;

    float o[8][4];
    #pragma unroll
    for (int i = 0; i < 8; i++)
        #pragma unroll
        for (int j = 0; j < 4; j++) o[i][j] = 0.f;
    float mr0 = -1e30f, mr1 = -1e30f, lr0 = 0.f, lr1 = 0.f;

    const int nkt = CAUSAL ? (2 * qt + 2) : (Tkv >> 6);

    for (int kt = 0; kt < nkt; kt++) {
        if (kt + 1 < nkt) {
            stage_kv(kt + 1, (kt + 1) & 1);
            asm volatile("cp.async.wait_group 1;");
        } else {
            asm volatile("cp.async.wait_group 0;");
        }
        __syncthreads();

        const uint32_t sb = base + QTB + (kt & 1) * KVSTAGE;
        const uint32_t sK = sb, sV = sb + KVT;

        float s[8][4];
        #pragma unroll
        for (int i = 0; i < 8; i++)
            #pragma unroll
            for (int j = 0; j < 4; j++) s[i][j] = 0.f;

        #pragma unroll
        for (int ks = 0; ks < 4; ks++) {
            uint32_t q[4];
            uint32_t qoff = ((wid * 16 + laRowA) * FRS + ks * 16 + laColA) * 2;
            ldsm4(sQ + qoff, q[0], q[1], q[2], q[3]);
            #pragma unroll
            for (int np = 0; np < 4; np++) {
                uint32_t koff = ((np * 16 + laRowB) * FRS + ks * 16 + laColB) * 2;
                uint32_t k0, k1, k2, k3;
                ldsm4(sK + koff, k0, k1, k2, k3);
                mma_f16(s[2*np],   q, k0, k1);
                mma_f16(s[2*np+1], q, k2, k3);
            }
        }
        #pragma unroll
        for (int i = 0; i < 8; i++)
            #pragma unroll
            for (int j = 0; j < 4; j++) s[i][j] *= scale;

        if (CAUSAL && kt >= 2 * qt) {
            const int row0 = qt * 128 + wid * 16 + (lane >> 2);
            #pragma unroll
            for (int nf = 0; nf < 8; nf++) {
                const int col = kt * 64 + nf * 8 + (lane & 3) * 2;
                if (col     > row0)     s[nf][0] = -1e30f;
                if (col + 1 > row0)     s[nf][1] = -1e30f;
                if (col     > row0 + 8) s[nf][2] = -1e30f;
                if (col + 1 > row0 + 8) s[nf][3] = -1e30f;
            }
        }

        float t0 = -1e30f, t1 = -1e30f;
        #pragma unroll
        for (int nf = 0; nf < 8; nf++) {
            t0 = fmaxf(t0, fmaxf(s[nf][0], s[nf][1]));
            t1 = fmaxf(t1, fmaxf(s[nf][2], s[nf][3]));
        }
        t0 = fmaxf(t0, __shfl_xor_sync(0xffffffffu, t0, 1));
        t0 = fmaxf(t0, __shfl_xor_sync(0xffffffffu, t0, 2));
        t1 = fmaxf(t1, __shfl_xor_sync(0xffffffffu, t1, 1));
        t1 = fmaxf(t1, __shfl_xor_sync(0xffffffffu, t1, 2));
        const float nm0 = fmaxf(mr0, t0), nm1 = fmaxf(mr1, t1);
        const float f0 = __expf(mr0 - nm0), f1 = __expf(mr1 - nm1);
        mr0 = nm0; mr1 = nm1;

        float rs0 = 0.f, rs1 = 0.f;
        #pragma unroll
        for (int nf = 0; nf < 8; nf++) {
            s[nf][0] = __expf(s[nf][0] - nm0);
            s[nf][1] = __expf(s[nf][1] - nm0);
            s[nf][2] = __expf(s[nf][2] - nm1);
            s[nf][3] = __expf(s[nf][3] - nm1);
            rs0 += s[nf][0] + s[nf][1];
            rs1 += s[nf][2] + s[nf][3];
        }
        rs0 += __shfl_xor_sync(0xffffffffu, rs0, 1);
        rs0 += __shfl_xor_sync(0xffffffffu, rs0, 2);
        rs1 += __shfl_xor_sync(0xffffffffu, rs1, 1);
        rs1 += __shfl_xor_sync(0xffffffffu, rs1, 2);
        lr0 = lr0 * f0 + rs0;
        lr1 = lr1 * f1 + rs1;
        #pragma unroll
        for (int nf = 0; nf < 8; nf++) {
            o[nf][0] *= f0; o[nf][1] *= f0;
            o[nf][2] *= f1; o[nf][3] *= f1;
        }

        uint32_t ph[4][4];
        #pragma unroll
        for (int j = 0; j < 4; j++) {
            ph[j][0] = pack2(__float2half(s[2*j][0]),   __float2half(s[2*j][1]));
            ph[j][1] = pack2(__float2half(s[2*j][2]),   __float2half(s[2*j][3]));
            ph[j][2] = pack2(__float2half(s[2*j+1][0]), __float2half(s[2*j+1][1]));
            ph[j][3] = pack2(__float2half(s[2*j+1][2]), __float2half(s[2*j+1][3]));
        }

        #pragma unroll
        for (int j = 0; j < 4; j++) {
            #pragma unroll
            for (int np = 0; np < 4; np++) {
                uint32_t voff = ((j * 16 + laRowA) * FRS + np * 16 + laColA) * 2;
                uint32_t v0, v1, v2, v3;
                ldsm4t(sV + voff, v0, v1, v2, v3);
                mma_f16(o[2*np],   ph[j], v0, v1);
                mma_f16(o[2*np+1], ph[j], v2, v3);
            }
        }
        __syncthreads();
    }

    const float inv0 = 1.0f / lr0, inv1 = 1.0f / lr1;
    const int row0 = qt * 128 + wid * 16 + (lane >> 2);
    #pragma unroll
    for (int nf = 0; nf < 8; nf++) {
        const int col = h * 64 + nf * 8 + (lane & 3) * 2;
        {
            size_t off = (size_t)(b * Tq + row0) * CC + col;
            *(uint32_t*)(Ohi + off) =
                pack2(__float2half(o[nf][0] * inv0), __float2half(o[nf][1] * inv0));
        }
        {
            size_t off = (size_t)(b * Tq + row0 + 8) * CC + col;
            *(uint32_t*)(Ohi + off) =
                pack2(__float2half(o[nf][2] * inv1), __float2half(o[nf][3] * inv1));
        }
    }
}

// ---------------------------------------------------------------------------
// Launch sequence
// ---------------------------------------------------------------------------
extern "C" void kernel_launch(void* const* d_in, const int* in_sizes, int n_in,
                              void* d_out, int out_size)
{
    (void)in_sizes; (void)n_in; (void)out_size;
    const float* x      = (const float*)d_in[0];
    const float* ximg   = (const float*)d_in[1];
    const float* ln1_g  = (const float*)d_in[2];
    const float* ln1_b  = (const float*)d_in[3];
    const float* ln2_g  = (const float*)d_in[4];
    const float* ln2_b  = (const float*)d_in[5];
    const float* W_attn = (const float*)d_in[6];
    const float* b_attn = (const float*)d_in[7];
    const float* W_aproj= (const float*)d_in[8];
    const float* b_aproj= (const float*)d_in[9];
    const float* Wq     = (const float*)d_in[10];
    const float* bq     = (const float*)d_in[11];
    const float* Wk     = (const float*)d_in[12];
    const float* bk     = (const float*)d_in[13];
    const float* Wv     = (const float*)d_in[14];
    const float* bv     = (const float*)d_in[15];
    const float* Wcproj = (const float*)d_in[16];
    const float* bcproj = (const float*)d_in[17];
    const float* W_fc   = (const float*)d_in[18];
    const float* b_fc   = (const float*)d_in[19];
    const float* W_mproj= (const float*)d_in[20];
    const float* b_mproj= (const float*)d_in[21];
    float* out = (float*)d_out;

    __half *wt, *qkv, *q, *kv, *a, *ff, *xi;
    float* bkv;
    cudaGetSymbolAddress((void**)&wt,  g_wt);
    cudaGetSymbolAddress((void**)&qkv, g_qkv);
    cudaGetSymbolAddress((void**)&q,   g_q);
    cudaGetSymbolAddress((void**)&kv,  g_kv);
    cudaGetSymbolAddress((void**)&a,   g_a);
    cudaGetSymbolAddress((void**)&ff,  g_ff);
    cudaGetSymbolAddress((void**)&xi,  g_xi);
    cudaGetSymbolAddress((void**)&bkv, g_bkv);

    cudaFuncSetAttribute(mma_gemm<0,false>, cudaFuncAttributeMaxDynamicSharedMemorySize, GEMM_SMEM);
    cudaFuncSetAttribute(mma_gemm<1,false>, cudaFuncAttributeMaxDynamicSharedMemorySize, GEMM_SMEM);
    cudaFuncSetAttribute(mma_gemm<1,true>,  cudaFuncAttributeMaxDynamicSharedMemorySize, GEMM_SMEM);
    cudaFuncSetAttribute(flash_mma<true>,  cudaFuncAttributeMaxDynamicSharedMemorySize, FLASH_SMEM);
    cudaFuncSetAttribute(flash_mma<false>, cudaFuncAttributeMaxDynamicSharedMemorySize, FLASH_SMEM);

    const float scale = 0.125f;

    // weight prep
    transpose_cast_kernel<<<dim3(3*CC/32, CC/32), 256>>>(W_attn,  wt+OFF_ATTN,  CC, 3*CC);
    transpose_cast_kernel<<<dim3(CC/32,   CC/32), 256>>>(W_aproj, wt+OFF_APROJ, CC, CC);
    transpose_cast_kernel<<<dim3(CC/32,   CC/32), 256>>>(Wq,      wt+OFF_Q,     CC, CC);
    transpose_cast_kernel<<<dim3(CC/32,   CC/32), 256>>>(Wk,      wt+OFF_K,     CC, CC);
    transpose_cast_kernel<<<dim3(CC/32,   CC/32), 256>>>(Wv,      wt+OFF_V,     CC, CC);
    transpose_cast_kernel<<<dim3(CC/32,   CC/32), 256>>>(Wcproj,  wt+OFF_CPROJ, CC, CC);
    transpose_cast_kernel<<<dim3(FFD/32,  CC/32), 256>>>(W_fc,    wt+OFF_FC,    CC, FFD);
    transpose_cast_kernel<<<dim3(CC/32,   FFD/32), 256>>>(W_mproj, wt+OFF_MPROJ, FFD, CC);
    tofp16_kernel<<<(MIMG*CC + 255)/256, 256>>>(ximg, xi, MIMG*CC);
    concat_bias_kernel<<<(2*CC + 255)/256, 256>>>(bk, bv, bkv);

    // ---- causal self-attention ----
    ln_h_kernel<<<MM, 256>>>(x, ln1_g, ln1_b, a);
    mma_gemm<1,false><<<dim3(3*CC/256, MM/128), 256, GEMM_SMEM>>>(
        a, wt+OFF_ATTN, b_attn, nullptr, nullptr, qkv, MM, 3*CC, CC);
    flash_mma<true><<<dim3(8, 128), 256, FLASH_SMEM>>>(
        qkv, qkv + CC, qkv + 2*CC, a, 1024, 1024, 3*CC, 3*CC, scale);
    mma_gemm<0,false><<<dim3(CC/256, MM/128), 256, GEMM_SMEM>>>(
        a, wt+OFF_APROJ, b_aproj, x, out, nullptr, MM, CC, CC);

    // ---- cross-attention ----
    ln_h_kernel<<<MM, 256>>>(out, ln1_g, ln1_b, a);
    mma_gemm<1,false><<<dim3(CC/256, MM/128), 256, GEMM_SMEM>>>(
        a, wt+OFF_Q, bq, nullptr, nullptr, q, MM, CC, CC);
    mma_gemm<1,false><<<dim3(2*CC/256, MIMG/128), 256, GEMM_SMEM>>>(
        xi, wt+OFF_K, bkv, nullptr, nullptr, kv, MIMG, 2*CC, CC);
    flash_mma<false><<<dim3(8, 128), 256, FLASH_SMEM>>>(
        q, kv, kv + CC, a, 1024, 256, CC, 2*CC, scale);
    mma_gemm<0,false><<<dim3(CC/256, MM/128), 256, GEMM_SMEM>>>(
        a, wt+OFF_CPROJ, bcproj, out, out, nullptr, MM, CC, CC);

    // ---- MLP ----
    ln_h_kernel<<<MM, 256>>>(out, ln2_g, ln2_b, a);
    mma_gemm<1,true><<<dim3(FFD/256, MM/128), 256, GEMM_SMEM>>>(
        a, wt+OFF_FC, b_fc, nullptr, nullptr, ff, MM, FFD, CC);
    mma_gemm<0,false><<<dim3(CC/256, MM/128), 256, GEMM_SMEM>>>(
        ff, wt+OFF_MPROJ, b_mproj, out, out, nullptr, MM, CC, FFD);
}

// round 10
// speedup vs baseline: 6.1418x; 1.0819x over previous
#include <cuda_runtime.h>
#include <cuda_fp16.h>
#include <cstdint>
#include <math.h>

#define CC    1024
#define MM    8192
#define MIMG  2048
#define FFD   4096

// ---------------------------------------------------------------------------
// helpers
// ---------------------------------------------------------------------------
__device__ __forceinline__ uint32_t smem_u32(const void* p) {
    uint32_t a;
    asm("{ .reg .u64 t; cvta.to.shared.u64 t, %1; cvt.u32.u64 %0, t; }" : "=r"(a) : "l"(p));
    return a;
}
__device__ __forceinline__ void ldsm4(uint32_t a, uint32_t& r0, uint32_t& r1,
                                      uint32_t& r2, uint32_t& r3) {
    asm volatile("ldmatrix.sync.aligned.m8n8.x4.shared.b16 {%0,%1,%2,%3}, [%4];"
                 : "=r"(r0), "=r"(r1), "=r"(r2), "=r"(r3) : "r"(a));
}
__device__ __forceinline__ void ldsm4t(uint32_t a, uint32_t& r0, uint32_t& r1,
                                       uint32_t& r2, uint32_t& r3) {
    asm volatile("ldmatrix.sync.aligned.m8n8.x4.trans.shared.b16 {%0,%1,%2,%3}, [%4];"
                 : "=r"(r0), "=r"(r1), "=r"(r2), "=r"(r3) : "r"(a));
}
__device__ __forceinline__ void mma_f16(float* c, const uint32_t* a, uint32_t b0, uint32_t b1) {
    asm volatile("mma.sync.aligned.m16n8k16.row.col.f32.f16.f16.f32 "
                 "{%0,%1,%2,%3}, {%4,%5,%6,%7}, {%8,%9}, {%0,%1,%2,%3};"
                 : "+f"(c[0]), "+f"(c[1]), "+f"(c[2]), "+f"(c[3])
                 : "r"(a[0]), "r"(a[1]), "r"(a[2]), "r"(a[3]), "r"(b0), "r"(b1));
}
__device__ __forceinline__ void cp16(uint32_t dst, const void* src) {
    asm volatile("cp.async.cg.shared.global [%0], [%1], 16;" :: "r"(dst), "l"(src));
}
__device__ __forceinline__ uint32_t pack2(__half a, __half b) {
    __half2 t = __halves2half2(a, b);
    return *reinterpret_cast<uint32_t*>(&t);
}
__device__ __forceinline__ float gelu_tanh(float x) {
    float u = 0.7978845608028654f * (x + 0.044715f * x * x * x);
    return 0.5f * x * (1.0f + tanhf(u));
}

// ---------------------------------------------------------------------------
// Scratch
// ---------------------------------------------------------------------------
__device__ __half g_wt[16777216];          // transposed fp16 weights [N,K]
__device__ __half g_qkv[MM * 3 * CC];
__device__ __half g_q[MM * CC];
__device__ __half g_kv[MIMG * 2 * CC];
__device__ __half g_a[MM * CC];
__device__ __half g_ff[MM * FFD];
__device__ __half g_xi[MIMG * CC];
__device__ float g_bkv[2 * CC];

#define OFF_ATTN  0u
#define OFF_APROJ 3145728u
#define OFF_Q     4194304u
#define OFF_K     5242880u
#define OFF_V     6291456u
#define OFF_CPROJ 7340032u
#define OFF_FC    8388608u
#define OFF_MPROJ 12582912u

// ---------------------------------------------------------------------------
// batched transpose+cast: 4 weights per launch.
// Each 32x32 tile handled by one block; W[K,N] fp32 -> Wt[N,K] fp16.
// ---------------------------------------------------------------------------
struct PrepDesc {
    const float* W;
    uint32_t dstOff;
    int K, N;
    int tiles;     // (N/32)*(K/32)
};
struct Prep4 { PrepDesc d[4]; };

__global__ __launch_bounds__(256) void prep_weights_kernel(Prep4 p, __half* dstBase)
{
    __shared__ float t[32][33];
    int bid = blockIdx.x;
    int di = 0;
    #pragma unroll
    for (int i = 0; i < 3; i++)
        if (bid >= p.d[di].tiles) { bid -= p.d[di].tiles; di++; }
    const PrepDesc& d = p.d[di];
    const int ntiles_n = d.N >> 5;
    const int n0 = (bid % ntiles_n) * 32;
    const int k0 = (bid / ntiles_n) * 32;
    const int tx = threadIdx.x & 31, ty = threadIdx.x >> 5;
    #pragma unroll
    for (int i = 0; i < 4; i++) {
        int kk = ty + i * 8;
        t[kk][tx] = d.W[(size_t)(k0 + kk) * d.N + n0 + tx];
    }
    __syncthreads();
    __half* dst = dstBase + d.dstOff;
    #pragma unroll
    for (int i = 0; i < 4; i++) {
        int nn = ty + i * 8;
        dst[(size_t)(n0 + nn) * d.K + k0 + tx] = __float2half(t[tx][nn]);
    }
}

__global__ void tofp16_kernel(const float* __restrict__ x,
                              __half* __restrict__ o, int n)
{
    int i = blockIdx.x * blockDim.x + threadIdx.x;
    if (i < n) o[i] = __float2half(x[i]);
}

__global__ void concat_bias_kernel(const float* __restrict__ a,
                                   const float* __restrict__ b,
                                   float* __restrict__ o)
{
    int i = blockIdx.x * blockDim.x + threadIdx.x;
    if (i < CC) o[i] = a[i];
    else if (i < 2 * CC) o[i] = b[i - CC];
}

// ---------------------------------------------------------------------------
// block reduction + LayerNorm (fp16 output)
// ---------------------------------------------------------------------------
__device__ __forceinline__ float block_sum(float v) {
    __shared__ float red[8];
    int lane = threadIdx.x & 31;
    int w    = threadIdx.x >> 5;
    #pragma unroll
    for (int o = 16; o; o >>= 1) v += __shfl_xor_sync(0xffffffffu, v, o);
    __syncthreads();
    if (lane == 0) red[w] = v;
    __syncthreads();
    if (w == 0) {
        v = (lane < 8) ? red[lane] : 0.f;
        #pragma unroll
        for (int o = 4; o; o >>= 1) v += __shfl_xor_sync(0xffffffffu, v, o);
        if (lane == 0) red[0] = v;
    }
    __syncthreads();
    return red[0];
}

__global__ __launch_bounds__(256) void ln_h_kernel(
    const float* __restrict__ in, const float* __restrict__ g,
    const float* __restrict__ b, __half* __restrict__ out)
{
    const int row = blockIdx.x;
    const float4 v = ((const float4*)(in + (size_t)row * CC))[threadIdx.x];
    float s = v.x + v.y + v.z + v.w;
    s = block_sum(s);
    const float mean = s * (1.0f / CC);
    float dx = v.x - mean, dy = v.y - mean, dz = v.z - mean, dw = v.w - mean;
    float sq = dx*dx + dy*dy + dz*dz + dw*dw;
    sq = block_sum(sq);
    const float rstd = rsqrtf(sq * (1.0f / CC) + 1e-5f);
    const float4 gg = ((const float4*)g)[threadIdx.x];
    const float4 bb = ((const float4*)b)[threadIdx.x];
    __half h0 = __float2half(dx * rstd * gg.x + bb.x);
    __half h1 = __float2half(dy * rstd * gg.y + bb.y);
    __half h2 = __float2half(dz * rstd * gg.z + bb.z);
    __half h3 = __float2half(dw * rstd * gg.w + bb.w);
    size_t off = (size_t)row * CC + threadIdx.x * 4;
    *(uint2*)(out + off) = make_uint2(pack2(h0,h1), pack2(h2,h3));
}

// ---------------------------------------------------------------------------
// HMMA fp16 single-pass GEMM: out[M,N] = A[M,K] @ Wt[N,K]^T + bias
// Block 128x256x64; 8 warps 2(M)x4(N); warp tile 64x64; 3-stage cp.async.
// OMODE: 0 = fp32 out (+res), 1 = fp16 out
// ---------------------------------------------------------------------------
#define GRS 72
#define ATB (128 * GRS * 2)              // 18432 bytes
#define BTB (256 * GRS * 2)              // 36864 bytes
#define GSTAGE (ATB + BTB)               // 55296 per stage
#define GEMM_SMEM (3 * GSTAGE)           // 165888

template<int OMODE, bool GELU>
__global__ __launch_bounds__(256, 1) void mma_gemm(
    const __half* __restrict__ Ah, const __half* __restrict__ Bh,
    const float* __restrict__ bias, const float* __restrict__ res,
    float* __restrict__ outf, __half* __restrict__ outh,
    int M, int N, int K)
{
    extern __shared__ __align__(16) char smem[];
    const uint32_t base = smem_u32(smem);
    const int tid = threadIdx.x;
    const int wid = tid >> 5, lane = tid & 31;
    const int wm = wid >> 2, wn = wid & 3;
    const int m0 = blockIdx.y * 128, n0 = blockIdx.x * 256;

    const __half* gA = Ah + (size_t)m0 * K;
    const __half* gB = Bh + (size_t)n0 * K;

    auto stage = [&](int k0, int buf) {
        const uint32_t sb = base + buf * GSTAGE;
        #pragma unroll
        for (int i = 0; i < 4; i++) {
            int idx = tid + i * 256;
            int r = idx >> 3, s = idx & 7;
            cp16(sb + (r * GRS + s * 8) * 2, gA + (size_t)r * K + k0 + s * 8);
        }
        #pragma unroll
        for (int i = 0; i < 8; i++) {
            int idx = tid + i * 256;
            int r = idx >> 3, s = idx & 7;
            cp16(sb + ATB + (r * GRS + s * 8) * 2, gB + (size_t)r * K + k0 + s * 8);
        }
        asm volatile("cp.async.commit_group;");
    };

    const int laRowA = ((lane >> 3) & 1) * 8 + (lane & 7);
    const int laColA = (lane >> 4) * 8;
    const int laRowB = ((lane >> 4) << 3) + (lane & 7);
    const int laColB = ((lane >> 3) & 1) * 8;

    float c[4][8][4];
    #pragma unroll
    for (int i = 0; i < 4; i++)
        #pragma unroll
        for (int j = 0; j < 8; j++)
            #pragma unroll
            for (int q = 0; q < 4; q++) c[i][j][q] = 0.f;

    const int nch = K >> 6;
    stage(0, 0);
    stage(64, 1);

    for (int ch = 0; ch < nch; ch++) {
        if (ch + 1 < nch) asm volatile("cp.async.wait_group 1;");
        else              asm volatile("cp.async.wait_group 0;");
        __syncthreads();
        if (ch + 2 < nch) stage((ch + 2) << 6, (ch + 2) % 3);

        const uint32_t sb = base + (ch % 3) * GSTAGE;
        const uint32_t sA = sb, sB = sb + ATB;

        #pragma unroll
        for (int ks = 0; ks < 64; ks += 16) {
            uint32_t a[4][4];
            #pragma unroll
            for (int mf = 0; mf < 4; mf++) {
                uint32_t off = ((wm * 64 + mf * 16 + laRowA) * GRS + ks + laColA) * 2;
                ldsm4(sA + off, a[mf][0], a[mf][1], a[mf][2], a[mf][3]);
            }
            uint32_t bh[8][2];
            #pragma unroll
            for (int np = 0; np < 4; np++) {
                uint32_t off = ((wn * 64 + np * 16 + laRowB) * GRS + ks + laColB) * 2;
                ldsm4(sB + off, bh[2*np][0], bh[2*np][1], bh[2*np+1][0], bh[2*np+1][1]);
            }
            #pragma unroll
            for (int mf = 0; mf < 4; mf++)
                #pragma unroll
                for (int nf = 0; nf < 8; nf++)
                    mma_f16(c[mf][nf], a[mf], bh[nf][0], bh[nf][1]);
        }
    }

    __syncthreads();

    #pragma unroll
    for (int mf = 0; mf < 4; mf++) {
        const int rbase = m0 + wm * 64 + mf * 16 + (lane >> 2);
        #pragma unroll
        for (int nf = 0; nf < 8; nf++) {
            const int gn = n0 + wn * 64 + nf * 8 + (lane & 3) * 2;
            const float2 b2 = *(const float2*)(bias + gn);
            #pragma unroll
            for (int half_ = 0; half_ < 2; half_++) {
                const int gm = rbase + half_ * 8;
                float v0 = c[mf][nf][half_ * 2 + 0] + b2.x;
                float v1 = c[mf][nf][half_ * 2 + 1] + b2.y;
                if (GELU) { v0 = gelu_tanh(v0); v1 = gelu_tanh(v1); }
                if (OMODE == 0) {
                    if (res) {
                        const float2 r2 = *(const float2*)(res + (size_t)gm * N + gn);
                        v0 += r2.x; v1 += r2.y;
                    }
                    *(float2*)(outf + (size_t)gm * N + gn) = make_float2(v0, v1);
                } else {
                    *(uint32_t*)(outh + (size_t)gm * N + gn) =
                        pack2(__float2half(v0), __float2half(v1));
                }
            }
        }
    }
}

// ---------------------------------------------------------------------------
// Flash attention, fp16 single-pass. BQ=128 (8 warps), BK=64, D=64.
// ---------------------------------------------------------------------------
#define FRS 72
#define QTB (128 * FRS * 2)          // 18432
#define KVT (64 * FRS * 2)           // 9216
#define KVSTAGE (2 * KVT)            // 18432
#define FLASH_SMEM (QTB + 2 * KVSTAGE)   // 55296

template<bool CAUSAL>
__global__ __launch_bounds__(256, 1) void flash_mma(
    const __half* __restrict__ Qh,
    const __half* __restrict__ Kh, const __half* __restrict__ Vh,
    __half* __restrict__ Ohi,
    int Tq, int Tkv, int qS, int kS, float scale)
{
    extern __shared__ __align__(16) char smem[];
    const uint32_t base = smem_u32(smem);
    const uint32_t sQ = base;

    const int tid = threadIdx.x;
    const int wid = tid >> 5, lane = tid & 31;
    const int bh = blockIdx.y;
    const int b = bh >> 4, h = bh & 15;
    const int qt = blockIdx.x;

    const __half* Qb  = Qh + (size_t)(b * Tq + qt * 128) * qS + h * 64;
    const __half* Khb = Kh + (size_t)(b * Tkv) * kS + h * 64;
    const __half* Vhb = Vh + (size_t)(b * Tkv) * kS + h * 64;

    auto stage_kv = [&](int kt, int buf) {
        const uint32_t sb = base + QTB + buf * KVSTAGE;
        #pragma unroll
        for (int i = 0; i < 2; i++) {
            int idx = tid + i * 256;
            int r = idx >> 3, s = idx & 7;
            size_t go = (size_t)(kt * 64 + r) * kS + s * 8;
            uint32_t off = (r * FRS + s * 8) * 2;
            cp16(sb + 0 * KVT + off, Khb + go);
            cp16(sb + 1 * KVT + off, Vhb + go);
        }
        asm volatile("cp.async.commit_group;");
    };

    #pragma unroll
    for (int i = 0; i < 4; i++) {
        int idx = tid + i * 256;
        int r = idx >> 3, s = idx & 7;
        cp16(sQ + (r * FRS + s * 8) * 2, Qb + (size_t)r * qS + s * 8);
    }
    stage_kv(0, 0);

    const int laRowA = ((lane >> 3) & 1) * 8 + (lane & 7);
    const int laColA = (lane >> 4) * 8;
    const int laRowB = ((lane >> 4) << 3) + (lane & 7);
    const int laColB = ((lane >> 3) & 1) * 8;

    float o[8][4];
    #pragma unroll
    for (int i = 0; i < 8; i++)
        #pragma unroll
        for (int j = 0; j < 4; j++) o[i][j] = 0.f;
    float mr0 = -1e30f, mr1 = -1e30f, lr0 = 0.f, lr1 = 0.f;

    const int nkt = CAUSAL ? (2 * qt + 2) : (Tkv >> 6);

    for (int kt = 0; kt < nkt; kt++) {
        if (kt + 1 < nkt) {
            stage_kv(kt + 1, (kt + 1) & 1);
            asm volatile("cp.async.wait_group 1;");
        } else {
            asm volatile("cp.async.wait_group 0;");
        }
        __syncthreads();

        const uint32_t sb = base + QTB + (kt & 1) * KVSTAGE;
        const uint32_t sK = sb, sV = sb + KVT;

        float s[8][4];
        #pragma unroll
        for (int i = 0; i < 8; i++)
            #pragma unroll
            for (int j = 0; j < 4; j++) s[i][j] = 0.f;

        #pragma unroll
        for (int ks = 0; ks < 4; ks++) {
            uint32_t q[4];
            uint32_t qoff = ((wid * 16 + laRowA) * FRS + ks * 16 + laColA) * 2;
            ldsm4(sQ + qoff, q[0], q[1], q[2], q[3]);
            #pragma unroll
            for (int np = 0; np < 4; np++) {
                uint32_t koff = ((np * 16 + laRowB) * FRS + ks * 16 + laColB) * 2;
                uint32_t k0, k1, k2, k3;
                ldsm4(sK + koff, k0, k1, k2, k3);
                mma_f16(s[2*np],   q, k0, k1);
                mma_f16(s[2*np+1], q, k2, k3);
            }
        }
        #pragma unroll
        for (int i = 0; i < 8; i++)
            #pragma unroll
            for (int j = 0; j < 4; j++) s[i][j] *= scale;

        if (CAUSAL && kt >= 2 * qt) {
            const int row0 = qt * 128 + wid * 16 + (lane >> 2);
            #pragma unroll
            for (int nf = 0; nf < 8; nf++) {
                const int col = kt * 64 + nf * 8 + (lane & 3) * 2;
                if (col     > row0)     s[nf][0] = -1e30f;
                if (col + 1 > row0)     s[nf][1] = -1e30f;
                if (col     > row0 + 8) s[nf][2] = -1e30f;
                if (col + 1 > row0 + 8) s[nf][3] = -1e30f;
            }
        }

        float t0 = -1e30f, t1 = -1e30f;
        #pragma unroll
        for (int nf = 0; nf < 8; nf++) {
            t0 = fmaxf(t0, fmaxf(s[nf][0], s[nf][1]));
            t1 = fmaxf(t1, fmaxf(s[nf][2], s[nf][3]));
        }
        t0 = fmaxf(t0, __shfl_xor_sync(0xffffffffu, t0, 1));
        t0 = fmaxf(t0, __shfl_xor_sync(0xffffffffu, t0, 2));
        t1 = fmaxf(t1, __shfl_xor_sync(0xffffffffu, t1, 1));
        t1 = fmaxf(t1, __shfl_xor_sync(0xffffffffu, t1, 2));
        const float nm0 = fmaxf(mr0, t0), nm1 = fmaxf(mr1, t1);
        const float f0 = __expf(mr0 - nm0), f1 = __expf(mr1 - nm1);
        mr0 = nm0; mr1 = nm1;

        float rs0 = 0.f, rs1 = 0.f;
        #pragma unroll
        for (int nf = 0; nf < 8; nf++) {
            s[nf][0] = __expf(s[nf][0] - nm0);
            s[nf][1] = __expf(s[nf][1] - nm0);
            s[nf][2] = __expf(s[nf][2] - nm1);
            s[nf][3] = __expf(s[nf][3] - nm1);
            rs0 += s[nf][0] + s[nf][1];
            rs1 += s[nf][2] + s[nf][3];
        }
        rs0 += __shfl_xor_sync(0xffffffffu, rs0, 1);
        rs0 += __shfl_xor_sync(0xffffffffu, rs0, 2);
        rs1 += __shfl_xor_sync(0xffffffffu, rs1, 1);
        rs1 += __shfl_xor_sync(0xffffffffu, rs1, 2);
        lr0 = lr0 * f0 + rs0;
        lr1 = lr1 * f1 + rs1;
        #pragma unroll
        for (int nf = 0; nf < 8; nf++) {
            o[nf][0] *= f0; o[nf][1] *= f0;
            o[nf][2] *= f1; o[nf][3] *= f1;
        }

        uint32_t ph[4][4];
        #pragma unroll
        for (int j = 0; j < 4; j++) {
            ph[j][0] = pack2(__float2half(s[2*j][0]),   __float2half(s[2*j][1]));
            ph[j][1] = pack2(__float2half(s[2*j][2]),   __float2half(s[2*j][3]));
            ph[j][2] = pack2(__float2half(s[2*j+1][0]), __float2half(s[2*j+1][1]));
            ph[j][3] = pack2(__float2half(s[2*j+1][2]), __float2half(s[2*j+1][3]));
        }

        #pragma unroll
        for (int j = 0; j < 4; j++) {
            #pragma unroll
            for (int np = 0; np < 4; np++) {
                uint32_t voff = ((j * 16 + laRowA) * FRS + np * 16 + laColA) * 2;
                uint32_t v0, v1, v2, v3;
                ldsm4t(sV + voff, v0, v1, v2, v3);
                mma_f16(o[2*np],   ph[j], v0, v1);
                mma_f16(o[2*np+1], ph[j], v2, v3);
            }
        }
        __syncthreads();
    }

    const float inv0 = 1.0f / lr0, inv1 = 1.0f / lr1;
    const int row0 = qt * 128 + wid * 16 + (lane >> 2);
    #pragma unroll
    for (int nf = 0; nf < 8; nf++) {
        const int col = h * 64 + nf * 8 + (lane & 3) * 2;
        {
            size_t off = (size_t)(b * Tq + row0) * CC + col;
            *(uint32_t*)(Ohi + off) =
                pack2(__float2half(o[nf][0] * inv0), __float2half(o[nf][1] * inv0));
        }
        {
            size_t off = (size_t)(b * Tq + row0 + 8) * CC + col;
            *(uint32_t*)(Ohi + off) =
                pack2(__float2half(o[nf][2] * inv1), __float2half(o[nf][3] * inv1));
        }
    }
}

// ---------------------------------------------------------------------------
// Launch sequence
// ---------------------------------------------------------------------------
extern "C" void kernel_launch(void* const* d_in, const int* in_sizes, int n_in,
                              void* d_out, int out_size)
{
    (void)in_sizes; (void)n_in; (void)out_size;
    const float* x      = (const float*)d_in[0];
    const float* ximg   = (const float*)d_in[1];
    const float* ln1_g  = (const float*)d_in[2];
    const float* ln1_b  = (const float*)d_in[3];
    const float* ln2_g  = (const float*)d_in[4];
    const float* ln2_b  = (const float*)d_in[5];
    const float* W_attn = (const float*)d_in[6];
    const float* b_attn = (const float*)d_in[7];
    const float* W_aproj= (const float*)d_in[8];
    const float* b_aproj= (const float*)d_in[9];
    const float* Wq     = (const float*)d_in[10];
    const float* bq     = (const float*)d_in[11];
    const float* Wk     = (const float*)d_in[12];
    const float* bk     = (const float*)d_in[13];
    const float* Wv     = (const float*)d_in[14];
    const float* bv     = (const float*)d_in[15];
    const float* Wcproj = (const float*)d_in[16];
    const float* bcproj = (const float*)d_in[17];
    const float* W_fc   = (const float*)d_in[18];
    const float* b_fc   = (const float*)d_in[19];
    const float* W_mproj= (const float*)d_in[20];
    const float* b_mproj= (const float*)d_in[21];
    float* out = (float*)d_out;

    __half *wt, *qkv, *q, *kv, *a, *ff, *xi;
    float* bkv;
    cudaGetSymbolAddress((void**)&wt,  g_wt);
    cudaGetSymbolAddress((void**)&qkv, g_qkv);
    cudaGetSymbolAddress((void**)&q,   g_q);
    cudaGetSymbolAddress((void**)&kv,  g_kv);
    cudaGetSymbolAddress((void**)&a,   g_a);
    cudaGetSymbolAddress((void**)&ff,  g_ff);
    cudaGetSymbolAddress((void**)&xi,  g_xi);
    cudaGetSymbolAddress((void**)&bkv, g_bkv);

    cudaFuncSetAttribute(mma_gemm<0,false>, cudaFuncAttributeMaxDynamicSharedMemorySize, GEMM_SMEM);
    cudaFuncSetAttribute(mma_gemm<1,false>, cudaFuncAttributeMaxDynamicSharedMemorySize, GEMM_SMEM);
    cudaFuncSetAttribute(mma_gemm<1,true>,  cudaFuncAttributeMaxDynamicSharedMemorySize, GEMM_SMEM);
    cudaFuncSetAttribute(flash_mma<true>,  cudaFuncAttributeMaxDynamicSharedMemorySize, FLASH_SMEM);
    cudaFuncSetAttribute(flash_mma<false>, cudaFuncAttributeMaxDynamicSharedMemorySize, FLASH_SMEM);

    const float scale = 0.125f;

    // ---- prep: launches 0..3 so the qkv GEMM is capture index 5 ----
    tofp16_kernel<<<(MIMG*CC + 255)/256, 256>>>(ximg, xi, MIMG*CC);            // 0
    concat_bias_kernel<<<(2*CC + 255)/256, 256>>>(bk, bv, bkv);                // 1

    Prep4 pa;
    pa.d[0] = { W_attn,  OFF_ATTN,  CC, 3*CC, (3*CC/32)*(CC/32) };   // 3072
    pa.d[1] = { W_aproj, OFF_APROJ, CC, CC,   (CC/32)*(CC/32)   };   // 1024
    pa.d[2] = { Wq,      OFF_Q,     CC, CC,   (CC/32)*(CC/32)   };
    pa.d[3] = { Wk,      OFF_K,     CC, CC,   (CC/32)*(CC/32)   };
    prep_weights_kernel<<<3072 + 3*1024, 256>>>(pa, wt);                       // 2

    Prep4 pb;
    pb.d[0] = { Wv,      OFF_V,     CC, CC,   (CC/32)*(CC/32)    };
    pb.d[1] = { Wcproj,  OFF_CPROJ, CC, CC,   (CC/32)*(CC/32)    };
    pb.d[2] = { W_fc,    OFF_FC,    CC, FFD,  (FFD/32)*(CC/32)   };  // 4096
    pb.d[3] = { W_mproj, OFF_MPROJ, FFD, CC,  (CC/32)*(FFD/32)   };  // 4096
    prep_weights_kernel<<<2*1024 + 2*4096, 256>>>(pb, wt);                     // 3

    // ---- causal self-attention ----
    ln_h_kernel<<<MM, 256>>>(x, ln1_g, ln1_b, a);                              // 4
    mma_gemm<1,false><<<dim3(3*CC/256, MM/128), 256, GEMM_SMEM>>>(             // 5 (ncu)
        a, wt+OFF_ATTN, b_attn, nullptr, nullptr, qkv, MM, 3*CC, CC);
    flash_mma<true><<<dim3(8, 128), 256, FLASH_SMEM>>>(
        qkv, qkv + CC, qkv + 2*CC, a, 1024, 1024, 3*CC, 3*CC, scale);
    mma_gemm<0,false><<<dim3(CC/256, MM/128), 256, GEMM_SMEM>>>(
        a, wt+OFF_APROJ, b_aproj, x, out, nullptr, MM, CC, CC);

    // ---- cross-attention ----
    ln_h_kernel<<<MM, 256>>>(out, ln1_g, ln1_b, a);
    mma_gemm<1,false><<<dim3(CC/256, MM/128), 256, GEMM_SMEM>>>(
        a, wt+OFF_Q, bq, nullptr, nullptr, q, MM, CC, CC);
    mma_gemm<1,false><<<dim3(2*CC/256, MIMG/128), 256, GEMM_SMEM>>>(
        xi, wt+OFF_K, bkv, nullptr, nullptr, kv, MIMG, 2*CC, CC);
    flash_mma<false><<<dim3(8, 128), 256, FLASH_SMEM>>>(
        q, kv, kv + CC, a, 1024, 256, CC, 2*CC, scale);
    mma_gemm<0,false><<<dim3(CC/256, MM/128), 256, GEMM_SMEM>>>(
        a, wt+OFF_CPROJ, bcproj, out, out, nullptr, MM, CC, CC);

    // ---- MLP ----
    ln_h_kernel<<<MM, 256>>>(out, ln2_g, ln2_b, a);
    mma_gemm<1,true><<<dim3(FFD/256, MM/128), 256, GEMM_SMEM>>>(
        a, wt+OFF_FC, b_fc, nullptr, nullptr, ff, MM, FFD, CC);
    mma_gemm<0,false><<<dim3(CC/256, MM/128), 256, GEMM_SMEM>>>(
        ff, wt+OFF_MPROJ, b_mproj, out, out, nullptr, MM, CC, FFD);
}

// round 12
// speedup vs baseline: 6.4030x; 1.0425x over previous
#include <cuda_runtime.h>
#include <cuda_fp16.h>
#include <cstdint>
#include <math.h>

#define CC    1024
#define MM    8192
#define MIMG  2048
#define FFD   4096

// ---------------------------------------------------------------------------
// helpers
// ---------------------------------------------------------------------------
__device__ __forceinline__ uint32_t smem_u32(const void* p) {
    uint32_t a;
    asm("{ .reg .u64 t; cvta.to.shared.u64 t, %1; cvt.u32.u64 %0, t; }" : "=r"(a) : "l"(p));
    return a;
}
__device__ __forceinline__ void ldsm4(uint32_t a, uint32_t& r0, uint32_t& r1,
                                      uint32_t& r2, uint32_t& r3) {
    asm volatile("ldmatrix.sync.aligned.m8n8.x4.shared.b16 {%0,%1,%2,%3}, [%4];"
                 : "=r"(r0), "=r"(r1), "=r"(r2), "=r"(r3) : "r"(a));
}
__device__ __forceinline__ void ldsm4t(uint32_t a, uint32_t& r0, uint32_t& r1,
                                       uint32_t& r2, uint32_t& r3) {
    asm volatile("ldmatrix.sync.aligned.m8n8.x4.trans.shared.b16 {%0,%1,%2,%3}, [%4];"
                 : "=r"(r0), "=r"(r1), "=r"(r2), "=r"(r3) : "r"(a));
}
__device__ __forceinline__ void mma_f16(float* c, const uint32_t* a, uint32_t b0, uint32_t b1) {
    asm volatile("mma.sync.aligned.m16n8k16.row.col.f32.f16.f16.f32 "
                 "{%0,%1,%2,%3}, {%4,%5,%6,%7}, {%8,%9}, {%0,%1,%2,%3};"
                 : "+f"(c[0]), "+f"(c[1]), "+f"(c[2]), "+f"(c[3])
                 : "r"(a[0]), "r"(a[1]), "r"(a[2]), "r"(a[3]), "r"(b0), "r"(b1));
}
__device__ __forceinline__ void cp16(uint32_t dst, const void* src) {
    asm volatile("cp.async.cg.shared.global [%0], [%1], 16;" :: "r"(dst), "l"(src));
}
__device__ __forceinline__ uint32_t pack2(__half a, __half b) {
    __half2 t = __halves2half2(a, b);
    return *reinterpret_cast<uint32_t*>(&t);
}
__device__ __forceinline__ float gelu_tanh(float x) {
    float u = 0.7978845608028654f * (x + 0.044715f * x * x * x);
    return 0.5f * x * (1.0f + tanhf(u));
}

// ---------------------------------------------------------------------------
// Scratch
// ---------------------------------------------------------------------------
__device__ __half g_wt[16777216];          // transposed fp16 weights [N,K]
__device__ __half g_qkv[MM * 3 * CC];
__device__ __half g_q[MM * CC];
__device__ __half g_kv[MIMG * 2 * CC];
__device__ __half g_a[MM * CC];
__device__ __half g_ff[MM * FFD];
__device__ __half g_xi[MIMG * CC];
__device__ float g_bkv[2 * CC];

#define OFF_ATTN  0u
#define OFF_APROJ 3145728u
#define OFF_Q     4194304u
#define OFF_K     5242880u
#define OFF_V     6291456u
#define OFF_CPROJ 7340032u
#define OFF_FC    8388608u
#define OFF_MPROJ 12582912u

// ---------------------------------------------------------------------------
// batched transpose+cast: all 8 weights in ONE launch.
// 32x32 tile per block; W[K,N] fp32 -> Wt[N,K] fp16, packed 2-wide stores.
// ---------------------------------------------------------------------------
struct PrepDesc {
    const float* W;
    uint32_t dstOff;
    int K, N;
    int tiles;     // (N/32)*(K/32)
};
struct Prep8 { PrepDesc d[8]; };

__global__ __launch_bounds__(256) void prep_weights_kernel(Prep8 p, __half* dstBase)
{
    __shared__ float t[32][33];   // t[k][n]
    int bid = blockIdx.x;
    int di = 0;
    #pragma unroll
    for (int i = 0; i < 7; i++)
        if (bid >= p.d[di].tiles) { bid -= p.d[di].tiles; di++; }
    const PrepDesc& d = p.d[di];
    const int ntiles_n = d.N >> 5;
    const int n0 = (bid % ntiles_n) * 32;
    const int k0 = (bid / ntiles_n) * 32;
    {
        const int tx = threadIdx.x & 31, ty = threadIdx.x >> 5;
        #pragma unroll
        for (int i = 0; i < 4; i++) {
            int kk = ty + i * 8;
            t[kk][tx] = d.W[(size_t)(k0 + kk) * d.N + n0 + tx];
        }
    }
    __syncthreads();
    // store: thread -> (n row, k-pair). 16 kpairs x 16 n rows per iter, 2 iters.
    __half* dst = dstBase + d.dstOff;
    const int kp = threadIdx.x & 15;          // k pair index
    const int nyb = threadIdx.x >> 4;         // 0..15
    #pragma unroll
    for (int i = 0; i < 2; i++) {
        int nn = nyb + i * 16;
        uint32_t v = pack2(__float2half(t[2*kp][nn]), __float2half(t[2*kp+1][nn]));
        *(uint32_t*)(dst + (size_t)(n0 + nn) * d.K + k0 + 2*kp) = v;
    }
}

__global__ void tofp16_kernel(const float* __restrict__ x,
                              __half* __restrict__ o, int n)
{
    int i = blockIdx.x * blockDim.x + threadIdx.x;
    if (i < n) o[i] = __float2half(x[i]);
}

__global__ void concat_bias_kernel(const float* __restrict__ a,
                                   const float* __restrict__ b,
                                   float* __restrict__ o)
{
    int i = blockIdx.x * blockDim.x + threadIdx.x;
    if (i < CC) o[i] = a[i];
    else if (i < 2 * CC) o[i] = b[i - CC];
}

// ---------------------------------------------------------------------------
// block reduction + LayerNorm (fp16 output)
// ---------------------------------------------------------------------------
__device__ __forceinline__ float block_sum(float v) {
    __shared__ float red[8];
    int lane = threadIdx.x & 31;
    int w    = threadIdx.x >> 5;
    #pragma unroll
    for (int o = 16; o; o >>= 1) v += __shfl_xor_sync(0xffffffffu, v, o);
    __syncthreads();
    if (lane == 0) red[w] = v;
    __syncthreads();
    if (w == 0) {
        v = (lane < 8) ? red[lane] : 0.f;
        #pragma unroll
        for (int o = 4; o; o >>= 1) v += __shfl_xor_sync(0xffffffffu, v, o);
        if (lane == 0) red[0] = v;
    }
    __syncthreads();
    return red[0];
}

__global__ __launch_bounds__(256) void ln_h_kernel(
    const float* __restrict__ in, const float* __restrict__ g,
    const float* __restrict__ b, __half* __restrict__ out)
{
    const int row = blockIdx.x;
    const float4 v = ((const float4*)(in + (size_t)row * CC))[threadIdx.x];
    float s = v.x + v.y + v.z + v.w;
    s = block_sum(s);
    const float mean = s * (1.0f / CC);
    float dx = v.x - mean, dy = v.y - mean, dz = v.z - mean, dw = v.w - mean;
    float sq = dx*dx + dy*dy + dz*dz + dw*dw;
    sq = block_sum(sq);
    const float rstd = rsqrtf(sq * (1.0f / CC) + 1e-5f);
    const float4 gg = ((const float4*)g)[threadIdx.x];
    const float4 bb = ((const float4*)b)[threadIdx.x];
    __half h0 = __float2half(dx * rstd * gg.x + bb.x);
    __half h1 = __float2half(dy * rstd * gg.y + bb.y);
    __half h2 = __float2half(dz * rstd * gg.z + bb.z);
    __half h3 = __float2half(dw * rstd * gg.w + bb.w);
    size_t off = (size_t)row * CC + threadIdx.x * 4;
    *(uint2*)(out + off) = make_uint2(pack2(h0,h1), pack2(h2,h3));
}

// ---------------------------------------------------------------------------
// HMMA fp16 single-pass GEMM: out[M,N] = A[M,K] @ Wt[N,K]^T + bias
// Block 128x256x64; 8 warps 2(M)x4(N); warp tile 64x64; 3-stage cp.async.
// OMODE: 0 = fp32 out (+res), 1 = fp16 out
// ---------------------------------------------------------------------------
#define GRS 72
#define ATB (128 * GRS * 2)              // 18432 bytes
#define BTB (256 * GRS * 2)              // 36864 bytes
#define GSTAGE (ATB + BTB)               // 55296 per stage
#define GEMM_SMEM (3 * GSTAGE)           // 165888

template<int OMODE, bool GELU>
__global__ __launch_bounds__(256, 1) void mma_gemm(
    const __half* __restrict__ Ah, const __half* __restrict__ Bh,
    const float* __restrict__ bias, const float* __restrict__ res,
    float* __restrict__ outf, __half* __restrict__ outh,
    int M, int N, int K)
{
    extern __shared__ __align__(16) char smem[];
    const uint32_t base = smem_u32(smem);
    const int tid = threadIdx.x;
    const int wid = tid >> 5, lane = tid & 31;
    const int wm = wid >> 2, wn = wid & 3;
    const int m0 = blockIdx.y * 128, n0 = blockIdx.x * 256;

    const __half* gA = Ah + (size_t)m0 * K;
    const __half* gB = Bh + (size_t)n0 * K;

    auto stage = [&](int k0, int buf) {
        const uint32_t sb = base + buf * GSTAGE;
        #pragma unroll
        for (int i = 0; i < 4; i++) {
            int idx = tid + i * 256;
            int r = idx >> 3, s = idx & 7;
            cp16(sb + (r * GRS + s * 8) * 2, gA + (size_t)r * K + k0 + s * 8);
        }
        #pragma unroll
        for (int i = 0; i < 8; i++) {
            int idx = tid + i * 256;
            int r = idx >> 3, s = idx & 7;
            cp16(sb + ATB + (r * GRS + s * 8) * 2, gB + (size_t)r * K + k0 + s * 8);
        }
        asm volatile("cp.async.commit_group;");
    };

    const int laRowA = ((lane >> 3) & 1) * 8 + (lane & 7);
    const int laColA = (lane >> 4) * 8;
    const int laRowB = ((lane >> 4) << 3) + (lane & 7);
    const int laColB = ((lane >> 3) & 1) * 8;

    float c[4][8][4];
    #pragma unroll
    for (int i = 0; i < 4; i++)
        #pragma unroll
        for (int j = 0; j < 8; j++)
            #pragma unroll
            for (int q = 0; q < 4; q++) c[i][j][q] = 0.f;

    const int nch = K >> 6;
    stage(0, 0);
    stage(64, 1);

    for (int ch = 0; ch < nch; ch++) {
        if (ch + 1 < nch) asm volatile("cp.async.wait_group 1;");
        else              asm volatile("cp.async.wait_group 0;");
        __syncthreads();
        if (ch + 2 < nch) stage((ch + 2) << 6, (ch + 2) % 3);

        const uint32_t sb = base + (ch % 3) * GSTAGE;
        const uint32_t sA = sb, sB = sb + ATB;

        #pragma unroll
        for (int ks = 0; ks < 64; ks += 16) {
            uint32_t a[4][4];
            #pragma unroll
            for (int mf = 0; mf < 4; mf++) {
                uint32_t off = ((wm * 64 + mf * 16 + laRowA) * GRS + ks + laColA) * 2;
                ldsm4(sA + off, a[mf][0], a[mf][1], a[mf][2], a[mf][3]);
            }
            uint32_t bh[8][2];
            #pragma unroll
            for (int np = 0; np < 4; np++) {
                uint32_t off = ((wn * 64 + np * 16 + laRowB) * GRS + ks + laColB) * 2;
                ldsm4(sB + off, bh[2*np][0], bh[2*np][1], bh[2*np+1][0], bh[2*np+1][1]);
            }
            #pragma unroll
            for (int mf = 0; mf < 4; mf++)
                #pragma unroll
                for (int nf = 0; nf < 8; nf++)
                    mma_f16(c[mf][nf], a[mf], bh[nf][0], bh[nf][1]);
        }
    }

    // epilogue: registers only — no smem reuse, no barrier needed
    #pragma unroll
    for (int mf = 0; mf < 4; mf++) {
        const int rbase = m0 + wm * 64 + mf * 16 + (lane >> 2);
        #pragma unroll
        for (int nf = 0; nf < 8; nf++) {
            const int gn = n0 + wn * 64 + nf * 8 + (lane & 3) * 2;
            const float2 b2 = *(const float2*)(bias + gn);
            #pragma unroll
            for (int half_ = 0; half_ < 2; half_++) {
                const int gm = rbase + half_ * 8;
                float v0 = c[mf][nf][half_ * 2 + 0] + b2.x;
                float v1 = c[mf][nf][half_ * 2 + 1] + b2.y;
                if (GELU) { v0 = gelu_tanh(v0); v1 = gelu_tanh(v1); }
                if (OMODE == 0) {
                    if (res) {
                        const float2 r2 = *(const float2*)(res + (size_t)gm * N + gn);
                        v0 += r2.x; v1 += r2.y;
                    }
                    *(float2*)(outf + (size_t)gm * N + gn) = make_float2(v0, v1);
                } else {
                    *(uint32_t*)(outh + (size_t)gm * N + gn) =
                        pack2(__float2half(v0), __float2half(v1));
                }
            }
        }
    }
}

// ---------------------------------------------------------------------------
// Flash attention, fp16 single-pass. BQ=128 (8 warps), BK=64, D=64.
// ---------------------------------------------------------------------------
#define FRS 72
#define QTB (128 * FRS * 2)          // 18432
#define KVT (64 * FRS * 2)           // 9216
#define KVSTAGE (2 * KVT)            // 18432
#define FLASH_SMEM (QTB + 2 * KVSTAGE)   // 55296

template<bool CAUSAL>
__global__ __launch_bounds__(256, 1) void flash_mma(
    const __half* __restrict__ Qh,
    const __half* __restrict__ Kh, const __half* __restrict__ Vh,
    __half* __restrict__ Ohi,
    int Tq, int Tkv, int qS, int kS, float scale)
{
    extern __shared__ __align__(16) char smem[];
    const uint32_t base = smem_u32(smem);
    const uint32_t sQ = base;

    const int tid = threadIdx.x;
    const int wid = tid >> 5, lane = tid & 31;
    const int bh = blockIdx.y;
    const int b = bh >> 4, h = bh & 15;
    const int qt = blockIdx.x;

    const __half* Qb  = Qh + (size_t)(b * Tq + qt * 128) * qS + h * 64;
    const __half* Khb = Kh + (size_t)(b * Tkv) * kS + h * 64;
    const __half* Vhb = Vh + (size_t)(b * Tkv) * kS + h * 64;

    auto stage_kv = [&](int kt, int buf) {
        const uint32_t sb = base + QTB + buf * KVSTAGE;
        #pragma unroll
        for (int i = 0; i < 2; i++) {
            int idx = tid + i * 256;
            int r = idx >> 3, s = idx & 7;
            size_t go = (size_t)(kt * 64 + r) * kS + s * 8;
            uint32_t off = (r * FRS + s * 8) * 2;
            cp16(sb + 0 * KVT + off, Khb + go);
            cp16(sb + 1 * KVT + off, Vhb + go);
        }
        asm volatile("cp.async.commit_group;");
    };

    #pragma unroll
    for (int i = 0; i < 4; i++) {
        int idx = tid + i * 256;
        int r = idx >> 3, s = idx & 7;
        cp16(sQ + (r * FRS + s * 8) * 2, Qb + (size_t)r * qS + s * 8);
    }
    stage_kv(0, 0);

    const int laRowA = ((lane >> 3) & 1) * 8 + (lane & 7);
    const int laColA = (lane >> 4) * 8;
    const int laRowB = ((lane >> 4) << 3) + (lane & 7);
    const int laColB = ((lane >> 3) & 1) * 8;

    float o[8][4];
    #pragma unroll
    for (int i = 0; i < 8; i++)
        #pragma unroll
        for (int j = 0; j < 4; j++) o[i][j] = 0.f;
    float mr0 = -1e30f, mr1 = -1e30f, lr0 = 0.f, lr1 = 0.f;

    const int nkt = CAUSAL ? (2 * qt + 2) : (Tkv >> 6);

    for (int kt = 0; kt < nkt; kt++) {
        if (kt + 1 < nkt) {
            stage_kv(kt + 1, (kt + 1) & 1);
            asm volatile("cp.async.wait_group 1;");
        } else {
            asm volatile("cp.async.wait_group 0;");
        }
        __syncthreads();

        const uint32_t sb = base + QTB + (kt & 1) * KVSTAGE;
        const uint32_t sK = sb, sV = sb + KVT;

        float s[8][4];
        #pragma unroll
        for (int i = 0; i < 8; i++)
            #pragma unroll
            for (int j = 0; j < 4; j++) s[i][j] = 0.f;

        #pragma unroll
        for (int ks = 0; ks < 4; ks++) {
            uint32_t q[4];
            uint32_t qoff = ((wid * 16 + laRowA) * FRS + ks * 16 + laColA) * 2;
            ldsm4(sQ + qoff, q[0], q[1], q[2], q[3]);
            #pragma unroll
            for (int np = 0; np < 4; np++) {
                uint32_t koff = ((np * 16 + laRowB) * FRS + ks * 16 + laColB) * 2;
                uint32_t k0, k1, k2, k3;
                ldsm4(sK + koff, k0, k1, k2, k3);
                mma_f16(s[2*np],   q, k0, k1);
                mma_f16(s[2*np+1], q, k2, k3);
            }
        }
        #pragma unroll
        for (int i = 0; i < 8; i++)
            #pragma unroll
            for (int j = 0; j < 4; j++) s[i][j] *= scale;

        if (CAUSAL && kt >= 2 * qt) {
            const int row0 = qt * 128 + wid * 16 + (lane >> 2);
            #pragma unroll
            for (int nf = 0; nf < 8; nf++) {
                const int col = kt * 64 + nf * 8 + (lane & 3) * 2;
                if (col     > row0)     s[nf][0] = -1e30f;
                if (col + 1 > row0)     s[nf][1] = -1e30f;
                if (col     > row0 + 8) s[nf][2] = -1e30f;
                if (col + 1 > row0 + 8) s[nf][3] = -1e30f;
            }
        }

        float t0 = -1e30f, t1 = -1e30f;
        #pragma unroll
        for (int nf = 0; nf < 8; nf++) {
            t0 = fmaxf(t0, fmaxf(s[nf][0], s[nf][1]));
            t1 = fmaxf(t1, fmaxf(s[nf][2], s[nf][3]));
        }
        t0 = fmaxf(t0, __shfl_xor_sync(0xffffffffu, t0, 1));
        t0 = fmaxf(t0, __shfl_xor_sync(0xffffffffu, t0, 2));
        t1 = fmaxf(t1, __shfl_xor_sync(0xffffffffu, t1, 1));
        t1 = fmaxf(t1, __shfl_xor_sync(0xffffffffu, t1, 2));
        const float nm0 = fmaxf(mr0, t0), nm1 = fmaxf(mr1, t1);
        const float f0 = __expf(mr0 - nm0), f1 = __expf(mr1 - nm1);
        mr0 = nm0; mr1 = nm1;

        float rs0 = 0.f, rs1 = 0.f;
        #pragma unroll
        for (int nf = 0; nf < 8; nf++) {
            s[nf][0] = __expf(s[nf][0] - nm0);
            s[nf][1] = __expf(s[nf][1] - nm0);
            s[nf][2] = __expf(s[nf][2] - nm1);
            s[nf][3] = __expf(s[nf][3] - nm1);
            rs0 += s[nf][0] + s[nf][1];
            rs1 += s[nf][2] + s[nf][3];
        }
        rs0 += __shfl_xor_sync(0xffffffffu, rs0, 1);
        rs0 += __shfl_xor_sync(0xffffffffu, rs0, 2);
        rs1 += __shfl_xor_sync(0xffffffffu, rs1, 1);
        rs1 += __shfl_xor_sync(0xffffffffu, rs1, 2);
        lr0 = lr0 * f0 + rs0;
        lr1 = lr1 * f1 + rs1;
        #pragma unroll
        for (int nf = 0; nf < 8; nf++) {
            o[nf][0] *= f0; o[nf][1] *= f0;
            o[nf][2] *= f1; o[nf][3] *= f1;
        }

        uint32_t ph[4][4];
        #pragma unroll
        for (int j = 0; j < 4; j++) {
            ph[j][0] = pack2(__float2half(s[2*j][0]),   __float2half(s[2*j][1]));
            ph[j][1] = pack2(__float2half(s[2*j][2]),   __float2half(s[2*j][3]));
            ph[j][2] = pack2(__float2half(s[2*j+1][0]), __float2half(s[2*j+1][1]));
            ph[j][3] = pack2(__float2half(s[2*j+1][2]), __float2half(s[2*j+1][3]));
        }

        #pragma unroll
        for (int j = 0; j < 4; j++) {
            #pragma unroll
            for (int np = 0; np < 4; np++) {
                uint32_t voff = ((j * 16 + laRowA) * FRS + np * 16 + laColA) * 2;
                uint32_t v0, v1, v2, v3;
                ldsm4t(sV + voff, v0, v1, v2, v3);
                mma_f16(o[2*np],   ph[j], v0, v1);
                mma_f16(o[2*np+1], ph[j], v2, v3);
            }
        }
        __syncthreads();
    }

    const float inv0 = 1.0f / lr0, inv1 = 1.0f / lr1;
    const int row0 = qt * 128 + wid * 16 + (lane >> 2);
    #pragma unroll
    for (int nf = 0; nf < 8; nf++) {
        const int col = h * 64 + nf * 8 + (lane & 3) * 2;
        {
            size_t off = (size_t)(b * Tq + row0) * CC + col;
            *(uint32_t*)(Ohi + off) =
                pack2(__float2half(o[nf][0] * inv0), __float2half(o[nf][1] * inv0));
        }
        {
            size_t off = (size_t)(b * Tq + row0 + 8) * CC + col;
            *(uint32_t*)(Ohi + off) =
                pack2(__float2half(o[nf][2] * inv1), __float2half(o[nf][3] * inv1));
        }
    }
}

// ---------------------------------------------------------------------------
// Launch sequence
// ---------------------------------------------------------------------------
extern "C" void kernel_launch(void* const* d_in, const int* in_sizes, int n_in,
                              void* d_out, int out_size)
{
    (void)in_sizes; (void)n_in; (void)out_size;
    const float* x      = (const float*)d_in[0];
    const float* ximg   = (const float*)d_in[1];
    const float* ln1_g  = (const float*)d_in[2];
    const float* ln1_b  = (const float*)d_in[3];
    const float* ln2_g  = (const float*)d_in[4];
    const float* ln2_b  = (const float*)d_in[5];
    const float* W_attn = (const float*)d_in[6];
    const float* b_attn = (const float*)d_in[7];
    const float* W_aproj= (const float*)d_in[8];
    const float* b_aproj= (const float*)d_in[9];
    const float* Wq     = (const float*)d_in[10];
    const float* bq     = (const float*)d_in[11];
    const float* Wk     = (const float*)d_in[12];
    const float* bk     = (const float*)d_in[13];
    const float* Wv     = (const float*)d_in[14];
    const float* bv     = (const float*)d_in[15];
    const float* Wcproj = (const float*)d_in[16];
    const float* bcproj = (const float*)d_in[17];
    const float* W_fc   = (const float*)d_in[18];
    const float* b_fc   = (const float*)d_in[19];
    const float* W_mproj= (const float*)d_in[20];
    const float* b_mproj= (const float*)d_in[21];
    float* out = (float*)d_out;

    __half *wt, *qkv, *q, *kv, *a, *ff, *xi;
    float* bkv;
    cudaGetSymbolAddress((void**)&wt,  g_wt);
    cudaGetSymbolAddress((void**)&qkv, g_qkv);
    cudaGetSymbolAddress((void**)&q,   g_q);
    cudaGetSymbolAddress((void**)&kv,  g_kv);
    cudaGetSymbolAddress((void**)&a,   g_a);
    cudaGetSymbolAddress((void**)&ff,  g_ff);
    cudaGetSymbolAddress((void**)&xi,  g_xi);
    cudaGetSymbolAddress((void**)&bkv, g_bkv);

    cudaFuncSetAttribute(mma_gemm<0,false>, cudaFuncAttributeMaxDynamicSharedMemorySize, GEMM_SMEM);
    cudaFuncSetAttribute(mma_gemm<1,false>, cudaFuncAttributeMaxDynamicSharedMemorySize, GEMM_SMEM);
    cudaFuncSetAttribute(mma_gemm<1,true>,  cudaFuncAttributeMaxDynamicSharedMemorySize, GEMM_SMEM);
    cudaFuncSetAttribute(flash_mma<true>,  cudaFuncAttributeMaxDynamicSharedMemorySize, FLASH_SMEM);
    cudaFuncSetAttribute(flash_mma<false>, cudaFuncAttributeMaxDynamicSharedMemorySize, FLASH_SMEM);

    const float scale = 0.125f;

    // ---- prep ----
    tofp16_kernel<<<(MIMG*CC + 255)/256, 256>>>(ximg, xi, MIMG*CC);            // 0
    concat_bias_kernel<<<(2*CC + 255)/256, 256>>>(bk, bv, bkv);                // 1

    Prep8 pp;
    pp.d[0] = { W_attn,  OFF_ATTN,  CC, 3*CC, (3*CC/32)*(CC/32) };   // 3072
    pp.d[1] = { W_aproj, OFF_APROJ, CC, CC,   (CC/32)*(CC/32)   };   // 1024
    pp.d[2] = { Wq,      OFF_Q,     CC, CC,   (CC/32)*(CC/32)   };
    pp.d[3] = { Wk,      OFF_K,     CC, CC,   (CC/32)*(CC/32)   };
    pp.d[4] = { Wv,      OFF_V,     CC, CC,   (CC/32)*(CC/32)   };
    pp.d[5] = { Wcproj,  OFF_CPROJ, CC, CC,   (CC/32)*(CC/32)   };
    pp.d[6] = { W_fc,    OFF_FC,    CC, FFD,  (FFD/32)*(CC/32)  };   // 4096
    pp.d[7] = { W_mproj, OFF_MPROJ, FFD, CC,  (CC/32)*(FFD/32)  };   // 4096
    prep_weights_kernel<<<3072 + 5*1024 + 2*4096, 256>>>(pp, wt);              // 2

    // ---- causal self-attention ----
    ln_h_kernel<<<MM, 256>>>(x, ln1_g, ln1_b, a);                              // 3
    mma_gemm<1,false><<<dim3(3*CC/256, MM/128), 256, GEMM_SMEM>>>(             // 4
        a, wt+OFF_ATTN, b_attn, nullptr, nullptr, qkv, MM, 3*CC, CC);
    flash_mma<true><<<dim3(8, 128), 256, FLASH_SMEM>>>(                        // 5
        qkv, qkv + CC, qkv + 2*CC, a, 1024, 1024, 3*CC, 3*CC, scale);
    mma_gemm<0,false><<<dim3(CC/256, MM/128), 256, GEMM_SMEM>>>(
        a, wt+OFF_APROJ, b_aproj, x, out, nullptr, MM, CC, CC);

    // ---- cross-attention ----
    ln_h_kernel<<<MM, 256>>>(out, ln1_g, ln1_b, a);
    mma_gemm<1,false><<<dim3(CC/256, MM/128), 256, GEMM_SMEM>>>(
        a, wt+OFF_Q, bq, nullptr, nullptr, q, MM, CC, CC);
    mma_gemm<1,false><<<dim3(2*CC/256, MIMG/128), 256, GEMM_SMEM>>>(
        xi, wt+OFF_K, bkv, nullptr, nullptr, kv, MIMG, 2*CC, CC);
    flash_mma<false><<<dim3(8, 128), 256, FLASH_SMEM>>>(
        q, kv, kv + CC, a, 1024, 256, CC, 2*CC, scale);
    mma_gemm<0,false><<<dim3(CC/256, MM/128), 256, GEMM_SMEM>>>(
        a, wt+OFF_CPROJ, bcproj, out, out, nullptr, MM, CC, CC);

    // ---- MLP ----
    ln_h_kernel<<<MM, 256>>>(out, ln2_g, ln2_b, a);
    mma_gemm<1,true><<<dim3(FFD/256, MM/128), 256, GEMM_SMEM>>>(
        a, wt+OFF_FC, b_fc, nullptr, nullptr, ff, MM, FFD, CC);
    mma_gemm<0,false><<<dim3(CC/256, MM/128), 256, GEMM_SMEM>>>(
        ff, wt+OFF_MPROJ, b_mproj, out, out, nullptr, MM, CC, FFD);
}